// round 11
// baseline (speedup 1.0000x reference)
#include <cuda_runtime.h>
#include <cuda_fp16.h>
#include <math.h>
#include <stdint.h>

#define BATCH 8
#define SEQ 512
#define BT (BATCH*SEQ)        // 4096
#define EMB 768
#define NH 12
#define DH 64
#define VOC 60
#define DST 128
#define NLAYER 12
#define QKVN (3*EMB)          // 2304
#define FFN (4*EMB)           // 3072

#define W_QKV (QKVN*EMB)
#define W_PROJ (EMB*EMB)
#define W_FC (FFN*EMB)
#define W_MLP (EMB*FFN)
#define OFF_QKV 0
#define OFF_PROJ (12*W_QKV)
#define OFF_FC (OFF_PROJ + 12*W_PROJ)
#define OFF_MLP (OFF_FC + 12*W_FC)
#define W_TOTAL (OFF_MLP + 12*W_MLP)

// ---------------- scratch ----------------
__device__ float g_h[BT*EMB];
__device__ float g_ln[BT*EMB];
__device__ float g_qkv[BT*QKVN];
__device__ float g_semb[VOC*EMB];
__device__ int   g_pre[BT];

__device__ __half g_wh[W_TOTAL];                 // weights, single fp16, [N][K]
__device__ __half g_lnh[BT*EMB],  g_lnl[BT*EMB]; // activations, fp16 hi/lo
__device__ __half g_atth[BT*EMB], g_attl[BT*EMB];
__device__ __half g_midh[BT*FFN], g_midl[BT*FFN];

// ---------------- helpers ----------------
__device__ __forceinline__ uint32_t smem_u32(const void* p) {
    uint32_t a;
    asm("{ .reg .u64 t; cvta.to.shared.u64 t, %1; cvt.u32.u64 %0, t; }" : "=r"(a) : "l"(p));
    return a;
}

__device__ __forceinline__ void ldsm_x4(uint32_t* r, uint32_t addr) {
    asm volatile("ldmatrix.sync.aligned.m8n8.x4.shared.b16 {%0,%1,%2,%3}, [%4];"
        : "=r"(r[0]), "=r"(r[1]), "=r"(r[2]), "=r"(r[3]) : "r"(addr));
}

__device__ __forceinline__ void mma_f16(float* c, const uint32_t* a, const uint32_t* b) {
    asm volatile("mma.sync.aligned.m16n8k16.row.col.f32.f16.f16.f32 "
        "{%0,%1,%2,%3}, {%4,%5,%6,%7}, {%8,%9}, {%0,%1,%2,%3};"
        : "+f"(c[0]), "+f"(c[1]), "+f"(c[2]), "+f"(c[3])
        : "r"(a[0]), "r"(a[1]), "r"(a[2]), "r"(a[3]), "r"(b[0]), "r"(b[1]));
}

// fp16-accumulator variant (lo-term only; contribution <= 2^-11 of total)
__device__ __forceinline__ void mma_f16acc(uint32_t* c, const uint32_t* a, const uint32_t* b) {
    asm volatile("mma.sync.aligned.m16n8k16.row.col.f16.f16.f16.f16 "
        "{%0,%1}, {%2,%3,%4,%5}, {%6,%7}, {%0,%1};"
        : "+r"(c[0]), "+r"(c[1])
        : "r"(a[0]), "r"(a[1]), "r"(a[2]), "r"(a[3]), "r"(b[0]), "r"(b[1]));
}

__device__ __forceinline__ void cp16(uint32_t dst, const void* src) {
    asm volatile("cp.async.cg.shared.global [%0], [%1], 16;" :: "r"(dst), "l"(src));
}
#define CP_COMMIT() asm volatile("cp.async.commit_group;" ::: "memory")
#define CP_WAIT(n)  asm volatile("cp.async.wait_group %0;" :: "n"(n) : "memory")

__device__ __forceinline__ void cvt_split2h(float x0, float x1, uint32_t& hi, uint32_t& lo) {
    __half h0 = __float2half_rn(x0);
    __half h1 = __float2half_rn(x1);
    __half l0 = __float2half_rn(x0 - __half2float(h0));
    __half l1 = __float2half_rn(x1 - __half2float(h1));
    __half2 H(h0, h1), L(l0, l1);
    hi = *(uint32_t*)&H;
    lo = *(uint32_t*)&L;
}

// ---------------- reductions ----------------
__device__ __forceinline__ float breduce_sum(float v, float* sh, int nthr) {
#pragma unroll
    for (int o = 16; o > 0; o >>= 1) v += __shfl_xor_sync(0xffffffffu, v, o);
    int lane = threadIdx.x & 31, w = threadIdx.x >> 5;
    if (lane == 0) sh[w] = v;
    __syncthreads();
    float r = 0.f;
    if ((int)threadIdx.x < (nthr >> 5)) r = sh[threadIdx.x];
    if (threadIdx.x < 32) {
#pragma unroll
        for (int o = 16; o > 0; o >>= 1) r += __shfl_xor_sync(0xffffffffu, r, o);
        if (threadIdx.x == 0) sh[0] = r;
    }
    __syncthreads();
    r = sh[0];
    __syncthreads();
    return r;
}

// ---------------- automaton state scan ----------------
__global__ void state_scan_kernel(const int* __restrict__ ids, const int* __restrict__ mul) {
    __shared__ int smul[VOC*VOC];
    __shared__ int sids[BT];
    int tid = threadIdx.x;
    for (int i = tid; i < VOC*VOC; i += blockDim.x) smul[i] = mul[i];
    for (int i = tid; i < BT; i += blockDim.x) sids[i] = ids[i];
    __syncthreads();
    if (tid < BATCH) {
        int s = 0;
        const int* row = sids + tid * SEQ;
        int* pre = g_pre + tid * SEQ;
        for (int t = 0; t < SEQ; t++) {
            pre[t] = s;
            s = smul[row[t] * VOC + s];
        }
    }
}

__global__ void state_proj_kernel(const float* __restrict__ semb,
                                  const float* __restrict__ W,
                                  const float* __restrict__ b) {
    int idx = blockIdx.x * blockDim.x + threadIdx.x;
    if (idx >= VOC * EMB) return;
    int v = idx / EMB, e = idx % EMB;
    float acc = b[e];
#pragma unroll 8
    for (int d = 0; d < DST; d++) acc += semb[v * DST + d] * W[d * EMB + e];
    g_semb[idx] = acc;
}

__global__ void embed_kernel(const int* __restrict__ ids,
                             const float* __restrict__ tok_emb,
                             const float* __restrict__ wpe) {
    int idx = blockIdx.x * blockDim.x + threadIdx.x;
    if (idx >= BT * EMB) return;
    int bt = idx / EMB, e = idx % EMB;
    int t = bt % SEQ;
    g_h[idx] = tok_emb[ids[bt] * EMB + e] + g_semb[g_pre[bt] * EMB + e] + wpe[t * EMB + e];
}

// ---------------- weight convert: W[K][N] fp32 -> fp16 [N][K] --------------
__global__ __launch_bounds__(256) void wconv_kernel(
    const float* __restrict__ W, __half* __restrict__ Hi, int K, int N)
{
    __shared__ float t[32][33];
    int l = blockIdx.z;
    const float* Wl = W + (size_t)l * K * N;
    __half* Hl = Hi + (size_t)l * K * N;
    int n0 = blockIdx.x * 32, k0 = blockIdx.y * 32;
    int tx = threadIdx.x & 31, ty = threadIdx.x >> 5;
#pragma unroll
    for (int j = 0; j < 4; j++)
        t[ty + 8 * j][tx] = Wl[(size_t)(k0 + ty + 8 * j) * N + n0 + tx];
    __syncthreads();
#pragma unroll
    for (int j = 0; j < 4; j++) {
        float v = t[tx][ty + 8 * j];
        Hl[(size_t)(n0 + ty + 8 * j) * K + k0 + tx] = __float2half_rn(v);
    }
}

// ---------------- layernorm variants ----------------
__global__ __launch_bounds__(256) void ln_kernel(const float* __restrict__ x,
                                                 const float* __restrict__ g,
                                                 const float* __restrict__ b,
                                                 float* __restrict__ y) {
    __shared__ float sh[8];
    int row = blockIdx.x, tid = threadIdx.x;
    const float* xr = x + (size_t)row * EMB;
    float v0 = xr[tid], v1 = xr[tid + 256], v2 = xr[tid + 512];
    float mean = breduce_sum(v0 + v1 + v2, sh, 256) * (1.f / EMB);
    float d0 = v0 - mean, d1 = v1 - mean, d2 = v2 - mean;
    float var = breduce_sum(d0*d0 + d1*d1 + d2*d2, sh, 256) * (1.f / EMB);
    float rstd = rsqrtf(var + 1e-5f);
    float* yr = y + (size_t)row * EMB;
    yr[tid]       = d0 * rstd * g[tid]       + b[tid];
    yr[tid + 256] = d1 * rstd * g[tid + 256] + b[tid + 256];
    yr[tid + 512] = d2 * rstd * g[tid + 512] + b[tid + 512];
}

__global__ __launch_bounds__(256) void ln_f16_kernel(const float* __restrict__ x,
                                                     const float* __restrict__ g,
                                                     const float* __restrict__ b,
                                                     __half* __restrict__ yh,
                                                     __half* __restrict__ yl) {
    __shared__ float sh[8];
    int row = blockIdx.x, tid = threadIdx.x;
    const float* xr = x + (size_t)row * EMB;
    float v0 = xr[tid], v1 = xr[tid + 256], v2 = xr[tid + 512];
    float mean = breduce_sum(v0 + v1 + v2, sh, 256) * (1.f / EMB);
    float d0 = v0 - mean, d1 = v1 - mean, d2 = v2 - mean;
    float var = breduce_sum(d0*d0 + d1*d1 + d2*d2, sh, 256) * (1.f / EMB);
    float rstd = rsqrtf(var + 1e-5f);
    size_t base = (size_t)row * EMB;
#pragma unroll
    for (int q = 0; q < 3; q++) {
        int e = tid + q * 256;
        float d = (q == 0) ? d0 : (q == 1) ? d1 : d2;
        float v = d * rstd * g[e] + b[e];
        __half h = __float2half_rn(v);
        yh[base + e] = h;
        yl[base + e] = __float2half_rn(v - __half2float(h));
    }
}

// ================= mma.sync fp16 2-term GEMM (R9 geometry) =================
// hi-term: fp32-acc MMAs; lo-term: fp16-acc MMAs (single-variable test).
__device__ __forceinline__ float gelu_f(float x) {
    return 0.5f * x * (1.f + tanhf(0.7978845608028654f * (x + 0.044715f * x * x * x)));
}

#define ROWB 80
#define SM_AH 0
#define SM_AL 10240
#define SM_BH 20480
#define BUFSZ 25600
#define GEMM_SMEM (2*BUFSZ)   // 51200

template<int EPI>
__global__ __launch_bounds__(256, 2) void mma_gemm(
    const __half* __restrict__ Ah, const __half* __restrict__ Al,
    const __half* __restrict__ Bh,
    const float* __restrict__ bias,
    const float* __restrict__ Res,
    float* __restrict__ C,
    __half* __restrict__ Ch, __half* __restrict__ Cl,
    int K, int N)
{
    extern __shared__ __align__(16) char sm[];
    uint32_t sb = smem_u32(sm);
    int tid = threadIdx.x;
    int wid = tid >> 5, lane = tid & 31;
    int wm = wid & 3, wn = wid >> 2;
    int m0 = blockIdx.y * 128, n0 = blockIdx.x * 64;

    int p_row = tid >> 2;
    int p_seg = tid & 3;

    int a_row = lane & 15;
    int a_colb = ((lane >> 4) * 8) * 2;
    int b_row = (lane & 7) + ((lane >> 4) & 1) * 8;
    int b_colb = (((lane >> 3) & 1) * 8) * 2;

    float acc[2][4][4];
    uint32_t acc16[2][4][2];
#pragma unroll
    for (int i = 0; i < 2; i++)
#pragma unroll
        for (int j = 0; j < 4; j++) {
#pragma unroll
            for (int q = 0; q < 4; q++) acc[i][j][q] = 0.f;
            acc16[i][j][0] = 0u; acc16[i][j][1] = 0u;
        }

    const int nch = K >> 5;

    auto issue = [&](int c, int bufsel) {
        int k0 = c << 5;
        uint32_t base = sb + bufsel * BUFSZ;
        uint32_t doff = (uint32_t)(p_row * ROWB + p_seg * 16);
#pragma unroll
        for (int i = 0; i < 2; i++) {
            int row = p_row + i * 64;
            size_t aoff = (size_t)(m0 + row) * K + k0 + p_seg * 8;
            cp16(base + SM_AH + doff + i * (64 * ROWB), Ah + aoff);
            cp16(base + SM_AL + doff + i * (64 * ROWB), Al + aoff);
        }
        size_t boff = (size_t)(n0 + p_row) * K + k0 + p_seg * 8;
        cp16(base + SM_BH + doff, Bh + boff);
    };

    issue(0, 0);
    CP_COMMIT();

    for (int c = 0; c < nch; c++) {
        int cur = c & 1;
        if (c + 1 < nch) {
            issue(c + 1, cur ^ 1);
            CP_COMMIT();
            CP_WAIT(1);
        } else {
            CP_WAIT(0);
        }
        __syncthreads();

        uint32_t base = sb + cur * BUFSZ;
#pragma unroll
        for (int ks = 0; ks < 2; ks++) {
            uint32_t a_hi[2][4], a_lo[2][4];
#pragma unroll
            for (int mt = 0; mt < 2; mt++) {
                uint32_t off = (uint32_t)((wm * 32 + mt * 16 + a_row) * ROWB
                                          + ks * 32 + a_colb);
                ldsm_x4(a_hi[mt], base + SM_AH + off);
                ldsm_x4(a_lo[mt], base + SM_AL + off);
            }
            uint32_t b_hi[2][4];
#pragma unroll
            for (int p = 0; p < 2; p++) {
                uint32_t off = (uint32_t)((wn * 32 + p * 16 + b_row) * ROWB
                                          + ks * 32 + b_colb);
                ldsm_x4(b_hi[p], base + SM_BH + off);
            }
#pragma unroll
            for (int mt = 0; mt < 2; mt++)
#pragma unroll
                for (int p = 0; p < 2; p++) {
                    mma_f16(acc[mt][2*p],   a_hi[mt], &b_hi[p][0]);
                    mma_f16(acc[mt][2*p+1], a_hi[mt], &b_hi[p][2]);
                }
#pragma unroll
            for (int mt = 0; mt < 2; mt++)
#pragma unroll
                for (int p = 0; p < 2; p++) {
                    mma_f16acc(acc16[mt][2*p],   a_lo[mt], &b_hi[p][0]);
                    mma_f16acc(acc16[mt][2*p+1], a_lo[mt], &b_hi[p][2]);
                }
        }
        __syncthreads();
    }

    int r0 = m0 + wm * 32 + (lane >> 2);
    int c0 = n0 + wn * 32 + (lane & 3) * 2;
#pragma unroll
    for (int mt = 0; mt < 2; mt++) {
#pragma unroll
        for (int nt = 0; nt < 4; nt++) {
            int r = r0 + mt * 16;
            int cc = c0 + nt * 8;
            float2 lo0 = __half22float2(*(__half2*)&acc16[mt][nt][0]);
            float2 lo1 = __half22float2(*(__half2*)&acc16[mt][nt][1]);
            float b0 = bias[cc], b1 = bias[cc + 1];
            float v0 = acc[mt][nt][0] + lo0.x + b0;
            float v1 = acc[mt][nt][1] + lo0.y + b1;
            float v2 = acc[mt][nt][2] + lo1.x + b0;
            float v3 = acc[mt][nt][3] + lo1.y + b1;
            if (EPI == 2) {
                v0 = gelu_f(v0); v1 = gelu_f(v1);
                v2 = gelu_f(v2); v3 = gelu_f(v3);
                uint32_t h01, l01, h23, l23;
                cvt_split2h(v0, v1, h01, l01);
                cvt_split2h(v2, v3, h23, l23);
                *(uint32_t*)(Ch + (size_t)r * N + cc) = h01;
                *(uint32_t*)(Cl + (size_t)r * N + cc) = l01;
                *(uint32_t*)(Ch + (size_t)(r + 8) * N + cc) = h23;
                *(uint32_t*)(Cl + (size_t)(r + 8) * N + cc) = l23;
            } else {
                if (EPI == 1) {
                    const float* rp0 = Res + (size_t)r * N + cc;
                    const float* rp1 = Res + (size_t)(r + 8) * N + cc;
                    v0 += rp0[0]; v1 += rp0[1];
                    v2 += rp1[0]; v3 += rp1[1];
                }
                *reinterpret_cast<float2*>(C + (size_t)r * N + cc) = make_float2(v0, v1);
                *reinterpret_cast<float2*>(C + (size_t)(r + 8) * N + cc) = make_float2(v2, v3);
            }
        }
    }
}

// ================= tensor-core causal flash attention ======================
#define FROWB 144
#define FT_QH 0
#define FT_QL (128*FROWB)
#define FT_KH (2*128*FROWB)
#define FT_KL (FT_KH + 64*FROWB)
#define FT_VH (FT_KL + 64*FROWB)
#define FT_VL (FT_VH + 64*FROWB)
#define FT_SMEM (FT_VL + 64*FROWB)   // 73728

__global__ __launch_bounds__(256, 2) void flash_tc_kernel() {
    extern __shared__ __align__(16) char fsm[];
    uint32_t sb = smem_u32(fsm);
    int bh = blockIdx.y;
    int b = bh / NH, h = bh % NH;
    int t0 = blockIdx.x * 128;
    const float* qb = g_qkv + (size_t)b * SEQ * QKVN + h * DH;
    const float* kb = qb + EMB;
    const float* vb = qb + 2 * EMB;
    int tid = threadIdx.x;
    int wid = tid >> 5, lane = tid & 31;

    int a_row = lane & 15;
    int a_colb = ((lane >> 4) * 8) * 2;
    int b_row = (lane & 7) + ((lane >> 4) & 1) * 8;
    int b_colb = (((lane >> 3) & 1) * 8) * 2;

    {
        int row = tid >> 1, d0 = (tid & 1) * 32;
        const float* qp = qb + (size_t)(t0 + row) * QKVN + d0;
#pragma unroll
        for (int i = 0; i < 8; i++) {
            float4 v = *reinterpret_cast<const float4*>(qp + 4 * i);
            uint32_t h01, l01, h23, l23;
            cvt_split2h(v.x, v.y, h01, l01);
            cvt_split2h(v.z, v.w, h23, l23);
            uint32_t off = (uint32_t)(row * FROWB + (d0 + 4 * i) * 2);
            *(uint32_t*)(fsm + FT_QH + off)     = h01;
            *(uint32_t*)(fsm + FT_QH + off + 4) = h23;
            *(uint32_t*)(fsm + FT_QL + off)     = l01;
            *(uint32_t*)(fsm + FT_QL + off + 4) = l23;
        }
    }

    float m0 = -1e30f, m1 = -1e30f, l0 = 0.f, l1 = 0.f;
    float O[8][4];
#pragma unroll
    for (int f = 0; f < 8; f++)
#pragma unroll
        for (int q = 0; q < 4; q++) O[f][q] = 0.f;

    int t_r0 = t0 + wid * 16 + (lane >> 2);
    int ntile = (t0 >> 6) + 2;

    for (int j = 0; j < ntile; j++) {
        __syncthreads();
        {
            int s = tid >> 2, d0 = (tid & 3) * 16;
            const float* kp = kb + (size_t)(j * 64 + s) * QKVN + d0;
            const float* vp = vb + (size_t)(j * 64 + s) * QKVN + d0;
#pragma unroll
            for (int i = 0; i < 4; i++) {
                float4 kv = *reinterpret_cast<const float4*>(kp + 4 * i);
                uint32_t h01, lo01, h23, lo23;
                cvt_split2h(kv.x, kv.y, h01, lo01);
                cvt_split2h(kv.z, kv.w, h23, lo23);
                uint32_t off = (uint32_t)(s * FROWB + (d0 + 4 * i) * 2);
                *(uint32_t*)(fsm + FT_KH + off)     = h01;
                *(uint32_t*)(fsm + FT_KH + off + 4) = h23;
                *(uint32_t*)(fsm + FT_KL + off)     = lo01;
                *(uint32_t*)(fsm + FT_KL + off + 4) = lo23;

                float4 vv = *reinterpret_cast<const float4*>(vp + 4 * i);
                float vals[4] = {vv.x, vv.y, vv.z, vv.w};
#pragma unroll
                for (int q = 0; q < 4; q++) {
                    int d = d0 + 4 * i + q;
                    __half hh = __float2half_rn(vals[q]);
                    __half ll = __float2half_rn(vals[q] - __half2float(hh));
                    *(__half*)(fsm + FT_VH + d * FROWB + s * 2) = hh;
                    *(__half*)(fsm + FT_VL + d * FROWB + s * 2) = ll;
                }
            }
        }
        __syncthreads();

        float S[8][4];
#pragma unroll
        for (int f = 0; f < 8; f++)
#pragma unroll
            for (int q = 0; q < 4; q++) S[f][q] = 0.f;
#pragma unroll
        for (int ks = 0; ks < 4; ks++) {
            uint32_t aq_h[4], aq_l[4];
            uint32_t aoff = (uint32_t)((wid * 16 + a_row) * FROWB + ks * 32 + a_colb);
            ldsm_x4(aq_h, sb + FT_QH + aoff);
            ldsm_x4(aq_l, sb + FT_QL + aoff);
#pragma unroll
            for (int p = 0; p < 4; p++) {
                uint32_t bk_h[4], bk_l[4];
                uint32_t boff = (uint32_t)((p * 16 + b_row) * FROWB + ks * 32 + b_colb);
                ldsm_x4(bk_h, sb + FT_KH + boff);
                ldsm_x4(bk_l, sb + FT_KL + boff);
                mma_f16(S[2*p],   aq_h, &bk_h[0]);
                mma_f16(S[2*p+1], aq_h, &bk_h[2]);
                mma_f16(S[2*p],   aq_l, &bk_h[0]);
                mma_f16(S[2*p+1], aq_l, &bk_h[2]);
                mma_f16(S[2*p],   aq_h, &bk_l[0]);
                mma_f16(S[2*p+1], aq_h, &bk_l[2]);
            }
        }

#pragma unroll
        for (int f = 0; f < 8; f++) {
            int c = j * 64 + (f >> 1) * 16 + (f & 1) * 8 + (lane & 3) * 2;
#pragma unroll
            for (int q = 0; q < 4; q++) S[f][q] *= 0.125f;
            if (c     > t_r0) S[f][0] = -1e30f;
            if (c + 1 > t_r0) S[f][1] = -1e30f;
            if (c     > t_r0 + 8) S[f][2] = -1e30f;
            if (c + 1 > t_r0 + 8) S[f][3] = -1e30f;
        }

        float mx0 = -1e30f, mx1 = -1e30f;
#pragma unroll
        for (int f = 0; f < 8; f++) {
            mx0 = fmaxf(mx0, fmaxf(S[f][0], S[f][1]));
            mx1 = fmaxf(mx1, fmaxf(S[f][2], S[f][3]));
        }
        mx0 = fmaxf(mx0, __shfl_xor_sync(0xffffffffu, mx0, 1));
        mx0 = fmaxf(mx0, __shfl_xor_sync(0xffffffffu, mx0, 2));
        mx1 = fmaxf(mx1, __shfl_xor_sync(0xffffffffu, mx1, 1));
        mx1 = fmaxf(mx1, __shfl_xor_sync(0xffffffffu, mx1, 2));
        float mn0 = fmaxf(m0, mx0), mn1 = fmaxf(m1, mx1);
        float c0 = __expf(m0 - mn0), c1 = __expf(m1 - mn1);
        m0 = mn0; m1 = mn1;
        float rs0 = 0.f, rs1 = 0.f;
#pragma unroll
        for (int f = 0; f < 8; f++) {
            S[f][0] = __expf(S[f][0] - mn0);
            S[f][1] = __expf(S[f][1] - mn0);
            S[f][2] = __expf(S[f][2] - mn1);
            S[f][3] = __expf(S[f][3] - mn1);
            rs0 += S[f][0] + S[f][1];
            rs1 += S[f][2] + S[f][3];
        }
        rs0 += __shfl_xor_sync(0xffffffffu, rs0, 1);
        rs0 += __shfl_xor_sync(0xffffffffu, rs0, 2);
        rs1 += __shfl_xor_sync(0xffffffffu, rs1, 1);
        rs1 += __shfl_xor_sync(0xffffffffu, rs1, 2);
        l0 = l0 * c0 + rs0;
        l1 = l1 * c1 + rs1;
#pragma unroll
        for (int f = 0; f < 8; f++) {
            O[f][0] *= c0; O[f][1] *= c0;
            O[f][2] *= c1; O[f][3] *= c1;
        }

#pragma unroll
        for (int g = 0; g < 4; g++) {
            uint32_t pa[4];
            __half2 p0 = __floats2half2_rn(S[2*g][0],   S[2*g][1]);
            __half2 p1 = __floats2half2_rn(S[2*g][2],   S[2*g][3]);
            __half2 p2 = __floats2half2_rn(S[2*g+1][0], S[2*g+1][1]);
            __half2 p3 = __floats2half2_rn(S[2*g+1][2], S[2*g+1][3]);
            pa[0] = *(uint32_t*)&p0;
            pa[1] = *(uint32_t*)&p1;
            pa[2] = *(uint32_t*)&p2;
            pa[3] = *(uint32_t*)&p3;
#pragma unroll
            for (int p = 0; p < 4; p++) {
                uint32_t bv_h[4], bv_l[4];
                uint32_t boff = (uint32_t)((p * 16 + b_row) * FROWB + g * 32 + b_colb);
                ldsm_x4(bv_h, sb + FT_VH + boff);
                ldsm_x4(bv_l, sb + FT_VL + boff);
                mma_f16(O[2*p],   pa, &bv_h[0]);
                mma_f16(O[2*p+1], pa, &bv_h[2]);
                mma_f16(O[2*p],   pa, &bv_l[0]);
                mma_f16(O[2*p+1], pa, &bv_l[2]);
            }
        }
    }

    float inv0 = 1.f / l0, inv1 = 1.f / l1;
#pragma unroll
    for (int f = 0; f < 8; f++) {
        int d = (f >> 1) * 16 + (f & 1) * 8 + (lane & 3) * 2;
        size_t base0 = (size_t)(b * SEQ + t_r0) * EMB + h * DH + d;
        size_t base1 = (size_t)(b * SEQ + t_r0 + 8) * EMB + h * DH + d;
        uint32_t hh, ll;
        cvt_split2h(O[f][0] * inv0, O[f][1] * inv0, hh, ll);
        *(uint32_t*)(g_atth + base0) = hh;
        *(uint32_t*)(g_attl + base0) = ll;
        cvt_split2h(O[f][2] * inv1, O[f][3] * inv1, hh, ll);
        *(uint32_t*)(g_atth + base1) = hh;
        *(uint32_t*)(g_attl + base1) = ll;
    }
}

// ---------------- head GEMM (N=60, FFMA) ----------------
__global__ __launch_bounds__(256) void head_gemm_kernel(
    const float* __restrict__ A,
    const float* __restrict__ Bm,
    const float* __restrict__ bias,
    float* __restrict__ C,
    int N, int K)
{
    __shared__ float As[16][68];
    __shared__ float Bs[16][64];
    int m0 = blockIdx.y * 64, n0 = blockIdx.x * 64;
    int tid = threadIdx.x;
    int tx = tid & 15, ty = tid >> 4;
    float acc[4][4] = {};
    for (int k0 = 0; k0 < K; k0 += 16) {
#pragma unroll
        for (int i = 0; i < 4; i++) {
            int lin = tid + i * 256;
            int r = lin >> 4, c = lin & 15;
            As[c][r] = A[(size_t)(m0 + r) * K + k0 + c];
        }
#pragma unroll
        for (int i = 0; i < 4; i++) {
            int lin = tid + i * 256;
            int r = lin >> 6, c = lin & 63;
            int n = n0 + c;
            Bs[r][c] = (n < N) ? Bm[(size_t)(k0 + r) * N + n] : 0.f;
        }
        __syncthreads();
#pragma unroll
        for (int kk = 0; kk < 16; kk++) {
            float4 a4 = *reinterpret_cast<const float4*>(&As[kk][ty * 4]);
            float4 b4 = *reinterpret_cast<const float4*>(&Bs[kk][tx * 4]);
            float a[4] = {a4.x, a4.y, a4.z, a4.w};
            float bv[4] = {b4.x, b4.y, b4.z, b4.w};
#pragma unroll
            for (int i = 0; i < 4; i++)
#pragma unroll
                for (int j = 0; j < 4; j++)
                    acc[i][j] = fmaf(a[i], bv[j], acc[i][j]);
        }
        __syncthreads();
    }
#pragma unroll
    for (int i = 0; i < 4; i++) {
        int m = m0 + ty * 4 + i;
#pragma unroll
        for (int j = 0; j < 4; j++) {
            int n = n0 + tx * 4 + j;
            if (n < N) C[(size_t)m * N + n] = acc[i][j] + bias[n];
        }
    }
}

// ---------------- host orchestration ----------------
extern "C" void kernel_launch(void* const* d_in, const int* in_sizes, int n_in,
                              void* d_out, int out_size) {
    const int*   ids          = (const int*)d_in[0];
    const int*   mul          = (const int*)d_in[1];
    const float* tok_emb      = (const float*)d_in[2];
    const float* state_emb    = (const float*)d_in[3];
    const float* state_proj_w = (const float*)d_in[4];
    const float* state_proj_b = (const float*)d_in[5];
    const float* wpe          = (const float*)d_in[6];
    const float* ln1_g        = (const float*)d_in[7];
    const float* ln1_b        = (const float*)d_in[8];
    const float* attn_w       = (const float*)d_in[9];
    const float* attn_b       = (const float*)d_in[10];
    const float* attn_proj_w  = (const float*)d_in[11];
    const float* attn_proj_b  = (const float*)d_in[12];
    const float* ln2_g        = (const float*)d_in[13];
    const float* ln2_b        = (const float*)d_in[14];
    const float* fc_w         = (const float*)d_in[15];
    const float* fc_b         = (const float*)d_in[16];
    const float* mlp_proj_w   = (const float*)d_in[17];
    const float* mlp_proj_b   = (const float*)d_in[18];
    const float* lnf_g        = (const float*)d_in[19];
    const float* lnf_b        = (const float*)d_in[20];
    const float* head_w       = (const float*)d_in[21];
    const float* head_b       = (const float*)d_in[22];
    float* out = (float*)d_out;

    float *h, *lnbuf, *qkv;
    __half *wh, *lnh, *lnl, *atth, *attl, *midh, *midl;
    cudaGetSymbolAddress((void**)&h,     g_h);
    cudaGetSymbolAddress((void**)&lnbuf, g_ln);
    cudaGetSymbolAddress((void**)&qkv,   g_qkv);
    cudaGetSymbolAddress((void**)&wh,    g_wh);
    cudaGetSymbolAddress((void**)&lnh,   g_lnh);
    cudaGetSymbolAddress((void**)&lnl,   g_lnl);
    cudaGetSymbolAddress((void**)&atth,  g_atth);
    cudaGetSymbolAddress((void**)&attl,  g_attl);
    cudaGetSymbolAddress((void**)&midh,  g_midh);
    cudaGetSymbolAddress((void**)&midl,  g_midl);

    cudaFuncSetAttribute(mma_gemm<0>, cudaFuncAttributeMaxDynamicSharedMemorySize, GEMM_SMEM);
    cudaFuncSetAttribute(mma_gemm<1>, cudaFuncAttributeMaxDynamicSharedMemorySize, GEMM_SMEM);
    cudaFuncSetAttribute(mma_gemm<2>, cudaFuncAttributeMaxDynamicSharedMemorySize, GEMM_SMEM);
    cudaFuncSetAttribute(flash_tc_kernel, cudaFuncAttributeMaxDynamicSharedMemorySize, FT_SMEM);

    wconv_kernel<<<dim3(QKVN/32, EMB/32, NLAYER), 256>>>(attn_w, wh + OFF_QKV, EMB, QKVN);
    wconv_kernel<<<dim3(EMB/32, EMB/32, NLAYER), 256>>>(attn_proj_w, wh + OFF_PROJ, EMB, EMB);
    wconv_kernel<<<dim3(FFN/32, EMB/32, NLAYER), 256>>>(fc_w, wh + OFF_FC, EMB, FFN);
    wconv_kernel<<<dim3(EMB/32, FFN/32, NLAYER), 256>>>(mlp_proj_w, wh + OFF_MLP, FFN, EMB);

    state_scan_kernel<<<1, 256>>>(ids, mul);
    state_proj_kernel<<<(VOC * EMB + 255) / 256, 256>>>(state_emb, state_proj_w, state_proj_b);
    embed_kernel<<<(BT * EMB + 255) / 256, 256>>>(ids, tok_emb, wpe);

    for (int l = 0; l < NLAYER; l++) {
        ln_f16_kernel<<<BT, 256>>>(h, ln1_g + l * EMB, ln1_b + l * EMB, lnh, lnl);
        mma_gemm<0><<<dim3(QKVN/64, BT/128), 256, GEMM_SMEM>>>(
            lnh, lnl, wh + OFF_QKV + (size_t)l * W_QKV,
            attn_b + l * QKVN, nullptr, qkv, nullptr, nullptr, EMB, QKVN);
        flash_tc_kernel<<<dim3(SEQ/128, BATCH * NH), 256, FT_SMEM>>>();
        mma_gemm<1><<<dim3(EMB/64, BT/128), 256, GEMM_SMEM>>>(
            atth, attl, wh + OFF_PROJ + (size_t)l * W_PROJ,
            attn_proj_b + l * EMB, h, h, nullptr, nullptr, EMB, EMB);
        ln_f16_kernel<<<BT, 256>>>(h, ln2_g + l * EMB, ln2_b + l * EMB, lnh, lnl);
        mma_gemm<2><<<dim3(FFN/64, BT/128), 256, GEMM_SMEM>>>(
            lnh, lnl, wh + OFF_FC + (size_t)l * W_FC,
            fc_b + l * FFN, nullptr, nullptr, midh, midl, EMB, FFN);
        mma_gemm<1><<<dim3(EMB/64, BT/128), 256, GEMM_SMEM>>>(
            midh, midl, wh + OFF_MLP + (size_t)l * W_MLP,
            mlp_proj_b + l * EMB, h, h, nullptr, nullptr, FFN, EMB);
    }

    ln_kernel<<<BT, 256>>>(h, lnf_g, lnf_b, lnbuf);
    head_gemm_kernel<<<dim3(1, BT / 64), 256>>>(lnbuf, head_w, head_b, out, VOC, EMB);
}

// round 12
// speedup vs baseline: 1.1774x; 1.1774x over previous
#include <cuda_runtime.h>
#include <cuda_fp16.h>
#include <math.h>
#include <stdint.h>

#define BATCH 8
#define SEQ 512
#define BT (BATCH*SEQ)        // 4096
#define EMB 768
#define NH 12
#define DH 64
#define VOC 60
#define DST 128
#define NLAYER 12
#define QKVN (3*EMB)          // 2304
#define FFN (4*EMB)           // 3072

#define W_QKV (QKVN*EMB)
#define W_PROJ (EMB*EMB)
#define W_FC (FFN*EMB)
#define W_MLP (EMB*FFN)
#define OFF_QKV 0
#define OFF_PROJ (12*W_QKV)
#define OFF_FC (OFF_PROJ + 12*W_PROJ)
#define OFF_MLP (OFF_FC + 12*W_FC)
#define W_TOTAL (OFF_MLP + 12*W_MLP)

// ---------------- scratch ----------------
__device__ float g_h[BT*EMB];
__device__ float g_ln[BT*EMB];
__device__ float g_qkv[BT*QKVN];
__device__ float g_semb[VOC*EMB];
__device__ int   g_pre[BT];

__device__ __half g_wh[W_TOTAL];                 // weights, single fp16, [N][K]
__device__ __half g_lnh[BT*EMB],  g_lnl[BT*EMB]; // activations, fp16 hi/lo
__device__ __half g_atth[BT*EMB], g_attl[BT*EMB];
__device__ __half g_midh[BT*FFN], g_midl[BT*FFN];

// ---------------- helpers ----------------
__device__ __forceinline__ uint32_t smem_u32(const void* p) {
    uint32_t a;
    asm("{ .reg .u64 t; cvta.to.shared.u64 t, %1; cvt.u32.u64 %0, t; }" : "=r"(a) : "l"(p));
    return a;
}

__device__ __forceinline__ void ldsm_x4(uint32_t* r, uint32_t addr) {
    asm volatile("ldmatrix.sync.aligned.m8n8.x4.shared.b16 {%0,%1,%2,%3}, [%4];"
        : "=r"(r[0]), "=r"(r[1]), "=r"(r[2]), "=r"(r[3]) : "r"(addr));
}

__device__ __forceinline__ void mma_f16(float* c, const uint32_t* a, const uint32_t* b) {
    asm volatile("mma.sync.aligned.m16n8k16.row.col.f32.f16.f16.f32 "
        "{%0,%1,%2,%3}, {%4,%5,%6,%7}, {%8,%9}, {%0,%1,%2,%3};"
        : "+f"(c[0]), "+f"(c[1]), "+f"(c[2]), "+f"(c[3])
        : "r"(a[0]), "r"(a[1]), "r"(a[2]), "r"(a[3]), "r"(b[0]), "r"(b[1]));
}

__device__ __forceinline__ void cp16(uint32_t dst, const void* src) {
    asm volatile("cp.async.cg.shared.global [%0], [%1], 16;" :: "r"(dst), "l"(src));
}
#define CP_COMMIT() asm volatile("cp.async.commit_group;" ::: "memory")
#define CP_WAIT(n)  asm volatile("cp.async.wait_group %0;" :: "n"(n) : "memory")

__device__ __forceinline__ void cvt_split2h(float x0, float x1, uint32_t& hi, uint32_t& lo) {
    __half h0 = __float2half_rn(x0);
    __half h1 = __float2half_rn(x1);
    __half l0 = __float2half_rn(x0 - __half2float(h0));
    __half l1 = __float2half_rn(x1 - __half2float(h1));
    __half2 H(h0, h1), L(l0, l1);
    hi = *(uint32_t*)&H;
    lo = *(uint32_t*)&L;
}

// ---------------- reductions ----------------
__device__ __forceinline__ float breduce_sum(float v, float* sh, int nthr) {
#pragma unroll
    for (int o = 16; o > 0; o >>= 1) v += __shfl_xor_sync(0xffffffffu, v, o);
    int lane = threadIdx.x & 31, w = threadIdx.x >> 5;
    if (lane == 0) sh[w] = v;
    __syncthreads();
    float r = 0.f;
    if ((int)threadIdx.x < (nthr >> 5)) r = sh[threadIdx.x];
    if (threadIdx.x < 32) {
#pragma unroll
        for (int o = 16; o > 0; o >>= 1) r += __shfl_xor_sync(0xffffffffu, r, o);
        if (threadIdx.x == 0) sh[0] = r;
    }
    __syncthreads();
    r = sh[0];
    __syncthreads();
    return r;
}

// ---------------- automaton state scan ----------------
__global__ void state_scan_kernel(const int* __restrict__ ids, const int* __restrict__ mul) {
    __shared__ int smul[VOC*VOC];
    __shared__ int sids[BT];
    int tid = threadIdx.x;
    for (int i = tid; i < VOC*VOC; i += blockDim.x) smul[i] = mul[i];
    for (int i = tid; i < BT; i += blockDim.x) sids[i] = ids[i];
    __syncthreads();
    if (tid < BATCH) {
        int s = 0;
        const int* row = sids + tid * SEQ;
        int* pre = g_pre + tid * SEQ;
        for (int t = 0; t < SEQ; t++) {
            pre[t] = s;
            s = smul[row[t] * VOC + s];
        }
    }
}

__global__ void state_proj_kernel(const float* __restrict__ semb,
                                  const float* __restrict__ W,
                                  const float* __restrict__ b) {
    int idx = blockIdx.x * blockDim.x + threadIdx.x;
    if (idx >= VOC * EMB) return;
    int v = idx / EMB, e = idx % EMB;
    float acc = b[e];
#pragma unroll 8
    for (int d = 0; d < DST; d++) acc += semb[v * DST + d] * W[d * EMB + e];
    g_semb[idx] = acc;
}

__global__ void embed_kernel(const int* __restrict__ ids,
                             const float* __restrict__ tok_emb,
                             const float* __restrict__ wpe) {
    int idx = blockIdx.x * blockDim.x + threadIdx.x;
    if (idx >= BT * EMB) return;
    int bt = idx / EMB, e = idx % EMB;
    int t = bt % SEQ;
    g_h[idx] = tok_emb[ids[bt] * EMB + e] + g_semb[g_pre[bt] * EMB + e] + wpe[t * EMB + e];
}

// ---------------- weight convert: W[K][N] fp32 -> fp16 [N][K] --------------
__global__ __launch_bounds__(256) void wconv_kernel(
    const float* __restrict__ W, __half* __restrict__ Hi, int K, int N)
{
    __shared__ float t[32][33];
    int l = blockIdx.z;
    const float* Wl = W + (size_t)l * K * N;
    __half* Hl = Hi + (size_t)l * K * N;
    int n0 = blockIdx.x * 32, k0 = blockIdx.y * 32;
    int tx = threadIdx.x & 31, ty = threadIdx.x >> 5;
#pragma unroll
    for (int j = 0; j < 4; j++)
        t[ty + 8 * j][tx] = Wl[(size_t)(k0 + ty + 8 * j) * N + n0 + tx];
    __syncthreads();
#pragma unroll
    for (int j = 0; j < 4; j++) {
        float v = t[tx][ty + 8 * j];
        Hl[(size_t)(n0 + ty + 8 * j) * K + k0 + tx] = __float2half_rn(v);
    }
}

// ---------------- layernorm variants ----------------
__global__ __launch_bounds__(256) void ln_kernel(const float* __restrict__ x,
                                                 const float* __restrict__ g,
                                                 const float* __restrict__ b,
                                                 float* __restrict__ y) {
    __shared__ float sh[8];
    int row = blockIdx.x, tid = threadIdx.x;
    const float* xr = x + (size_t)row * EMB;
    float v0 = xr[tid], v1 = xr[tid + 256], v2 = xr[tid + 512];
    float mean = breduce_sum(v0 + v1 + v2, sh, 256) * (1.f / EMB);
    float d0 = v0 - mean, d1 = v1 - mean, d2 = v2 - mean;
    float var = breduce_sum(d0*d0 + d1*d1 + d2*d2, sh, 256) * (1.f / EMB);
    float rstd = rsqrtf(var + 1e-5f);
    float* yr = y + (size_t)row * EMB;
    yr[tid]       = d0 * rstd * g[tid]       + b[tid];
    yr[tid + 256] = d1 * rstd * g[tid + 256] + b[tid + 256];
    yr[tid + 512] = d2 * rstd * g[tid + 512] + b[tid + 512];
}

__global__ __launch_bounds__(256) void ln_f16_kernel(const float* __restrict__ x,
                                                     const float* __restrict__ g,
                                                     const float* __restrict__ b,
                                                     __half* __restrict__ yh,
                                                     __half* __restrict__ yl) {
    __shared__ float sh[8];
    int row = blockIdx.x, tid = threadIdx.x;
    const float* xr = x + (size_t)row * EMB;
    float v0 = xr[tid], v1 = xr[tid + 256], v2 = xr[tid + 512];
    float mean = breduce_sum(v0 + v1 + v2, sh, 256) * (1.f / EMB);
    float d0 = v0 - mean, d1 = v1 - mean, d2 = v2 - mean;
    float var = breduce_sum(d0*d0 + d1*d1 + d2*d2, sh, 256) * (1.f / EMB);
    float rstd = rsqrtf(var + 1e-5f);
    size_t base = (size_t)row * EMB;
#pragma unroll
    for (int q = 0; q < 3; q++) {
        int e = tid + q * 256;
        float d = (q == 0) ? d0 : (q == 1) ? d1 : d2;
        float v = d * rstd * g[e] + b[e];
        __half h = __float2half_rn(v);
        yh[base + e] = h;
        yl[base + e] = __float2half_rn(v - __half2float(h));
    }
}

// ================= mma.sync fp16 2-term GEMM ===============================
// R9 arithmetic; 3-deep cp.async ring buffer -> ONE __syncthreads per chunk.
__device__ __forceinline__ float gelu_f(float x) {
    return 0.5f * x * (1.f + tanhf(0.7978845608028654f * (x + 0.044715f * x * x * x)));
}

#define ROWB 80
#define SM_AH 0
#define SM_AL 10240
#define SM_BH 20480
#define BUFSZ 25600
#define GEMM_SMEM (3*BUFSZ)   // 76800/CTA, 153600/SM at 2 CTAs

template<int EPI>
__global__ __launch_bounds__(256, 2) void mma_gemm(
    const __half* __restrict__ Ah, const __half* __restrict__ Al,
    const __half* __restrict__ Bh,
    const float* __restrict__ bias,
    const float* __restrict__ Res,
    float* __restrict__ C,
    __half* __restrict__ Ch, __half* __restrict__ Cl,
    int K, int N)
{
    extern __shared__ __align__(16) char sm[];
    uint32_t sb = smem_u32(sm);
    int tid = threadIdx.x;
    int wid = tid >> 5, lane = tid & 31;
    int wm = wid & 3, wn = wid >> 2;
    int m0 = blockIdx.y * 128, n0 = blockIdx.x * 64;

    int p_row = tid >> 2;
    int p_seg = tid & 3;

    int a_row = lane & 15;
    int a_colb = ((lane >> 4) * 8) * 2;
    int b_row = (lane & 7) + ((lane >> 4) & 1) * 8;
    int b_colb = (((lane >> 3) & 1) * 8) * 2;

    float acc[2][4][4];
#pragma unroll
    for (int i = 0; i < 2; i++)
#pragma unroll
        for (int j = 0; j < 4; j++)
#pragma unroll
            for (int q = 0; q < 4; q++) acc[i][j][q] = 0.f;

    const int nch = K >> 5;

    auto issue = [&](int c, int bufsel) {
        int k0 = c << 5;
        uint32_t base = sb + bufsel * BUFSZ;
        uint32_t doff = (uint32_t)(p_row * ROWB + p_seg * 16);
#pragma unroll
        for (int i = 0; i < 2; i++) {
            int row = p_row + i * 64;
            size_t aoff = (size_t)(m0 + row) * K + k0 + p_seg * 8;
            cp16(base + SM_AH + doff + i * (64 * ROWB), Ah + aoff);
            cp16(base + SM_AL + doff + i * (64 * ROWB), Al + aoff);
        }
        size_t boff = (size_t)(n0 + p_row) * K + k0 + p_seg * 8;
        cp16(base + SM_BH + doff, Bh + boff);
    };

    issue(0, 0);
    CP_COMMIT();

    int curb = 0, nxtb = 1;
    for (int c = 0; c < nch; c++) {
        if (c + 1 < nch) {
            // target buffer (c+1)%3 is disjoint from buffers c%3 (about to be
            // read) and (c-1)%3 (possibly still read by straggler warps), so
            // no trailing barrier is needed.
            issue(c + 1, nxtb);
            CP_COMMIT();
            CP_WAIT(1);
        } else {
            CP_WAIT(0);
        }
        __syncthreads();   // cp.async visibility across threads + ring reuse

        uint32_t base = sb + curb * BUFSZ;
#pragma unroll
        for (int ks = 0; ks < 2; ks++) {
            uint32_t a_hi[2][4], a_lo[2][4];
#pragma unroll
            for (int mt = 0; mt < 2; mt++) {
                uint32_t off = (uint32_t)((wm * 32 + mt * 16 + a_row) * ROWB
                                          + ks * 32 + a_colb);
                ldsm_x4(a_hi[mt], base + SM_AH + off);
                ldsm_x4(a_lo[mt], base + SM_AL + off);
            }
            uint32_t b_hi[2][4];
#pragma unroll
            for (int p = 0; p < 2; p++) {
                uint32_t off = (uint32_t)((wn * 32 + p * 16 + b_row) * ROWB
                                          + ks * 32 + b_colb);
                ldsm_x4(b_hi[p], base + SM_BH + off);
            }
#pragma unroll
            for (int mt = 0; mt < 2; mt++)
#pragma unroll
                for (int p = 0; p < 2; p++) {
                    mma_f16(acc[mt][2*p],   a_hi[mt], &b_hi[p][0]);
                    mma_f16(acc[mt][2*p+1], a_hi[mt], &b_hi[p][2]);
                }
#pragma unroll
            for (int mt = 0; mt < 2; mt++)
#pragma unroll
                for (int p = 0; p < 2; p++) {
                    mma_f16(acc[mt][2*p],   a_lo[mt], &b_hi[p][0]);
                    mma_f16(acc[mt][2*p+1], a_lo[mt], &b_hi[p][2]);
                }
        }
        curb = nxtb;
        nxtb = (nxtb == 2) ? 0 : nxtb + 1;
    }

    int r0 = m0 + wm * 32 + (lane >> 2);
    int c0 = n0 + wn * 32 + (lane & 3) * 2;
#pragma unroll
    for (int mt = 0; mt < 2; mt++) {
#pragma unroll
        for (int nt = 0; nt < 4; nt++) {
            int r = r0 + mt * 16;
            int cc = c0 + nt * 8;
            float b0 = bias[cc], b1 = bias[cc + 1];
            float v0 = acc[mt][nt][0] + b0;
            float v1 = acc[mt][nt][1] + b1;
            float v2 = acc[mt][nt][2] + b0;
            float v3 = acc[mt][nt][3] + b1;
            if (EPI == 2) {
                v0 = gelu_f(v0); v1 = gelu_f(v1);
                v2 = gelu_f(v2); v3 = gelu_f(v3);
                uint32_t h01, l01, h23, l23;
                cvt_split2h(v0, v1, h01, l01);
                cvt_split2h(v2, v3, h23, l23);
                *(uint32_t*)(Ch + (size_t)r * N + cc) = h01;
                *(uint32_t*)(Cl + (size_t)r * N + cc) = l01;
                *(uint32_t*)(Ch + (size_t)(r + 8) * N + cc) = h23;
                *(uint32_t*)(Cl + (size_t)(r + 8) * N + cc) = l23;
            } else {
                if (EPI == 1) {
                    const float* rp0 = Res + (size_t)r * N + cc;
                    const float* rp1 = Res + (size_t)(r + 8) * N + cc;
                    v0 += rp0[0]; v1 += rp0[1];
                    v2 += rp1[0]; v3 += rp1[1];
                }
                *reinterpret_cast<float2*>(C + (size_t)r * N + cc) = make_float2(v0, v1);
                *reinterpret_cast<float2*>(C + (size_t)(r + 8) * N + cc) = make_float2(v2, v3);
            }
        }
    }
}

// ================= tensor-core causal flash attention ======================
#define FROWB 144
#define FT_QH 0
#define FT_QL (128*FROWB)
#define FT_KH (2*128*FROWB)
#define FT_KL (FT_KH + 64*FROWB)
#define FT_VH (FT_KL + 64*FROWB)
#define FT_VL (FT_VH + 64*FROWB)
#define FT_SMEM (FT_VL + 64*FROWB)   // 73728

__global__ __launch_bounds__(256, 2) void flash_tc_kernel() {
    extern __shared__ __align__(16) char fsm[];
    uint32_t sb = smem_u32(fsm);
    int bh = blockIdx.y;
    int b = bh / NH, h = bh % NH;
    int t0 = blockIdx.x * 128;
    const float* qb = g_qkv + (size_t)b * SEQ * QKVN + h * DH;
    const float* kb = qb + EMB;
    const float* vb = qb + 2 * EMB;
    int tid = threadIdx.x;
    int wid = tid >> 5, lane = tid & 31;

    int a_row = lane & 15;
    int a_colb = ((lane >> 4) * 8) * 2;
    int b_row = (lane & 7) + ((lane >> 4) & 1) * 8;
    int b_colb = (((lane >> 3) & 1) * 8) * 2;

    {
        int row = tid >> 1, d0 = (tid & 1) * 32;
        const float* qp = qb + (size_t)(t0 + row) * QKVN + d0;
#pragma unroll
        for (int i = 0; i < 8; i++) {
            float4 v = *reinterpret_cast<const float4*>(qp + 4 * i);
            uint32_t h01, l01, h23, l23;
            cvt_split2h(v.x, v.y, h01, l01);
            cvt_split2h(v.z, v.w, h23, l23);
            uint32_t off = (uint32_t)(row * FROWB + (d0 + 4 * i) * 2);
            *(uint32_t*)(fsm + FT_QH + off)     = h01;
            *(uint32_t*)(fsm + FT_QH + off + 4) = h23;
            *(uint32_t*)(fsm + FT_QL + off)     = l01;
            *(uint32_t*)(fsm + FT_QL + off + 4) = l23;
        }
    }

    float m0 = -1e30f, m1 = -1e30f, l0 = 0.f, l1 = 0.f;
    float O[8][4];
#pragma unroll
    for (int f = 0; f < 8; f++)
#pragma unroll
        for (int q = 0; q < 4; q++) O[f][q] = 0.f;

    int t_r0 = t0 + wid * 16 + (lane >> 2);
    int ntile = (t0 >> 6) + 2;

    for (int j = 0; j < ntile; j++) {
        __syncthreads();
        {
            int s = tid >> 2, d0 = (tid & 3) * 16;
            const float* kp = kb + (size_t)(j * 64 + s) * QKVN + d0;
            const float* vp = vb + (size_t)(j * 64 + s) * QKVN + d0;
#pragma unroll
            for (int i = 0; i < 4; i++) {
                float4 kv = *reinterpret_cast<const float4*>(kp + 4 * i);
                uint32_t h01, lo01, h23, lo23;
                cvt_split2h(kv.x, kv.y, h01, lo01);
                cvt_split2h(kv.z, kv.w, h23, lo23);
                uint32_t off = (uint32_t)(s * FROWB + (d0 + 4 * i) * 2);
                *(uint32_t*)(fsm + FT_KH + off)     = h01;
                *(uint32_t*)(fsm + FT_KH + off + 4) = h23;
                *(uint32_t*)(fsm + FT_KL + off)     = lo01;
                *(uint32_t*)(fsm + FT_KL + off + 4) = lo23;

                float4 vv = *reinterpret_cast<const float4*>(vp + 4 * i);
                float vals[4] = {vv.x, vv.y, vv.z, vv.w};
#pragma unroll
                for (int q = 0; q < 4; q++) {
                    int d = d0 + 4 * i + q;
                    __half hh = __float2half_rn(vals[q]);
                    __half ll = __float2half_rn(vals[q] - __half2float(hh));
                    *(__half*)(fsm + FT_VH + d * FROWB + s * 2) = hh;
                    *(__half*)(fsm + FT_VL + d * FROWB + s * 2) = ll;
                }
            }
        }
        __syncthreads();

        float S[8][4];
#pragma unroll
        for (int f = 0; f < 8; f++)
#pragma unroll
            for (int q = 0; q < 4; q++) S[f][q] = 0.f;
#pragma unroll
        for (int ks = 0; ks < 4; ks++) {
            uint32_t aq_h[4], aq_l[4];
            uint32_t aoff = (uint32_t)((wid * 16 + a_row) * FROWB + ks * 32 + a_colb);
            ldsm_x4(aq_h, sb + FT_QH + aoff);
            ldsm_x4(aq_l, sb + FT_QL + aoff);
#pragma unroll
            for (int p = 0; p < 4; p++) {
                uint32_t bk_h[4], bk_l[4];
                uint32_t boff = (uint32_t)((p * 16 + b_row) * FROWB + ks * 32 + b_colb);
                ldsm_x4(bk_h, sb + FT_KH + boff);
                ldsm_x4(bk_l, sb + FT_KL + boff);
                mma_f16(S[2*p],   aq_h, &bk_h[0]);
                mma_f16(S[2*p+1], aq_h, &bk_h[2]);
                mma_f16(S[2*p],   aq_l, &bk_h[0]);
                mma_f16(S[2*p+1], aq_l, &bk_h[2]);
                mma_f16(S[2*p],   aq_h, &bk_l[0]);
                mma_f16(S[2*p+1], aq_h, &bk_l[2]);
            }
        }

#pragma unroll
        for (int f = 0; f < 8; f++) {
            int c = j * 64 + (f >> 1) * 16 + (f & 1) * 8 + (lane & 3) * 2;
#pragma unroll
            for (int q = 0; q < 4; q++) S[f][q] *= 0.125f;
            if (c     > t_r0) S[f][0] = -1e30f;
            if (c + 1 > t_r0) S[f][1] = -1e30f;
            if (c     > t_r0 + 8) S[f][2] = -1e30f;
            if (c + 1 > t_r0 + 8) S[f][3] = -1e30f;
        }

        float mx0 = -1e30f, mx1 = -1e30f;
#pragma unroll
        for (int f = 0; f < 8; f++) {
            mx0 = fmaxf(mx0, fmaxf(S[f][0], S[f][1]));
            mx1 = fmaxf(mx1, fmaxf(S[f][2], S[f][3]));
        }
        mx0 = fmaxf(mx0, __shfl_xor_sync(0xffffffffu, mx0, 1));
        mx0 = fmaxf(mx0, __shfl_xor_sync(0xffffffffu, mx0, 2));
        mx1 = fmaxf(mx1, __shfl_xor_sync(0xffffffffu, mx1, 1));
        mx1 = fmaxf(mx1, __shfl_xor_sync(0xffffffffu, mx1, 2));
        float mn0 = fmaxf(m0, mx0), mn1 = fmaxf(m1, mx1);
        float c0 = __expf(m0 - mn0), c1 = __expf(m1 - mn1);
        m0 = mn0; m1 = mn1;
        float rs0 = 0.f, rs1 = 0.f;
#pragma unroll
        for (int f = 0; f < 8; f++) {
            S[f][0] = __expf(S[f][0] - mn0);
            S[f][1] = __expf(S[f][1] - mn0);
            S[f][2] = __expf(S[f][2] - mn1);
            S[f][3] = __expf(S[f][3] - mn1);
            rs0 += S[f][0] + S[f][1];
            rs1 += S[f][2] + S[f][3];
        }
        rs0 += __shfl_xor_sync(0xffffffffu, rs0, 1);
        rs0 += __shfl_xor_sync(0xffffffffu, rs0, 2);
        rs1 += __shfl_xor_sync(0xffffffffu, rs1, 1);
        rs1 += __shfl_xor_sync(0xffffffffu, rs1, 2);
        l0 = l0 * c0 + rs0;
        l1 = l1 * c1 + rs1;
#pragma unroll
        for (int f = 0; f < 8; f++) {
            O[f][0] *= c0; O[f][1] *= c0;
            O[f][2] *= c1; O[f][3] *= c1;
        }

#pragma unroll
        for (int g = 0; g < 4; g++) {
            uint32_t pa[4];
            __half2 p0 = __floats2half2_rn(S[2*g][0],   S[2*g][1]);
            __half2 p1 = __floats2half2_rn(S[2*g][2],   S[2*g][3]);
            __half2 p2 = __floats2half2_rn(S[2*g+1][0], S[2*g+1][1]);
            __half2 p3 = __floats2half2_rn(S[2*g+1][2], S[2*g+1][3]);
            pa[0] = *(uint32_t*)&p0;
            pa[1] = *(uint32_t*)&p1;
            pa[2] = *(uint32_t*)&p2;
            pa[3] = *(uint32_t*)&p3;
#pragma unroll
            for (int p = 0; p < 4; p++) {
                uint32_t bv_h[4], bv_l[4];
                uint32_t boff = (uint32_t)((p * 16 + b_row) * FROWB + g * 32 + b_colb);
                ldsm_x4(bv_h, sb + FT_VH + boff);
                ldsm_x4(bv_l, sb + FT_VL + boff);
                mma_f16(O[2*p],   pa, &bv_h[0]);
                mma_f16(O[2*p+1], pa, &bv_h[2]);
                mma_f16(O[2*p],   pa, &bv_l[0]);
                mma_f16(O[2*p+1], pa, &bv_l[2]);
            }
        }
    }

    float inv0 = 1.f / l0, inv1 = 1.f / l1;
#pragma unroll
    for (int f = 0; f < 8; f++) {
        int d = (f >> 1) * 16 + (f & 1) * 8 + (lane & 3) * 2;
        size_t base0 = (size_t)(b * SEQ + t_r0) * EMB + h * DH + d;
        size_t base1 = (size_t)(b * SEQ + t_r0 + 8) * EMB + h * DH + d;
        uint32_t hh, ll;
        cvt_split2h(O[f][0] * inv0, O[f][1] * inv0, hh, ll);
        *(uint32_t*)(g_atth + base0) = hh;
        *(uint32_t*)(g_attl + base0) = ll;
        cvt_split2h(O[f][2] * inv1, O[f][3] * inv1, hh, ll);
        *(uint32_t*)(g_atth + base1) = hh;
        *(uint32_t*)(g_attl + base1) = ll;
    }
}

// ---------------- head GEMM (N=60, FFMA) ----------------
__global__ __launch_bounds__(256) void head_gemm_kernel(
    const float* __restrict__ A,
    const float* __restrict__ Bm,
    const float* __restrict__ bias,
    float* __restrict__ C,
    int N, int K)
{
    __shared__ float As[16][68];
    __shared__ float Bs[16][64];
    int m0 = blockIdx.y * 64, n0 = blockIdx.x * 64;
    int tid = threadIdx.x;
    int tx = tid & 15, ty = tid >> 4;
    float acc[4][4] = {};
    for (int k0 = 0; k0 < K; k0 += 16) {
#pragma unroll
        for (int i = 0; i < 4; i++) {
            int lin = tid + i * 256;
            int r = lin >> 4, c = lin & 15;
            As[c][r] = A[(size_t)(m0 + r) * K + k0 + c];
        }
#pragma unroll
        for (int i = 0; i < 4; i++) {
            int lin = tid + i * 256;
            int r = lin >> 6, c = lin & 63;
            int n = n0 + c;
            Bs[r][c] = (n < N) ? Bm[(size_t)(k0 + r) * N + n] : 0.f;
        }
        __syncthreads();
#pragma unroll
        for (int kk = 0; kk < 16; kk++) {
            float4 a4 = *reinterpret_cast<const float4*>(&As[kk][ty * 4]);
            float4 b4 = *reinterpret_cast<const float4*>(&Bs[kk][tx * 4]);
            float a[4] = {a4.x, a4.y, a4.z, a4.w};
            float bv[4] = {b4.x, b4.y, b4.z, b4.w};
#pragma unroll
            for (int i = 0; i < 4; i++)
#pragma unroll
                for (int j = 0; j < 4; j++)
                    acc[i][j] = fmaf(a[i], bv[j], acc[i][j]);
        }
        __syncthreads();
    }
#pragma unroll
    for (int i = 0; i < 4; i++) {
        int m = m0 + ty * 4 + i;
#pragma unroll
        for (int j = 0; j < 4; j++) {
            int n = n0 + tx * 4 + j;
            if (n < N) C[(size_t)m * N + n] = acc[i][j] + bias[n];
        }
    }
}

// ---------------- host orchestration ----------------
extern "C" void kernel_launch(void* const* d_in, const int* in_sizes, int n_in,
                              void* d_out, int out_size) {
    const int*   ids          = (const int*)d_in[0];
    const int*   mul          = (const int*)d_in[1];
    const float* tok_emb      = (const float*)d_in[2];
    const float* state_emb    = (const float*)d_in[3];
    const float* state_proj_w = (const float*)d_in[4];
    const float* state_proj_b = (const float*)d_in[5];
    const float* wpe          = (const float*)d_in[6];
    const float* ln1_g        = (const float*)d_in[7];
    const float* ln1_b        = (const float*)d_in[8];
    const float* attn_w       = (const float*)d_in[9];
    const float* attn_b       = (const float*)d_in[10];
    const float* attn_proj_w  = (const float*)d_in[11];
    const float* attn_proj_b  = (const float*)d_in[12];
    const float* ln2_g        = (const float*)d_in[13];
    const float* ln2_b        = (const float*)d_in[14];
    const float* fc_w         = (const float*)d_in[15];
    const float* fc_b         = (const float*)d_in[16];
    const float* mlp_proj_w   = (const float*)d_in[17];
    const float* mlp_proj_b   = (const float*)d_in[18];
    const float* lnf_g        = (const float*)d_in[19];
    const float* lnf_b        = (const float*)d_in[20];
    const float* head_w       = (const float*)d_in[21];
    const float* head_b       = (const float*)d_in[22];
    float* out = (float*)d_out;

    float *h, *lnbuf, *qkv;
    __half *wh, *lnh, *lnl, *atth, *attl, *midh, *midl;
    cudaGetSymbolAddress((void**)&h,     g_h);
    cudaGetSymbolAddress((void**)&lnbuf, g_ln);
    cudaGetSymbolAddress((void**)&qkv,   g_qkv);
    cudaGetSymbolAddress((void**)&wh,    g_wh);
    cudaGetSymbolAddress((void**)&lnh,   g_lnh);
    cudaGetSymbolAddress((void**)&lnl,   g_lnl);
    cudaGetSymbolAddress((void**)&atth,  g_atth);
    cudaGetSymbolAddress((void**)&attl,  g_attl);
    cudaGetSymbolAddress((void**)&midh,  g_midh);
    cudaGetSymbolAddress((void**)&midl,  g_midl);

    cudaFuncSetAttribute(mma_gemm<0>, cudaFuncAttributeMaxDynamicSharedMemorySize, GEMM_SMEM);
    cudaFuncSetAttribute(mma_gemm<1>, cudaFuncAttributeMaxDynamicSharedMemorySize, GEMM_SMEM);
    cudaFuncSetAttribute(mma_gemm<2>, cudaFuncAttributeMaxDynamicSharedMemorySize, GEMM_SMEM);
    cudaFuncSetAttribute(flash_tc_kernel, cudaFuncAttributeMaxDynamicSharedMemorySize, FT_SMEM);

    wconv_kernel<<<dim3(QKVN/32, EMB/32, NLAYER), 256>>>(attn_w, wh + OFF_QKV, EMB, QKVN);
    wconv_kernel<<<dim3(EMB/32, EMB/32, NLAYER), 256>>>(attn_proj_w, wh + OFF_PROJ, EMB, EMB);
    wconv_kernel<<<dim3(FFN/32, EMB/32, NLAYER), 256>>>(fc_w, wh + OFF_FC, EMB, FFN);
    wconv_kernel<<<dim3(EMB/32, FFN/32, NLAYER), 256>>>(mlp_proj_w, wh + OFF_MLP, FFN, EMB);

    state_scan_kernel<<<1, 256>>>(ids, mul);
    state_proj_kernel<<<(VOC * EMB + 255) / 256, 256>>>(state_emb, state_proj_w, state_proj_b);
    embed_kernel<<<(BT * EMB + 255) / 256, 256>>>(ids, tok_emb, wpe);

    for (int l = 0; l < NLAYER; l++) {
        ln_f16_kernel<<<BT, 256>>>(h, ln1_g + l * EMB, ln1_b + l * EMB, lnh, lnl);
        mma_gemm<0><<<dim3(QKVN/64, BT/128), 256, GEMM_SMEM>>>(
            lnh, lnl, wh + OFF_QKV + (size_t)l * W_QKV,
            attn_b + l * QKVN, nullptr, qkv, nullptr, nullptr, EMB, QKVN);
        flash_tc_kernel<<<dim3(SEQ/128, BATCH * NH), 256, FT_SMEM>>>();
        mma_gemm<1><<<dim3(EMB/64, BT/128), 256, GEMM_SMEM>>>(
            atth, attl, wh + OFF_PROJ + (size_t)l * W_PROJ,
            attn_proj_b + l * EMB, h, h, nullptr, nullptr, EMB, EMB);
        ln_f16_kernel<<<BT, 256>>>(h, ln2_g + l * EMB, ln2_b + l * EMB, lnh, lnl);
        mma_gemm<2><<<dim3(FFN/64, BT/128), 256, GEMM_SMEM>>>(
            lnh, lnl, wh + OFF_FC + (size_t)l * W_FC,
            fc_b + l * FFN, nullptr, nullptr, midh, midl, EMB, FFN);
        mma_gemm<1><<<dim3(EMB/64, BT/128), 256, GEMM_SMEM>>>(
            midh, midl, wh + OFF_MLP + (size_t)l * W_MLP,
            mlp_proj_b + l * EMB, h, h, nullptr, nullptr, FFN, EMB);
    }

    ln_kernel<<<BT, 256>>>(h, lnf_g, lnf_b, lnbuf);
    head_gemm_kernel<<<dim3(1, BT / 64), 256>>>(lnbuf, head_w, head_b, out, VOC, EMB);
}

// round 13
// speedup vs baseline: 1.1995x; 1.0187x over previous
#include <cuda_runtime.h>
#include <cuda_fp16.h>
#include <math.h>
#include <stdint.h>

#define BATCH 8
#define SEQ 512
#define BT (BATCH*SEQ)        // 4096
#define EMB 768
#define NH 12
#define DH 64
#define VOC 60
#define DST 128
#define NLAYER 12
#define QKVN (3*EMB)          // 2304
#define FFN (4*EMB)           // 3072

#define W_QKV (QKVN*EMB)
#define W_PROJ (EMB*EMB)
#define W_FC (FFN*EMB)
#define W_MLP (EMB*FFN)
#define OFF_QKV 0
#define OFF_PROJ (12*W_QKV)
#define OFF_FC (OFF_PROJ + 12*W_PROJ)
#define OFF_MLP (OFF_FC + 12*W_FC)
#define W_TOTAL (OFF_MLP + 12*W_MLP)

// ---------------- scratch ----------------
__device__ float g_h[BT*EMB];
__device__ float g_ln[BT*EMB];
__device__ float g_semb[VOC*EMB];
__device__ int   g_pre[BT];

__device__ __half g_wh[W_TOTAL];                 // weights, single fp16, [N][K]
__device__ __half g_lnh[BT*EMB],  g_lnl[BT*EMB]; // activations, fp16 hi/lo
__device__ __half g_atth[BT*EMB], g_attl[BT*EMB];
__device__ __half g_midh[BT*FFN], g_midl[BT*FFN];
// QKV split outputs: Q at [0, BT*EMB), K at [BT*EMB, 2*BT*EMB), row-major [bt][hd]
__device__ __half g_qkh[2*BT*EMB], g_qkl[2*BT*EMB];
// V transposed: [bh][d][s]
__device__ __half g_vth[BATCH*NH*DH*SEQ], g_vtl[BATCH*NH*DH*SEQ];

// ---------------- helpers ----------------
__device__ __forceinline__ uint32_t smem_u32(const void* p) {
    uint32_t a;
    asm("{ .reg .u64 t; cvta.to.shared.u64 t, %1; cvt.u32.u64 %0, t; }" : "=r"(a) : "l"(p));
    return a;
}

__device__ __forceinline__ void ldsm_x4(uint32_t* r, uint32_t addr) {
    asm volatile("ldmatrix.sync.aligned.m8n8.x4.shared.b16 {%0,%1,%2,%3}, [%4];"
        : "=r"(r[0]), "=r"(r[1]), "=r"(r[2]), "=r"(r[3]) : "r"(addr));
}

__device__ __forceinline__ void mma_f16(float* c, const uint32_t* a, const uint32_t* b) {
    asm volatile("mma.sync.aligned.m16n8k16.row.col.f32.f16.f16.f32 "
        "{%0,%1,%2,%3}, {%4,%5,%6,%7}, {%8,%9}, {%0,%1,%2,%3};"
        : "+f"(c[0]), "+f"(c[1]), "+f"(c[2]), "+f"(c[3])
        : "r"(a[0]), "r"(a[1]), "r"(a[2]), "r"(a[3]), "r"(b[0]), "r"(b[1]));
}

__device__ __forceinline__ void cp16(uint32_t dst, const void* src) {
    asm volatile("cp.async.cg.shared.global [%0], [%1], 16;" :: "r"(dst), "l"(src));
}
#define CP_COMMIT() asm volatile("cp.async.commit_group;" ::: "memory")
#define CP_WAIT(n)  asm volatile("cp.async.wait_group %0;" :: "n"(n) : "memory")

__device__ __forceinline__ void cvt_split2h(float x0, float x1, uint32_t& hi, uint32_t& lo) {
    __half h0 = __float2half_rn(x0);
    __half h1 = __float2half_rn(x1);
    __half l0 = __float2half_rn(x0 - __half2float(h0));
    __half l1 = __float2half_rn(x1 - __half2float(h1));
    __half2 H(h0, h1), L(l0, l1);
    hi = *(uint32_t*)&H;
    lo = *(uint32_t*)&L;
}

// ---------------- reductions ----------------
__device__ __forceinline__ float breduce_sum(float v, float* sh, int nthr) {
#pragma unroll
    for (int o = 16; o > 0; o >>= 1) v += __shfl_xor_sync(0xffffffffu, v, o);
    int lane = threadIdx.x & 31, w = threadIdx.x >> 5;
    if (lane == 0) sh[w] = v;
    __syncthreads();
    float r = 0.f;
    if ((int)threadIdx.x < (nthr >> 5)) r = sh[threadIdx.x];
    if (threadIdx.x < 32) {
#pragma unroll
        for (int o = 16; o > 0; o >>= 1) r += __shfl_xor_sync(0xffffffffu, r, o);
        if (threadIdx.x == 0) sh[0] = r;
    }
    __syncthreads();
    r = sh[0];
    __syncthreads();
    return r;
}

// ---------------- automaton state scan ----------------
__global__ void state_scan_kernel(const int* __restrict__ ids, const int* __restrict__ mul) {
    __shared__ int smul[VOC*VOC];
    __shared__ int sids[BT];
    int tid = threadIdx.x;
    for (int i = tid; i < VOC*VOC; i += blockDim.x) smul[i] = mul[i];
    for (int i = tid; i < BT; i += blockDim.x) sids[i] = ids[i];
    __syncthreads();
    if (tid < BATCH) {
        int s = 0;
        const int* row = sids + tid * SEQ;
        int* pre = g_pre + tid * SEQ;
        for (int t = 0; t < SEQ; t++) {
            pre[t] = s;
            s = smul[row[t] * VOC + s];
        }
    }
}

__global__ void state_proj_kernel(const float* __restrict__ semb,
                                  const float* __restrict__ W,
                                  const float* __restrict__ b) {
    int idx = blockIdx.x * blockDim.x + threadIdx.x;
    if (idx >= VOC * EMB) return;
    int v = idx / EMB, e = idx % EMB;
    float acc = b[e];
#pragma unroll 8
    for (int d = 0; d < DST; d++) acc += semb[v * DST + d] * W[d * EMB + e];
    g_semb[idx] = acc;
}

__global__ void embed_kernel(const int* __restrict__ ids,
                             const float* __restrict__ tok_emb,
                             const float* __restrict__ wpe) {
    int idx = blockIdx.x * blockDim.x + threadIdx.x;
    if (idx >= BT * EMB) return;
    int bt = idx / EMB, e = idx % EMB;
    int t = bt % SEQ;
    g_h[idx] = tok_emb[ids[bt] * EMB + e] + g_semb[g_pre[bt] * EMB + e] + wpe[t * EMB + e];
}

// ---------------- weight convert: W[K][N] fp32 -> fp16 [N][K] --------------
__global__ __launch_bounds__(256) void wconv_kernel(
    const float* __restrict__ W, __half* __restrict__ Hi, int K, int N)
{
    __shared__ float t[32][33];
    int l = blockIdx.z;
    const float* Wl = W + (size_t)l * K * N;
    __half* Hl = Hi + (size_t)l * K * N;
    int n0 = blockIdx.x * 32, k0 = blockIdx.y * 32;
    int tx = threadIdx.x & 31, ty = threadIdx.x >> 5;
#pragma unroll
    for (int j = 0; j < 4; j++)
        t[ty + 8 * j][tx] = Wl[(size_t)(k0 + ty + 8 * j) * N + n0 + tx];
    __syncthreads();
#pragma unroll
    for (int j = 0; j < 4; j++) {
        float v = t[tx][ty + 8 * j];
        Hl[(size_t)(n0 + ty + 8 * j) * K + k0 + tx] = __float2half_rn(v);
    }
}

// ---------------- layernorm variants ----------------
__global__ __launch_bounds__(256) void ln_kernel(const float* __restrict__ x,
                                                 const float* __restrict__ g,
                                                 const float* __restrict__ b,
                                                 float* __restrict__ y) {
    __shared__ float sh[8];
    int row = blockIdx.x, tid = threadIdx.x;
    const float* xr = x + (size_t)row * EMB;
    float v0 = xr[tid], v1 = xr[tid + 256], v2 = xr[tid + 512];
    float mean = breduce_sum(v0 + v1 + v2, sh, 256) * (1.f / EMB);
    float d0 = v0 - mean, d1 = v1 - mean, d2 = v2 - mean;
    float var = breduce_sum(d0*d0 + d1*d1 + d2*d2, sh, 256) * (1.f / EMB);
    float rstd = rsqrtf(var + 1e-5f);
    float* yr = y + (size_t)row * EMB;
    yr[tid]       = d0 * rstd * g[tid]       + b[tid];
    yr[tid + 256] = d1 * rstd * g[tid + 256] + b[tid + 256];
    yr[tid + 512] = d2 * rstd * g[tid + 512] + b[tid + 512];
}

__global__ __launch_bounds__(256) void ln_f16_kernel(const float* __restrict__ x,
                                                     const float* __restrict__ g,
                                                     const float* __restrict__ b,
                                                     __half* __restrict__ yh,
                                                     __half* __restrict__ yl) {
    __shared__ float sh[8];
    int row = blockIdx.x, tid = threadIdx.x;
    const float* xr = x + (size_t)row * EMB;
    float v0 = xr[tid], v1 = xr[tid + 256], v2 = xr[tid + 512];
    float mean = breduce_sum(v0 + v1 + v2, sh, 256) * (1.f / EMB);
    float d0 = v0 - mean, d1 = v1 - mean, d2 = v2 - mean;
    float var = breduce_sum(d0*d0 + d1*d1 + d2*d2, sh, 256) * (1.f / EMB);
    float rstd = rsqrtf(var + 1e-5f);
    size_t base = (size_t)row * EMB;
#pragma unroll
    for (int q = 0; q < 3; q++) {
        int e = tid + q * 256;
        float d = (q == 0) ? d0 : (q == 1) ? d1 : d2;
        float v = d * rstd * g[e] + b[e];
        __half h = __float2half_rn(v);
        yh[base + e] = h;
        yl[base + e] = __float2half_rn(v - __half2float(h));
    }
}

// ================= mma.sync fp16 2-term GEMM (3-deep ring, R12 proven) =====
// EPI: 0=fp32 C; 1=fp32 C+Res; 2=bf16 split of gelu; 3=QKV fp16 split
//      (Q,K row-major into Ch/Cl, K at +BT*EMB; V transposed into Vh/Vl).
__device__ __forceinline__ float gelu_f(float x) {
    return 0.5f * x * (1.f + tanhf(0.7978845608028654f * (x + 0.044715f * x * x * x)));
}

#define ROWB 80
#define SM_AH 0
#define SM_AL 10240
#define SM_BH 20480
#define BUFSZ 25600
#define GEMM_SMEM (3*BUFSZ)   // 76800/CTA

template<int EPI>
__global__ __launch_bounds__(256, 2) void mma_gemm(
    const __half* __restrict__ Ah, const __half* __restrict__ Al,
    const __half* __restrict__ Bh,
    const float* __restrict__ bias,
    const float* __restrict__ Res,
    float* __restrict__ C,
    __half* __restrict__ Ch, __half* __restrict__ Cl,
    __half* __restrict__ Vh, __half* __restrict__ Vl,
    int K, int N)
{
    extern __shared__ __align__(16) char sm[];
    uint32_t sb = smem_u32(sm);
    int tid = threadIdx.x;
    int wid = tid >> 5, lane = tid & 31;
    int wm = wid & 3, wn = wid >> 2;
    int m0 = blockIdx.y * 128, n0 = blockIdx.x * 64;

    int p_row = tid >> 2;
    int p_seg = tid & 3;

    int a_row = lane & 15;
    int a_colb = ((lane >> 4) * 8) * 2;
    int b_row = (lane & 7) + ((lane >> 4) & 1) * 8;
    int b_colb = (((lane >> 3) & 1) * 8) * 2;

    float acc[2][4][4];
#pragma unroll
    for (int i = 0; i < 2; i++)
#pragma unroll
        for (int j = 0; j < 4; j++)
#pragma unroll
            for (int q = 0; q < 4; q++) acc[i][j][q] = 0.f;

    const int nch = K >> 5;

    auto issue = [&](int c, int bufsel) {
        int k0 = c << 5;
        uint32_t base = sb + bufsel * BUFSZ;
        uint32_t doff = (uint32_t)(p_row * ROWB + p_seg * 16);
#pragma unroll
        for (int i = 0; i < 2; i++) {
            int row = p_row + i * 64;
            size_t aoff = (size_t)(m0 + row) * K + k0 + p_seg * 8;
            cp16(base + SM_AH + doff + i * (64 * ROWB), Ah + aoff);
            cp16(base + SM_AL + doff + i * (64 * ROWB), Al + aoff);
        }
        size_t boff = (size_t)(n0 + p_row) * K + k0 + p_seg * 8;
        cp16(base + SM_BH + doff, Bh + boff);
    };

    issue(0, 0);
    CP_COMMIT();

    int curb = 0, nxtb = 1;
    for (int c = 0; c < nch; c++) {
        if (c + 1 < nch) {
            issue(c + 1, nxtb);
            CP_COMMIT();
            CP_WAIT(1);
        } else {
            CP_WAIT(0);
        }
        __syncthreads();

        uint32_t base = sb + curb * BUFSZ;
#pragma unroll
        for (int ks = 0; ks < 2; ks++) {
            uint32_t a_hi[2][4], a_lo[2][4];
#pragma unroll
            for (int mt = 0; mt < 2; mt++) {
                uint32_t off = (uint32_t)((wm * 32 + mt * 16 + a_row) * ROWB
                                          + ks * 32 + a_colb);
                ldsm_x4(a_hi[mt], base + SM_AH + off);
                ldsm_x4(a_lo[mt], base + SM_AL + off);
            }
            uint32_t b_hi[2][4];
#pragma unroll
            for (int p = 0; p < 2; p++) {
                uint32_t off = (uint32_t)((wn * 32 + p * 16 + b_row) * ROWB
                                          + ks * 32 + b_colb);
                ldsm_x4(b_hi[p], base + SM_BH + off);
            }
#pragma unroll
            for (int mt = 0; mt < 2; mt++)
#pragma unroll
                for (int p = 0; p < 2; p++) {
                    mma_f16(acc[mt][2*p],   a_hi[mt], &b_hi[p][0]);
                    mma_f16(acc[mt][2*p+1], a_hi[mt], &b_hi[p][2]);
                }
#pragma unroll
            for (int mt = 0; mt < 2; mt++)
#pragma unroll
                for (int p = 0; p < 2; p++) {
                    mma_f16(acc[mt][2*p],   a_lo[mt], &b_hi[p][0]);
                    mma_f16(acc[mt][2*p+1], a_lo[mt], &b_hi[p][2]);
                }
        }
        curb = nxtb;
        nxtb = (nxtb == 2) ? 0 : nxtb + 1;
    }

    int r0 = m0 + wm * 32 + (lane >> 2);
    int c0 = n0 + wn * 32 + (lane & 3) * 2;
#pragma unroll
    for (int mt = 0; mt < 2; mt++) {
#pragma unroll
        for (int nt = 0; nt < 4; nt++) {
            int r = r0 + mt * 16;
            int cc = c0 + nt * 8;
            float b0 = bias[cc], b1 = bias[cc + 1];
            float v0 = acc[mt][nt][0] + b0;
            float v1 = acc[mt][nt][1] + b1;
            float v2 = acc[mt][nt][2] + b0;
            float v3 = acc[mt][nt][3] + b1;
            if (EPI == 2) {
                v0 = gelu_f(v0); v1 = gelu_f(v1);
                v2 = gelu_f(v2); v3 = gelu_f(v3);
                uint32_t h01, l01, h23, l23;
                cvt_split2h(v0, v1, h01, l01);
                cvt_split2h(v2, v3, h23, l23);
                *(uint32_t*)(Ch + (size_t)r * N + cc) = h01;
                *(uint32_t*)(Cl + (size_t)r * N + cc) = l01;
                *(uint32_t*)(Ch + (size_t)(r + 8) * N + cc) = h23;
                *(uint32_t*)(Cl + (size_t)(r + 8) * N + cc) = l23;
            } else if (EPI == 3) {
                if (cc < 1536) {
                    // Q (cc<768) or K region: row-major fp16 hi/lo
                    int kk = (cc >= 768);
                    size_t idx = (size_t)kk * (BT * EMB)
                               + (size_t)r * EMB + (cc - kk * 768);
                    uint32_t h01, l01, h23, l23;
                    cvt_split2h(v0, v1, h01, l01);
                    cvt_split2h(v2, v3, h23, l23);
                    *(uint32_t*)(Ch + idx) = h01;
                    *(uint32_t*)(Cl + idx) = l01;
                    *(uint32_t*)(Ch + idx + (size_t)8 * EMB) = h23;
                    *(uint32_t*)(Cl + idx + (size_t)8 * EMB) = l23;
                } else {
                    // V region: transposed [bh][d][s]
                    int b = r >> 9, s = r & 511;
                    int hd = cc - 1536;
                    int hh_ = hd >> 6, d = hd & 63;
                    size_t idx = ((size_t)(b * NH + hh_) * 64 + d) * 512 + s;
                    __half a0 = __float2half_rn(v0);
                    Vh[idx] = a0;
                    Vl[idx] = __float2half_rn(v0 - __half2float(a0));
                    __half a1 = __float2half_rn(v1);
                    Vh[idx + 512] = a1;
                    Vl[idx + 512] = __float2half_rn(v1 - __half2float(a1));
                    __half a2 = __float2half_rn(v2);
                    Vh[idx + 8] = a2;
                    Vl[idx + 8] = __float2half_rn(v2 - __half2float(a2));
                    __half a3 = __float2half_rn(v3);
                    Vh[idx + 512 + 8] = a3;
                    Vl[idx + 512 + 8] = __float2half_rn(v3 - __half2float(a3));
                }
            } else {
                if (EPI == 1) {
                    const float* rp0 = Res + (size_t)r * N + cc;
                    const float* rp1 = Res + (size_t)(r + 8) * N + cc;
                    v0 += rp0[0]; v1 += rp0[1];
                    v2 += rp1[0]; v3 += rp1[1];
                }
                *reinterpret_cast<float2*>(C + (size_t)r * N + cc) = make_float2(v0, v1);
                *reinterpret_cast<float2*>(C + (size_t)(r + 8) * N + cc) = make_float2(v2, v3);
            }
        }
    }
}

// ================= tensor-core causal flash attention ======================
// Q/K/V already fp16 hi/lo in global (V pre-transposed); pure cp.async loads.
#define FROWB 144
#define FT_QH 0
#define FT_QL (128*FROWB)
#define FT_KH (2*128*FROWB)
#define FT_KL (FT_KH + 64*FROWB)
#define FT_VH (FT_KL + 64*FROWB)
#define FT_VL (FT_VH + 64*FROWB)
#define FT_SMEM (FT_VL + 64*FROWB)   // 73728

__global__ __launch_bounds__(256, 2) void flash_tc_kernel() {
    extern __shared__ __align__(16) char fsm[];
    uint32_t sb = smem_u32(fsm);
    int bh = blockIdx.y;
    int b = bh / NH, h = bh % NH;
    int t0 = blockIdx.x * 128;
    int tid = threadIdx.x;
    int wid = tid >> 5, lane = tid & 31;

    const __half* Kh = g_qkh + (size_t)BT * EMB;
    const __half* Kl = g_qkl + (size_t)BT * EMB;

    int a_row = lane & 15;
    int a_colb = ((lane >> 4) * 8) * 2;
    int b_row = (lane & 7) + ((lane >> 4) & 1) * 8;
    int b_colb = (((lane >> 3) & 1) * 8) * 2;

    // stage Q via cp.async (row-major fp16 hi/lo, 128B per row)
    {
        int row = tid >> 1, hf = tid & 1;
        size_t qoff = (size_t)(b * SEQ + t0 + row) * EMB + h * DH + hf * 32;
        uint32_t dh_ = sb + FT_QH + row * FROWB + hf * 64;
        uint32_t dl_ = sb + FT_QL + row * FROWB + hf * 64;
#pragma unroll
        for (int i = 0; i < 4; i++) {
            cp16(dh_ + 16 * i, g_qkh + qoff + 8 * i);
            cp16(dl_ + 16 * i, g_qkl + qoff + 8 * i);
        }
        CP_COMMIT();
    }

    float m0 = -1e30f, m1 = -1e30f, l0 = 0.f, l1 = 0.f;
    float O[8][4];
#pragma unroll
    for (int f = 0; f < 8; f++)
#pragma unroll
        for (int q = 0; q < 4; q++) O[f][q] = 0.f;

    int t_r0 = t0 + wid * 16 + (lane >> 2);
    int ntile = (t0 >> 6) + 2;

    for (int j = 0; j < ntile; j++) {
        __syncthreads();   // previous tile's smem reads complete
        {
            int s = tid >> 2, seg = tid & 3;   // s doubles as d for V
            size_t koff = (size_t)(b * SEQ + j * 64 + s) * EMB + h * DH + seg * 16;
            uint32_t kdh = sb + FT_KH + s * FROWB + seg * 32;
            uint32_t kdl = sb + FT_KL + s * FROWB + seg * 32;
            cp16(kdh,      Kh + koff);
            cp16(kdh + 16, Kh + koff + 8);
            cp16(kdl,      Kl + koff);
            cp16(kdl + 16, Kl + koff + 8);
            size_t voff = ((size_t)bh * 64 + s) * 512 + j * 64 + seg * 16;
            uint32_t vdh = sb + FT_VH + s * FROWB + seg * 32;
            uint32_t vdl = sb + FT_VL + s * FROWB + seg * 32;
            cp16(vdh,      g_vth + voff);
            cp16(vdh + 16, g_vth + voff + 8);
            cp16(vdl,      g_vtl + voff);
            cp16(vdl + 16, g_vtl + voff + 8);
        }
        CP_COMMIT();
        CP_WAIT(0);
        __syncthreads();

        float S[8][4];
#pragma unroll
        for (int f = 0; f < 8; f++)
#pragma unroll
            for (int q = 0; q < 4; q++) S[f][q] = 0.f;
#pragma unroll
        for (int ks = 0; ks < 4; ks++) {
            uint32_t aq_h[4], aq_l[4];
            uint32_t aoff = (uint32_t)((wid * 16 + a_row) * FROWB + ks * 32 + a_colb);
            ldsm_x4(aq_h, sb + FT_QH + aoff);
            ldsm_x4(aq_l, sb + FT_QL + aoff);
#pragma unroll
            for (int p = 0; p < 4; p++) {
                uint32_t bk_h[4], bk_l[4];
                uint32_t boff = (uint32_t)((p * 16 + b_row) * FROWB + ks * 32 + b_colb);
                ldsm_x4(bk_h, sb + FT_KH + boff);
                ldsm_x4(bk_l, sb + FT_KL + boff);
                mma_f16(S[2*p],   aq_h, &bk_h[0]);
                mma_f16(S[2*p+1], aq_h, &bk_h[2]);
                mma_f16(S[2*p],   aq_l, &bk_h[0]);
                mma_f16(S[2*p+1], aq_l, &bk_h[2]);
                mma_f16(S[2*p],   aq_h, &bk_l[0]);
                mma_f16(S[2*p+1], aq_h, &bk_l[2]);
            }
        }

#pragma unroll
        for (int f = 0; f < 8; f++) {
            int c = j * 64 + (f >> 1) * 16 + (f & 1) * 8 + (lane & 3) * 2;
#pragma unroll
            for (int q = 0; q < 4; q++) S[f][q] *= 0.125f;
            if (c     > t_r0) S[f][0] = -1e30f;
            if (c + 1 > t_r0) S[f][1] = -1e30f;
            if (c     > t_r0 + 8) S[f][2] = -1e30f;
            if (c + 1 > t_r0 + 8) S[f][3] = -1e30f;
        }

        float mx0 = -1e30f, mx1 = -1e30f;
#pragma unroll
        for (int f = 0; f < 8; f++) {
            mx0 = fmaxf(mx0, fmaxf(S[f][0], S[f][1]));
            mx1 = fmaxf(mx1, fmaxf(S[f][2], S[f][3]));
        }
        mx0 = fmaxf(mx0, __shfl_xor_sync(0xffffffffu, mx0, 1));
        mx0 = fmaxf(mx0, __shfl_xor_sync(0xffffffffu, mx0, 2));
        mx1 = fmaxf(mx1, __shfl_xor_sync(0xffffffffu, mx1, 1));
        mx1 = fmaxf(mx1, __shfl_xor_sync(0xffffffffu, mx1, 2));
        float mn0 = fmaxf(m0, mx0), mn1 = fmaxf(m1, mx1);
        float c0 = __expf(m0 - mn0), c1 = __expf(m1 - mn1);
        m0 = mn0; m1 = mn1;
        float rs0 = 0.f, rs1 = 0.f;
#pragma unroll
        for (int f = 0; f < 8; f++) {
            S[f][0] = __expf(S[f][0] - mn0);
            S[f][1] = __expf(S[f][1] - mn0);
            S[f][2] = __expf(S[f][2] - mn1);
            S[f][3] = __expf(S[f][3] - mn1);
            rs0 += S[f][0] + S[f][1];
            rs1 += S[f][2] + S[f][3];
        }
        rs0 += __shfl_xor_sync(0xffffffffu, rs0, 1);
        rs0 += __shfl_xor_sync(0xffffffffu, rs0, 2);
        rs1 += __shfl_xor_sync(0xffffffffu, rs1, 1);
        rs1 += __shfl_xor_sync(0xffffffffu, rs1, 2);
        l0 = l0 * c0 + rs0;
        l1 = l1 * c1 + rs1;
#pragma unroll
        for (int f = 0; f < 8; f++) {
            O[f][0] *= c0; O[f][1] *= c0;
            O[f][2] *= c1; O[f][3] *= c1;
        }

#pragma unroll
        for (int g = 0; g < 4; g++) {
            uint32_t pa[4];
            __half2 p0 = __floats2half2_rn(S[2*g][0],   S[2*g][1]);
            __half2 p1 = __floats2half2_rn(S[2*g][2],   S[2*g][3]);
            __half2 p2 = __floats2half2_rn(S[2*g+1][0], S[2*g+1][1]);
            __half2 p3 = __floats2half2_rn(S[2*g+1][2], S[2*g+1][3]);
            pa[0] = *(uint32_t*)&p0;
            pa[1] = *(uint32_t*)&p1;
            pa[2] = *(uint32_t*)&p2;
            pa[3] = *(uint32_t*)&p3;
#pragma unroll
            for (int p = 0; p < 4; p++) {
                uint32_t bv_h[4], bv_l[4];
                uint32_t boff = (uint32_t)((p * 16 + b_row) * FROWB + g * 32 + b_colb);
                ldsm_x4(bv_h, sb + FT_VH + boff);
                ldsm_x4(bv_l, sb + FT_VL + boff);
                mma_f16(O[2*p],   pa, &bv_h[0]);
                mma_f16(O[2*p+1], pa, &bv_h[2]);
                mma_f16(O[2*p],   pa, &bv_l[0]);
                mma_f16(O[2*p+1], pa, &bv_l[2]);
            }
        }
    }

    float inv0 = 1.f / l0, inv1 = 1.f / l1;
#pragma unroll
    for (int f = 0; f < 8; f++) {
        int d = (f >> 1) * 16 + (f & 1) * 8 + (lane & 3) * 2;
        size_t base0 = (size_t)(b * SEQ + t_r0) * EMB + h * DH + d;
        size_t base1 = (size_t)(b * SEQ + t_r0 + 8) * EMB + h * DH + d;
        uint32_t hh, ll;
        cvt_split2h(O[f][0] * inv0, O[f][1] * inv0, hh, ll);
        *(uint32_t*)(g_atth + base0) = hh;
        *(uint32_t*)(g_attl + base0) = ll;
        cvt_split2h(O[f][2] * inv1, O[f][3] * inv1, hh, ll);
        *(uint32_t*)(g_atth + base1) = hh;
        *(uint32_t*)(g_attl + base1) = ll;
    }
}

// ---------------- head GEMM (N=60, FFMA) ----------------
__global__ __launch_bounds__(256) void head_gemm_kernel(
    const float* __restrict__ A,
    const float* __restrict__ Bm,
    const float* __restrict__ bias,
    float* __restrict__ C,
    int N, int K)
{
    __shared__ float As[16][68];
    __shared__ float Bs[16][64];
    int m0 = blockIdx.y * 64, n0 = blockIdx.x * 64;
    int tid = threadIdx.x;
    int tx = tid & 15, ty = tid >> 4;
    float acc[4][4] = {};
    for (int k0 = 0; k0 < K; k0 += 16) {
#pragma unroll
        for (int i = 0; i < 4; i++) {
            int lin = tid + i * 256;
            int r = lin >> 4, c = lin & 15;
            As[c][r] = A[(size_t)(m0 + r) * K + k0 + c];
        }
#pragma unroll
        for (int i = 0; i < 4; i++) {
            int lin = tid + i * 256;
            int r = lin >> 6, c = lin & 63;
            int n = n0 + c;
            Bs[r][c] = (n < N) ? Bm[(size_t)(k0 + r) * N + n] : 0.f;
        }
        __syncthreads();
#pragma unroll
        for (int kk = 0; kk < 16; kk++) {
            float4 a4 = *reinterpret_cast<const float4*>(&As[kk][ty * 4]);
            float4 b4 = *reinterpret_cast<const float4*>(&Bs[kk][tx * 4]);
            float a[4] = {a4.x, a4.y, a4.z, a4.w};
            float bv[4] = {b4.x, b4.y, b4.z, b4.w};
#pragma unroll
            for (int i = 0; i < 4; i++)
#pragma unroll
                for (int j = 0; j < 4; j++)
                    acc[i][j] = fmaf(a[i], bv[j], acc[i][j]);
        }
        __syncthreads();
    }
#pragma unroll
    for (int i = 0; i < 4; i++) {
        int m = m0 + ty * 4 + i;
#pragma unroll
        for (int j = 0; j < 4; j++) {
            int n = n0 + tx * 4 + j;
            if (n < N) C[(size_t)m * N + n] = acc[i][j] + bias[n];
        }
    }
}

// ---------------- host orchestration ----------------
extern "C" void kernel_launch(void* const* d_in, const int* in_sizes, int n_in,
                              void* d_out, int out_size) {
    const int*   ids          = (const int*)d_in[0];
    const int*   mul          = (const int*)d_in[1];
    const float* tok_emb      = (const float*)d_in[2];
    const float* state_emb    = (const float*)d_in[3];
    const float* state_proj_w = (const float*)d_in[4];
    const float* state_proj_b = (const float*)d_in[5];
    const float* wpe          = (const float*)d_in[6];
    const float* ln1_g        = (const float*)d_in[7];
    const float* ln1_b        = (const float*)d_in[8];
    const float* attn_w       = (const float*)d_in[9];
    const float* attn_b       = (const float*)d_in[10];
    const float* attn_proj_w  = (const float*)d_in[11];
    const float* attn_proj_b  = (const float*)d_in[12];
    const float* ln2_g        = (const float*)d_in[13];
    const float* ln2_b        = (const float*)d_in[14];
    const float* fc_w         = (const float*)d_in[15];
    const float* fc_b         = (const float*)d_in[16];
    const float* mlp_proj_w   = (const float*)d_in[17];
    const float* mlp_proj_b   = (const float*)d_in[18];
    const float* lnf_g        = (const float*)d_in[19];
    const float* lnf_b        = (const float*)d_in[20];
    const float* head_w       = (const float*)d_in[21];
    const float* head_b       = (const float*)d_in[22];
    float* out = (float*)d_out;

    float *h, *lnbuf;
    __half *wh, *lnh, *lnl, *atth, *attl, *midh, *midl, *qkh, *qkl, *vth, *vtl;
    cudaGetSymbolAddress((void**)&h,     g_h);
    cudaGetSymbolAddress((void**)&lnbuf, g_ln);
    cudaGetSymbolAddress((void**)&wh,    g_wh);
    cudaGetSymbolAddress((void**)&lnh,   g_lnh);
    cudaGetSymbolAddress((void**)&lnl,   g_lnl);
    cudaGetSymbolAddress((void**)&atth,  g_atth);
    cudaGetSymbolAddress((void**)&attl,  g_attl);
    cudaGetSymbolAddress((void**)&midh,  g_midh);
    cudaGetSymbolAddress((void**)&midl,  g_midl);
    cudaGetSymbolAddress((void**)&qkh,   g_qkh);
    cudaGetSymbolAddress((void**)&qkl,   g_qkl);
    cudaGetSymbolAddress((void**)&vth,   g_vth);
    cudaGetSymbolAddress((void**)&vtl,   g_vtl);

    cudaFuncSetAttribute(mma_gemm<1>, cudaFuncAttributeMaxDynamicSharedMemorySize, GEMM_SMEM);
    cudaFuncSetAttribute(mma_gemm<2>, cudaFuncAttributeMaxDynamicSharedMemorySize, GEMM_SMEM);
    cudaFuncSetAttribute(mma_gemm<3>, cudaFuncAttributeMaxDynamicSharedMemorySize, GEMM_SMEM);
    cudaFuncSetAttribute(flash_tc_kernel, cudaFuncAttributeMaxDynamicSharedMemorySize, FT_SMEM);

    wconv_kernel<<<dim3(QKVN/32, EMB/32, NLAYER), 256>>>(attn_w, wh + OFF_QKV, EMB, QKVN);
    wconv_kernel<<<dim3(EMB/32, EMB/32, NLAYER), 256>>>(attn_proj_w, wh + OFF_PROJ, EMB, EMB);
    wconv_kernel<<<dim3(FFN/32, EMB/32, NLAYER), 256>>>(fc_w, wh + OFF_FC, EMB, FFN);
    wconv_kernel<<<dim3(EMB/32, FFN/32, NLAYER), 256>>>(mlp_proj_w, wh + OFF_MLP, FFN, EMB);

    state_scan_kernel<<<1, 256>>>(ids, mul);
    state_proj_kernel<<<(VOC * EMB + 255) / 256, 256>>>(state_emb, state_proj_w, state_proj_b);
    embed_kernel<<<(BT * EMB + 255) / 256, 256>>>(ids, tok_emb, wpe);

    for (int l = 0; l < NLAYER; l++) {
        ln_f16_kernel<<<BT, 256>>>(h, ln1_g + l * EMB, ln1_b + l * EMB, lnh, lnl);
        mma_gemm<3><<<dim3(QKVN/64, BT/128), 256, GEMM_SMEM>>>(
            lnh, lnl, wh + OFF_QKV + (size_t)l * W_QKV,
            attn_b + l * QKVN, nullptr, nullptr, qkh, qkl, vth, vtl, EMB, QKVN);
        flash_tc_kernel<<<dim3(SEQ/128, BATCH * NH), 256, FT_SMEM>>>();
        mma_gemm<1><<<dim3(EMB/64, BT/128), 256, GEMM_SMEM>>>(
            atth, attl, wh + OFF_PROJ + (size_t)l * W_PROJ,
            attn_proj_b + l * EMB, h, h, nullptr, nullptr, nullptr, nullptr, EMB, EMB);
        ln_f16_kernel<<<BT, 256>>>(h, ln2_g + l * EMB, ln2_b + l * EMB, lnh, lnl);
        mma_gemm<2><<<dim3(FFN/64, BT/128), 256, GEMM_SMEM>>>(
            lnh, lnl, wh + OFF_FC + (size_t)l * W_FC,
            fc_b + l * FFN, nullptr, nullptr, midh, midl, nullptr, nullptr, EMB, FFN);
        mma_gemm<1><<<dim3(EMB/64, BT/128), 256, GEMM_SMEM>>>(
            midh, midl, wh + OFF_MLP + (size_t)l * W_MLP,
            mlp_proj_b + l * EMB, h, h, nullptr, nullptr, nullptr, nullptr, FFN, EMB);
    }

    ln_kernel<<<BT, 256>>>(h, lnf_g, lnf_b, lnbuf);
    head_gemm_kernel<<<dim3(1, BT / 64), 256>>>(lnbuf, head_w, head_b, out, VOC, EMB);
}

// round 14
// speedup vs baseline: 1.2007x; 1.0011x over previous
#include <cuda_runtime.h>
#include <cuda_fp16.h>
#include <math.h>
#include <stdint.h>

#define BATCH 8
#define SEQ 512
#define BT (BATCH*SEQ)        // 4096
#define EMB 768
#define NH 12
#define DH 64
#define VOC 60
#define DST 128
#define NLAYER 12
#define QKVN (3*EMB)          // 2304
#define FFN (4*EMB)           // 3072

#define W_QKV (QKVN*EMB)
#define W_PROJ (EMB*EMB)
#define W_FC (FFN*EMB)
#define W_MLP (EMB*FFN)
#define OFF_QKV 0
#define OFF_PROJ (12*W_QKV)
#define OFF_FC (OFF_PROJ + 12*W_PROJ)
#define OFF_MLP (OFF_FC + 12*W_FC)
#define W_TOTAL (OFF_MLP + 12*W_MLP)

// ---------------- scratch ----------------
__device__ float g_h[BT*EMB];
__device__ float g_ln[BT*EMB];
__device__ float g_semb[VOC*EMB];
__device__ int   g_pre[BT];

__device__ __half g_wh[W_TOTAL];                 // weights, single fp16, [N][K]
__device__ __half g_lnh[BT*EMB],  g_lnl[BT*EMB]; // activations, fp16 hi/lo
__device__ __half g_atth[BT*EMB], g_attl[BT*EMB];
__device__ __half g_midh[BT*FFN], g_midl[BT*FFN];
__device__ __half g_qkh[2*BT*EMB], g_qkl[2*BT*EMB];   // Q then K, row-major
__device__ __half g_vth[BATCH*NH*DH*SEQ], g_vtl[BATCH*NH*DH*SEQ]; // V^T [bh][d][s]

// ---------------- helpers ----------------
__device__ __forceinline__ uint32_t smem_u32(const void* p) {
    uint32_t a;
    asm("{ .reg .u64 t; cvta.to.shared.u64 t, %1; cvt.u32.u64 %0, t; }" : "=r"(a) : "l"(p));
    return a;
}

__device__ __forceinline__ void ldsm_x4(uint32_t* r, uint32_t addr) {
    asm volatile("ldmatrix.sync.aligned.m8n8.x4.shared.b16 {%0,%1,%2,%3}, [%4];"
        : "=r"(r[0]), "=r"(r[1]), "=r"(r[2]), "=r"(r[3]) : "r"(addr));
}

__device__ __forceinline__ void mma_f16(float* c, const uint32_t* a, const uint32_t* b) {
    asm volatile("mma.sync.aligned.m16n8k16.row.col.f32.f16.f16.f32 "
        "{%0,%1,%2,%3}, {%4,%5,%6,%7}, {%8,%9}, {%0,%1,%2,%3};"
        : "+f"(c[0]), "+f"(c[1]), "+f"(c[2]), "+f"(c[3])
        : "r"(a[0]), "r"(a[1]), "r"(a[2]), "r"(a[3]), "r"(b[0]), "r"(b[1]));
}

__device__ __forceinline__ void cp16(uint32_t dst, const void* src) {
    asm volatile("cp.async.cg.shared.global [%0], [%1], 16;" :: "r"(dst), "l"(src));
}
#define CP_COMMIT() asm volatile("cp.async.commit_group;" ::: "memory")
#define CP_WAIT(n)  asm volatile("cp.async.wait_group %0;" :: "n"(n) : "memory")

__device__ __forceinline__ void cvt_split2h(float x0, float x1, uint32_t& hi, uint32_t& lo) {
    __half h0 = __float2half_rn(x0);
    __half h1 = __float2half_rn(x1);
    __half l0 = __float2half_rn(x0 - __half2float(h0));
    __half l1 = __float2half_rn(x1 - __half2float(h1));
    __half2 H(h0, h1), L(l0, l1);
    hi = *(uint32_t*)&H;
    lo = *(uint32_t*)&L;
}

// ---------------- reductions ----------------
__device__ __forceinline__ float breduce_sum(float v, float* sh, int nthr) {
#pragma unroll
    for (int o = 16; o > 0; o >>= 1) v += __shfl_xor_sync(0xffffffffu, v, o);
    int lane = threadIdx.x & 31, w = threadIdx.x >> 5;
    if (lane == 0) sh[w] = v;
    __syncthreads();
    float r = 0.f;
    if ((int)threadIdx.x < (nthr >> 5)) r = sh[threadIdx.x];
    if (threadIdx.x < 32) {
#pragma unroll
        for (int o = 16; o > 0; o >>= 1) r += __shfl_xor_sync(0xffffffffu, r, o);
        if (threadIdx.x == 0) sh[0] = r;
    }
    __syncthreads();
    r = sh[0];
    __syncthreads();
    return r;
}

// ---------------- automaton state scan ----------------
__global__ void state_scan_kernel(const int* __restrict__ ids, const int* __restrict__ mul) {
    __shared__ int smul[VOC*VOC];
    __shared__ int sids[BT];
    int tid = threadIdx.x;
    for (int i = tid; i < VOC*VOC; i += blockDim.x) smul[i] = mul[i];
    for (int i = tid; i < BT; i += blockDim.x) sids[i] = ids[i];
    __syncthreads();
    if (tid < BATCH) {
        int s = 0;
        const int* row = sids + tid * SEQ;
        int* pre = g_pre + tid * SEQ;
        for (int t = 0; t < SEQ; t++) {
            pre[t] = s;
            s = smul[row[t] * VOC + s];
        }
    }
}

__global__ void state_proj_kernel(const float* __restrict__ semb,
                                  const float* __restrict__ W,
                                  const float* __restrict__ b) {
    int idx = blockIdx.x * blockDim.x + threadIdx.x;
    if (idx >= VOC * EMB) return;
    int v = idx / EMB, e = idx % EMB;
    float acc = b[e];
#pragma unroll 8
    for (int d = 0; d < DST; d++) acc += semb[v * DST + d] * W[d * EMB + e];
    g_semb[idx] = acc;
}

__global__ void embed_kernel(const int* __restrict__ ids,
                             const float* __restrict__ tok_emb,
                             const float* __restrict__ wpe) {
    int idx = blockIdx.x * blockDim.x + threadIdx.x;
    if (idx >= BT * EMB) return;
    int bt = idx / EMB, e = idx % EMB;
    int t = bt % SEQ;
    g_h[idx] = tok_emb[ids[bt] * EMB + e] + g_semb[g_pre[bt] * EMB + e] + wpe[t * EMB + e];
}

// ---------------- weight convert: W[K][N] fp32 -> fp16 [N][K] --------------
__global__ __launch_bounds__(256) void wconv_kernel(
    const float* __restrict__ W, __half* __restrict__ Hi, int K, int N)
{
    __shared__ float t[32][33];
    int l = blockIdx.z;
    const float* Wl = W + (size_t)l * K * N;
    __half* Hl = Hi + (size_t)l * K * N;
    int n0 = blockIdx.x * 32, k0 = blockIdx.y * 32;
    int tx = threadIdx.x & 31, ty = threadIdx.x >> 5;
#pragma unroll
    for (int j = 0; j < 4; j++)
        t[ty + 8 * j][tx] = Wl[(size_t)(k0 + ty + 8 * j) * N + n0 + tx];
    __syncthreads();
#pragma unroll
    for (int j = 0; j < 4; j++) {
        float v = t[tx][ty + 8 * j];
        Hl[(size_t)(n0 + ty + 8 * j) * K + k0 + tx] = __float2half_rn(v);
    }
}

// ---------------- layernorm variants ----------------
__global__ __launch_bounds__(256) void ln_kernel(const float* __restrict__ x,
                                                 const float* __restrict__ g,
                                                 const float* __restrict__ b,
                                                 float* __restrict__ y) {
    __shared__ float sh[8];
    int row = blockIdx.x, tid = threadIdx.x;
    const float* xr = x + (size_t)row * EMB;
    float v0 = xr[tid], v1 = xr[tid + 256], v2 = xr[tid + 512];
    float mean = breduce_sum(v0 + v1 + v2, sh, 256) * (1.f / EMB);
    float d0 = v0 - mean, d1 = v1 - mean, d2 = v2 - mean;
    float var = breduce_sum(d0*d0 + d1*d1 + d2*d2, sh, 256) * (1.f / EMB);
    float rstd = rsqrtf(var + 1e-5f);
    float* yr = y + (size_t)row * EMB;
    yr[tid]       = d0 * rstd * g[tid]       + b[tid];
    yr[tid + 256] = d1 * rstd * g[tid + 256] + b[tid + 256];
    yr[tid + 512] = d2 * rstd * g[tid + 512] + b[tid + 512];
}

__global__ __launch_bounds__(256) void ln_f16_kernel(const float* __restrict__ x,
                                                     const float* __restrict__ g,
                                                     const float* __restrict__ b,
                                                     __half* __restrict__ yh,
                                                     __half* __restrict__ yl) {
    __shared__ float sh[8];
    int row = blockIdx.x, tid = threadIdx.x;
    const float* xr = x + (size_t)row * EMB;
    float v0 = xr[tid], v1 = xr[tid + 256], v2 = xr[tid + 512];
    float mean = breduce_sum(v0 + v1 + v2, sh, 256) * (1.f / EMB);
    float d0 = v0 - mean, d1 = v1 - mean, d2 = v2 - mean;
    float var = breduce_sum(d0*d0 + d1*d1 + d2*d2, sh, 256) * (1.f / EMB);
    float rstd = rsqrtf(var + 1e-5f);
    size_t base = (size_t)row * EMB;
#pragma unroll
    for (int q = 0; q < 3; q++) {
        int e = tid + q * 256;
        float d = (q == 0) ? d0 : (q == 1) ? d1 : d2;
        float v = d * rstd * g[e] + b[e];
        __half h = __float2half_rn(v);
        yh[base + e] = h;
        yl[base + e] = __float2half_rn(v - __half2float(h));
    }
}

// ================= mma.sync fp16 2-term GEMM (3-deep ring, R12 proven) =====
__device__ __forceinline__ float gelu_f(float x) {
    return 0.5f * x * (1.f + tanhf(0.7978845608028654f * (x + 0.044715f * x * x * x)));
}

#define ROWB 80
#define SM_AH 0
#define SM_AL 10240
#define SM_BH 20480
#define BUFSZ 25600
#define GEMM_SMEM (3*BUFSZ)   // 76800/CTA

template<int EPI>
__global__ __launch_bounds__(256, 2) void mma_gemm(
    const __half* __restrict__ Ah, const __half* __restrict__ Al,
    const __half* __restrict__ Bh,
    const float* __restrict__ bias,
    const float* __restrict__ Res,
    float* __restrict__ C,
    __half* __restrict__ Ch, __half* __restrict__ Cl,
    __half* __restrict__ Vh, __half* __restrict__ Vl,
    int K, int N)
{
    extern __shared__ __align__(16) char sm[];
    uint32_t sb = smem_u32(sm);
    int tid = threadIdx.x;
    int wid = tid >> 5, lane = tid & 31;
    int wm = wid & 3, wn = wid >> 2;
    int m0 = blockIdx.y * 128, n0 = blockIdx.x * 64;

    int p_row = tid >> 2;
    int p_seg = tid & 3;

    int a_row = lane & 15;
    int a_colb = ((lane >> 4) * 8) * 2;
    int b_row = (lane & 7) + ((lane >> 4) & 1) * 8;
    int b_colb = (((lane >> 3) & 1) * 8) * 2;

    float acc[2][4][4];
#pragma unroll
    for (int i = 0; i < 2; i++)
#pragma unroll
        for (int j = 0; j < 4; j++)
#pragma unroll
            for (int q = 0; q < 4; q++) acc[i][j][q] = 0.f;

    const int nch = K >> 5;

    auto issue = [&](int c, int bufsel) {
        int k0 = c << 5;
        uint32_t base = sb + bufsel * BUFSZ;
        uint32_t doff = (uint32_t)(p_row * ROWB + p_seg * 16);
#pragma unroll
        for (int i = 0; i < 2; i++) {
            int row = p_row + i * 64;
            size_t aoff = (size_t)(m0 + row) * K + k0 + p_seg * 8;
            cp16(base + SM_AH + doff + i * (64 * ROWB), Ah + aoff);
            cp16(base + SM_AL + doff + i * (64 * ROWB), Al + aoff);
        }
        size_t boff = (size_t)(n0 + p_row) * K + k0 + p_seg * 8;
        cp16(base + SM_BH + doff, Bh + boff);
    };

    issue(0, 0);
    CP_COMMIT();

    int curb = 0, nxtb = 1;
    for (int c = 0; c < nch; c++) {
        if (c + 1 < nch) {
            issue(c + 1, nxtb);
            CP_COMMIT();
            CP_WAIT(1);
        } else {
            CP_WAIT(0);
        }
        __syncthreads();

        uint32_t base = sb + curb * BUFSZ;
#pragma unroll
        for (int ks = 0; ks < 2; ks++) {
            uint32_t a_hi[2][4], a_lo[2][4];
#pragma unroll
            for (int mt = 0; mt < 2; mt++) {
                uint32_t off = (uint32_t)((wm * 32 + mt * 16 + a_row) * ROWB
                                          + ks * 32 + a_colb);
                ldsm_x4(a_hi[mt], base + SM_AH + off);
                ldsm_x4(a_lo[mt], base + SM_AL + off);
            }
            uint32_t b_hi[2][4];
#pragma unroll
            for (int p = 0; p < 2; p++) {
                uint32_t off = (uint32_t)((wn * 32 + p * 16 + b_row) * ROWB
                                          + ks * 32 + b_colb);
                ldsm_x4(b_hi[p], base + SM_BH + off);
            }
#pragma unroll
            for (int mt = 0; mt < 2; mt++)
#pragma unroll
                for (int p = 0; p < 2; p++) {
                    mma_f16(acc[mt][2*p],   a_hi[mt], &b_hi[p][0]);
                    mma_f16(acc[mt][2*p+1], a_hi[mt], &b_hi[p][2]);
                }
#pragma unroll
            for (int mt = 0; mt < 2; mt++)
#pragma unroll
                for (int p = 0; p < 2; p++) {
                    mma_f16(acc[mt][2*p],   a_lo[mt], &b_hi[p][0]);
                    mma_f16(acc[mt][2*p+1], a_lo[mt], &b_hi[p][2]);
                }
        }
        curb = nxtb;
        nxtb = (nxtb == 2) ? 0 : nxtb + 1;
    }

    int r0 = m0 + wm * 32 + (lane >> 2);
    int c0 = n0 + wn * 32 + (lane & 3) * 2;
#pragma unroll
    for (int mt = 0; mt < 2; mt++) {
#pragma unroll
        for (int nt = 0; nt < 4; nt++) {
            int r = r0 + mt * 16;
            int cc = c0 + nt * 8;
            float b0 = bias[cc], b1 = bias[cc + 1];
            float v0 = acc[mt][nt][0] + b0;
            float v1 = acc[mt][nt][1] + b1;
            float v2 = acc[mt][nt][2] + b0;
            float v3 = acc[mt][nt][3] + b1;
            if (EPI == 2) {
                v0 = gelu_f(v0); v1 = gelu_f(v1);
                v2 = gelu_f(v2); v3 = gelu_f(v3);
                uint32_t h01, l01, h23, l23;
                cvt_split2h(v0, v1, h01, l01);
                cvt_split2h(v2, v3, h23, l23);
                *(uint32_t*)(Ch + (size_t)r * N + cc) = h01;
                *(uint32_t*)(Cl + (size_t)r * N + cc) = l01;
                *(uint32_t*)(Ch + (size_t)(r + 8) * N + cc) = h23;
                *(uint32_t*)(Cl + (size_t)(r + 8) * N + cc) = l23;
            } else if (EPI == 3) {
                if (cc < 1536) {
                    int kk = (cc >= 768);
                    size_t idx = (size_t)kk * (BT * EMB)
                               + (size_t)r * EMB + (cc - kk * 768);
                    uint32_t h01, l01, h23, l23;
                    cvt_split2h(v0, v1, h01, l01);
                    cvt_split2h(v2, v3, h23, l23);
                    *(uint32_t*)(Ch + idx) = h01;
                    *(uint32_t*)(Cl + idx) = l01;
                    *(uint32_t*)(Ch + idx + (size_t)8 * EMB) = h23;
                    *(uint32_t*)(Cl + idx + (size_t)8 * EMB) = l23;
                } else {
                    int b = r >> 9, s = r & 511;
                    int hd = cc - 1536;
                    int hh_ = hd >> 6, d = hd & 63;
                    size_t idx = ((size_t)(b * NH + hh_) * 64 + d) * 512 + s;
                    __half a0 = __float2half_rn(v0);
                    Vh[idx] = a0;
                    Vl[idx] = __float2half_rn(v0 - __half2float(a0));
                    __half a1 = __float2half_rn(v1);
                    Vh[idx + 512] = a1;
                    Vl[idx + 512] = __float2half_rn(v1 - __half2float(a1));
                    __half a2 = __float2half_rn(v2);
                    Vh[idx + 8] = a2;
                    Vl[idx + 8] = __float2half_rn(v2 - __half2float(a2));
                    __half a3 = __float2half_rn(v3);
                    Vh[idx + 512 + 8] = a3;
                    Vl[idx + 512 + 8] = __float2half_rn(v3 - __half2float(a3));
                }
            } else {
                if (EPI == 1) {
                    const float* rp0 = Res + (size_t)r * N + cc;
                    const float* rp1 = Res + (size_t)(r + 8) * N + cc;
                    v0 += rp0[0]; v1 += rp0[1];
                    v2 += rp1[0]; v3 += rp1[1];
                }
                *reinterpret_cast<float2*>(C + (size_t)r * N + cc) = make_float2(v0, v1);
                *reinterpret_cast<float2*>(C + (size_t)(r + 8) * N + cc) = make_float2(v2, v3);
            }
        }
    }
}

// ================= tensor-core causal flash attention ======================
// fp16 hi/lo QKV from global; KV tiles DOUBLE-BUFFERED (prefetch j+1 during j).
#define FROWB 144
#define FT_QH 0
#define FT_QL (128*FROWB)            // 18432
#define FT_KV0 (2*128*FROWB)         // 36864
#define KV_KH 0
#define KV_KL (64*FROWB)             // 9216
#define KV_VH (2*64*FROWB)           // 18432
#define KV_VL (3*64*FROWB)           // 27648
#define KVBUF (4*64*FROWB)           // 36864
#define FT_SMEM (FT_KV0 + 2*KVBUF)   // 110592

__global__ __launch_bounds__(256, 2) void flash_tc_kernel() {
    extern __shared__ __align__(16) char fsm[];
    uint32_t sb = smem_u32(fsm);
    int bh = blockIdx.y;
    int b = bh / NH, h = bh % NH;
    int t0 = blockIdx.x * 128;
    int tid = threadIdx.x;
    int wid = tid >> 5, lane = tid & 31;

    const __half* Kh = g_qkh + (size_t)BT * EMB;
    const __half* Kl = g_qkl + (size_t)BT * EMB;

    int a_row = lane & 15;
    int a_colb = ((lane >> 4) * 8) * 2;
    int b_row = (lane & 7) + ((lane >> 4) & 1) * 8;
    int b_colb = (((lane >> 3) & 1) * 8) * 2;

    // KV tile loader into buffer `buf`
    auto kv_issue = [&](int j, int buf) {
        int s = tid >> 2, seg = tid & 3;
        uint32_t base = sb + FT_KV0 + buf * KVBUF;
        size_t koff = (size_t)(b * SEQ + j * 64 + s) * EMB + h * DH + seg * 16;
        uint32_t kdh = base + KV_KH + s * FROWB + seg * 32;
        uint32_t kdl = base + KV_KL + s * FROWB + seg * 32;
        cp16(kdh,      Kh + koff);
        cp16(kdh + 16, Kh + koff + 8);
        cp16(kdl,      Kl + koff);
        cp16(kdl + 16, Kl + koff + 8);
        size_t voff = ((size_t)bh * 64 + s) * 512 + j * 64 + seg * 16;
        uint32_t vdh = base + KV_VH + s * FROWB + seg * 32;
        uint32_t vdl = base + KV_VL + s * FROWB + seg * 32;
        cp16(vdh,      g_vth + voff);
        cp16(vdh + 16, g_vth + voff + 8);
        cp16(vdl,      g_vtl + voff);
        cp16(vdl + 16, g_vtl + voff + 8);
    };

    // stage Q + KV tile 0
    {
        int row = tid >> 1, hf = tid & 1;
        size_t qoff = (size_t)(b * SEQ + t0 + row) * EMB + h * DH + hf * 32;
        uint32_t dh_ = sb + FT_QH + row * FROWB + hf * 64;
        uint32_t dl_ = sb + FT_QL + row * FROWB + hf * 64;
#pragma unroll
        for (int i = 0; i < 4; i++) {
            cp16(dh_ + 16 * i, g_qkh + qoff + 8 * i);
            cp16(dl_ + 16 * i, g_qkl + qoff + 8 * i);
        }
    }
    kv_issue(0, 0);
    CP_COMMIT();
    CP_WAIT(0);
    __syncthreads();

    float m0 = -1e30f, m1 = -1e30f, l0 = 0.f, l1 = 0.f;
    float O[8][4];
#pragma unroll
    for (int f = 0; f < 8; f++)
#pragma unroll
        for (int q = 0; q < 4; q++) O[f][q] = 0.f;

    int t_r0 = t0 + wid * 16 + (lane >> 2);
    int ntile = (t0 >> 6) + 2;

    for (int j = 0; j < ntile; j++) {
        int cur = j & 1;
        if (j + 1 < ntile) {
            kv_issue(j + 1, cur ^ 1);   // prefetch while computing tile j
            CP_COMMIT();
        }
        uint32_t kvb = sb + FT_KV0 + cur * KVBUF;

        float S[8][4];
#pragma unroll
        for (int f = 0; f < 8; f++)
#pragma unroll
            for (int q = 0; q < 4; q++) S[f][q] = 0.f;
#pragma unroll
        for (int ks = 0; ks < 4; ks++) {
            uint32_t aq_h[4], aq_l[4];
            uint32_t aoff = (uint32_t)((wid * 16 + a_row) * FROWB + ks * 32 + a_colb);
            ldsm_x4(aq_h, sb + FT_QH + aoff);
            ldsm_x4(aq_l, sb + FT_QL + aoff);
#pragma unroll
            for (int p = 0; p < 4; p++) {
                uint32_t bk_h[4], bk_l[4];
                uint32_t boff = (uint32_t)((p * 16 + b_row) * FROWB + ks * 32 + b_colb);
                ldsm_x4(bk_h, kvb + KV_KH + boff);
                ldsm_x4(bk_l, kvb + KV_KL + boff);
                mma_f16(S[2*p],   aq_h, &bk_h[0]);
                mma_f16(S[2*p+1], aq_h, &bk_h[2]);
                mma_f16(S[2*p],   aq_l, &bk_h[0]);
                mma_f16(S[2*p+1], aq_l, &bk_h[2]);
                mma_f16(S[2*p],   aq_h, &bk_l[0]);
                mma_f16(S[2*p+1], aq_h, &bk_l[2]);
            }
        }

#pragma unroll
        for (int f = 0; f < 8; f++) {
            int c = j * 64 + (f >> 1) * 16 + (f & 1) * 8 + (lane & 3) * 2;
#pragma unroll
            for (int q = 0; q < 4; q++) S[f][q] *= 0.125f;
            if (c     > t_r0) S[f][0] = -1e30f;
            if (c + 1 > t_r0) S[f][1] = -1e30f;
            if (c     > t_r0 + 8) S[f][2] = -1e30f;
            if (c + 1 > t_r0 + 8) S[f][3] = -1e30f;
        }

        float mx0 = -1e30f, mx1 = -1e30f;
#pragma unroll
        for (int f = 0; f < 8; f++) {
            mx0 = fmaxf(mx0, fmaxf(S[f][0], S[f][1]));
            mx1 = fmaxf(mx1, fmaxf(S[f][2], S[f][3]));
        }
        mx0 = fmaxf(mx0, __shfl_xor_sync(0xffffffffu, mx0, 1));
        mx0 = fmaxf(mx0, __shfl_xor_sync(0xffffffffu, mx0, 2));
        mx1 = fmaxf(mx1, __shfl_xor_sync(0xffffffffu, mx1, 1));
        mx1 = fmaxf(mx1, __shfl_xor_sync(0xffffffffu, mx1, 2));
        float mn0 = fmaxf(m0, mx0), mn1 = fmaxf(m1, mx1);
        float c0 = __expf(m0 - mn0), c1 = __expf(m1 - mn1);
        m0 = mn0; m1 = mn1;
        float rs0 = 0.f, rs1 = 0.f;
#pragma unroll
        for (int f = 0; f < 8; f++) {
            S[f][0] = __expf(S[f][0] - mn0);
            S[f][1] = __expf(S[f][1] - mn0);
            S[f][2] = __expf(S[f][2] - mn1);
            S[f][3] = __expf(S[f][3] - mn1);
            rs0 += S[f][0] + S[f][1];
            rs1 += S[f][2] + S[f][3];
        }
        rs0 += __shfl_xor_sync(0xffffffffu, rs0, 1);
        rs0 += __shfl_xor_sync(0xffffffffu, rs0, 2);
        rs1 += __shfl_xor_sync(0xffffffffu, rs1, 1);
        rs1 += __shfl_xor_sync(0xffffffffu, rs1, 2);
        l0 = l0 * c0 + rs0;
        l1 = l1 * c1 + rs1;
#pragma unroll
        for (int f = 0; f < 8; f++) {
            O[f][0] *= c0; O[f][1] *= c0;
            O[f][2] *= c1; O[f][3] *= c1;
        }

#pragma unroll
        for (int g = 0; g < 4; g++) {
            uint32_t pa[4];
            __half2 p0 = __floats2half2_rn(S[2*g][0],   S[2*g][1]);
            __half2 p1 = __floats2half2_rn(S[2*g][2],   S[2*g][3]);
            __half2 p2 = __floats2half2_rn(S[2*g+1][0], S[2*g+1][1]);
            __half2 p3 = __floats2half2_rn(S[2*g+1][2], S[2*g+1][3]);
            pa[0] = *(uint32_t*)&p0;
            pa[1] = *(uint32_t*)&p1;
            pa[2] = *(uint32_t*)&p2;
            pa[3] = *(uint32_t*)&p3;
#pragma unroll
            for (int p = 0; p < 4; p++) {
                uint32_t bv_h[4], bv_l[4];
                uint32_t boff = (uint32_t)((p * 16 + b_row) * FROWB + g * 32 + b_colb);
                ldsm_x4(bv_h, kvb + KV_VH + boff);
                ldsm_x4(bv_l, kvb + KV_VL + boff);
                mma_f16(O[2*p],   pa, &bv_h[0]);
                mma_f16(O[2*p+1], pa, &bv_h[2]);
                mma_f16(O[2*p],   pa, &bv_l[0]);
                mma_f16(O[2*p+1], pa, &bv_l[2]);
            }
        }

        if (j + 1 < ntile) {
            CP_WAIT(0);      // prefetched tile landed
        }
        __syncthreads();     // all warps done reading buf `cur`; prefetch visible
    }

    float inv0 = 1.f / l0, inv1 = 1.f / l1;
#pragma unroll
    for (int f = 0; f < 8; f++) {
        int d = (f >> 1) * 16 + (f & 1) * 8 + (lane & 3) * 2;
        size_t base0 = (size_t)(b * SEQ + t_r0) * EMB + h * DH + d;
        size_t base1 = (size_t)(b * SEQ + t_r0 + 8) * EMB + h * DH + d;
        uint32_t hh, ll;
        cvt_split2h(O[f][0] * inv0, O[f][1] * inv0, hh, ll);
        *(uint32_t*)(g_atth + base0) = hh;
        *(uint32_t*)(g_attl + base0) = ll;
        cvt_split2h(O[f][2] * inv1, O[f][3] * inv1, hh, ll);
        *(uint32_t*)(g_atth + base1) = hh;
        *(uint32_t*)(g_attl + base1) = ll;
    }
}

// ---------------- head GEMM (N=60, FFMA) ----------------
__global__ __launch_bounds__(256) void head_gemm_kernel(
    const float* __restrict__ A,
    const float* __restrict__ Bm,
    const float* __restrict__ bias,
    float* __restrict__ C,
    int N, int K)
{
    __shared__ float As[16][68];
    __shared__ float Bs[16][64];
    int m0 = blockIdx.y * 64, n0 = blockIdx.x * 64;
    int tid = threadIdx.x;
    int tx = tid & 15, ty = tid >> 4;
    float acc[4][4] = {};
    for (int k0 = 0; k0 < K; k0 += 16) {
#pragma unroll
        for (int i = 0; i < 4; i++) {
            int lin = tid + i * 256;
            int r = lin >> 4, c = lin & 15;
            As[c][r] = A[(size_t)(m0 + r) * K + k0 + c];
        }
#pragma unroll
        for (int i = 0; i < 4; i++) {
            int lin = tid + i * 256;
            int r = lin >> 6, c = lin & 63;
            int n = n0 + c;
            Bs[r][c] = (n < N) ? Bm[(size_t)(k0 + r) * N + n] : 0.f;
        }
        __syncthreads();
#pragma unroll
        for (int kk = 0; kk < 16; kk++) {
            float4 a4 = *reinterpret_cast<const float4*>(&As[kk][ty * 4]);
            float4 b4 = *reinterpret_cast<const float4*>(&Bs[kk][tx * 4]);
            float a[4] = {a4.x, a4.y, a4.z, a4.w};
            float bv[4] = {b4.x, b4.y, b4.z, b4.w};
#pragma unroll
            for (int i = 0; i < 4; i++)
#pragma unroll
                for (int j = 0; j < 4; j++)
                    acc[i][j] = fmaf(a[i], bv[j], acc[i][j]);
        }
        __syncthreads();
    }
#pragma unroll
    for (int i = 0; i < 4; i++) {
        int m = m0 + ty * 4 + i;
#pragma unroll
        for (int j = 0; j < 4; j++) {
            int n = n0 + tx * 4 + j;
            if (n < N) C[(size_t)m * N + n] = acc[i][j] + bias[n];
        }
    }
}

// ---------------- host orchestration ----------------
extern "C" void kernel_launch(void* const* d_in, const int* in_sizes, int n_in,
                              void* d_out, int out_size) {
    const int*   ids          = (const int*)d_in[0];
    const int*   mul          = (const int*)d_in[1];
    const float* tok_emb      = (const float*)d_in[2];
    const float* state_emb    = (const float*)d_in[3];
    const float* state_proj_w = (const float*)d_in[4];
    const float* state_proj_b = (const float*)d_in[5];
    const float* wpe          = (const float*)d_in[6];
    const float* ln1_g        = (const float*)d_in[7];
    const float* ln1_b        = (const float*)d_in[8];
    const float* attn_w       = (const float*)d_in[9];
    const float* attn_b       = (const float*)d_in[10];
    const float* attn_proj_w  = (const float*)d_in[11];
    const float* attn_proj_b  = (const float*)d_in[12];
    const float* ln2_g        = (const float*)d_in[13];
    const float* ln2_b        = (const float*)d_in[14];
    const float* fc_w         = (const float*)d_in[15];
    const float* fc_b         = (const float*)d_in[16];
    const float* mlp_proj_w   = (const float*)d_in[17];
    const float* mlp_proj_b   = (const float*)d_in[18];
    const float* lnf_g        = (const float*)d_in[19];
    const float* lnf_b        = (const float*)d_in[20];
    const float* head_w       = (const float*)d_in[21];
    const float* head_b       = (const float*)d_in[22];
    float* out = (float*)d_out;

    float *h, *lnbuf;
    __half *wh, *lnh, *lnl, *atth, *attl, *midh, *midl, *qkh, *qkl, *vth, *vtl;
    cudaGetSymbolAddress((void**)&h,     g_h);
    cudaGetSymbolAddress((void**)&lnbuf, g_ln);
    cudaGetSymbolAddress((void**)&wh,    g_wh);
    cudaGetSymbolAddress((void**)&lnh,   g_lnh);
    cudaGetSymbolAddress((void**)&lnl,   g_lnl);
    cudaGetSymbolAddress((void**)&atth,  g_atth);
    cudaGetSymbolAddress((void**)&attl,  g_attl);
    cudaGetSymbolAddress((void**)&midh,  g_midh);
    cudaGetSymbolAddress((void**)&midl,  g_midl);
    cudaGetSymbolAddress((void**)&qkh,   g_qkh);
    cudaGetSymbolAddress((void**)&qkl,   g_qkl);
    cudaGetSymbolAddress((void**)&vth,   g_vth);
    cudaGetSymbolAddress((void**)&vtl,   g_vtl);

    cudaFuncSetAttribute(mma_gemm<1>, cudaFuncAttributeMaxDynamicSharedMemorySize, GEMM_SMEM);
    cudaFuncSetAttribute(mma_gemm<2>, cudaFuncAttributeMaxDynamicSharedMemorySize, GEMM_SMEM);
    cudaFuncSetAttribute(mma_gemm<3>, cudaFuncAttributeMaxDynamicSharedMemorySize, GEMM_SMEM);
    cudaFuncSetAttribute(flash_tc_kernel, cudaFuncAttributeMaxDynamicSharedMemorySize, FT_SMEM);

    wconv_kernel<<<dim3(QKVN/32, EMB/32, NLAYER), 256>>>(attn_w, wh + OFF_QKV, EMB, QKVN);
    wconv_kernel<<<dim3(EMB/32, EMB/32, NLAYER), 256>>>(attn_proj_w, wh + OFF_PROJ, EMB, EMB);
    wconv_kernel<<<dim3(FFN/32, EMB/32, NLAYER), 256>>>(fc_w, wh + OFF_FC, EMB, FFN);
    wconv_kernel<<<dim3(EMB/32, FFN/32, NLAYER), 256>>>(mlp_proj_w, wh + OFF_MLP, FFN, EMB);

    state_scan_kernel<<<1, 256>>>(ids, mul);
    state_proj_kernel<<<(VOC * EMB + 255) / 256, 256>>>(state_emb, state_proj_w, state_proj_b);
    embed_kernel<<<(BT * EMB + 255) / 256, 256>>>(ids, tok_emb, wpe);

    for (int l = 0; l < NLAYER; l++) {
        ln_f16_kernel<<<BT, 256>>>(h, ln1_g + l * EMB, ln1_b + l * EMB, lnh, lnl);
        mma_gemm<3><<<dim3(QKVN/64, BT/128), 256, GEMM_SMEM>>>(
            lnh, lnl, wh + OFF_QKV + (size_t)l * W_QKV,
            attn_b + l * QKVN, nullptr, nullptr, qkh, qkl, vth, vtl, EMB, QKVN);
        flash_tc_kernel<<<dim3(SEQ/128, BATCH * NH), 256, FT_SMEM>>>();
        mma_gemm<1><<<dim3(EMB/64, BT/128), 256, GEMM_SMEM>>>(
            atth, attl, wh + OFF_PROJ + (size_t)l * W_PROJ,
            attn_proj_b + l * EMB, h, h, nullptr, nullptr, nullptr, nullptr, EMB, EMB);
        ln_f16_kernel<<<BT, 256>>>(h, ln2_g + l * EMB, ln2_b + l * EMB, lnh, lnl);
        mma_gemm<2><<<dim3(FFN/64, BT/128), 256, GEMM_SMEM>>>(
            lnh, lnl, wh + OFF_FC + (size_t)l * W_FC,
            fc_b + l * FFN, nullptr, nullptr, midh, midl, nullptr, nullptr, EMB, FFN);
        mma_gemm<1><<<dim3(EMB/64, BT/128), 256, GEMM_SMEM>>>(
            midh, midl, wh + OFF_MLP + (size_t)l * W_MLP,
            mlp_proj_b + l * EMB, h, h, nullptr, nullptr, nullptr, nullptr, FFN, EMB);
    }

    ln_kernel<<<BT, 256>>>(h, lnf_g, lnf_b, lnbuf);
    head_gemm_kernel<<<dim3(1, BT / 64), 256>>>(lnbuf, head_w, head_b, out, VOC, EMB);
}

// round 15
// speedup vs baseline: 1.2048x; 1.0034x over previous
#include <cuda_runtime.h>
#include <cuda_fp16.h>
#include <math.h>
#include <stdint.h>

#define BATCH 8
#define SEQ 512
#define BT (BATCH*SEQ)        // 4096
#define EMB 768
#define NH 12
#define DH 64
#define VOC 60
#define DST 128
#define NLAYER 12
#define QKVN (3*EMB)          // 2304
#define FFN (4*EMB)           // 3072

#define W_QKV (QKVN*EMB)
#define W_PROJ (EMB*EMB)
#define W_FC (FFN*EMB)
#define W_MLP (EMB*FFN)
#define OFF_QKV 0
#define OFF_PROJ (12*W_QKV)
#define OFF_FC (OFF_PROJ + 12*W_PROJ)
#define OFF_MLP (OFF_FC + 12*W_FC)
#define W_TOTAL (OFF_MLP + 12*W_MLP)

// ---------------- scratch ----------------
__device__ float g_h[BT*EMB];
__device__ float g_ln[BT*EMB];
__device__ float g_semb[VOC*EMB];
__device__ int   g_pre[BT];

__device__ __half g_wh[W_TOTAL];                 // weights, single fp16, [N][K]
__device__ __half g_lnh[BT*EMB],  g_lnl[BT*EMB]; // activations, fp16 hi/lo
__device__ __half g_atth[BT*EMB], g_attl[BT*EMB];
__device__ __half g_midh[BT*FFN], g_midl[BT*FFN];
__device__ __half g_qkh[2*BT*EMB], g_qkl[2*BT*EMB];   // Q then K, row-major
__device__ __half g_vth[BATCH*NH*DH*SEQ], g_vtl[BATCH*NH*DH*SEQ]; // V^T [bh][d][s]

// ---------------- helpers ----------------
__device__ __forceinline__ uint32_t smem_u32(const void* p) {
    uint32_t a;
    asm("{ .reg .u64 t; cvta.to.shared.u64 t, %1; cvt.u32.u64 %0, t; }" : "=r"(a) : "l"(p));
    return a;
}

__device__ __forceinline__ void ldsm_x4(uint32_t* r, uint32_t addr) {
    asm volatile("ldmatrix.sync.aligned.m8n8.x4.shared.b16 {%0,%1,%2,%3}, [%4];"
        : "=r"(r[0]), "=r"(r[1]), "=r"(r[2]), "=r"(r[3]) : "r"(addr));
}

__device__ __forceinline__ void mma_f16(float* c, const uint32_t* a, const uint32_t* b) {
    asm volatile("mma.sync.aligned.m16n8k16.row.col.f32.f16.f16.f32 "
        "{%0,%1,%2,%3}, {%4,%5,%6,%7}, {%8,%9}, {%0,%1,%2,%3};"
        : "+f"(c[0]), "+f"(c[1]), "+f"(c[2]), "+f"(c[3])
        : "r"(a[0]), "r"(a[1]), "r"(a[2]), "r"(a[3]), "r"(b[0]), "r"(b[1]));
}

__device__ __forceinline__ void cp16(uint32_t dst, const void* src) {
    asm volatile("cp.async.cg.shared.global [%0], [%1], 16;" :: "r"(dst), "l"(src));
}
#define CP_COMMIT() asm volatile("cp.async.commit_group;" ::: "memory")
#define CP_WAIT(n)  asm volatile("cp.async.wait_group %0;" :: "n"(n) : "memory")

__device__ __forceinline__ void cvt_split2h(float x0, float x1, uint32_t& hi, uint32_t& lo) {
    __half h0 = __float2half_rn(x0);
    __half h1 = __float2half_rn(x1);
    __half l0 = __float2half_rn(x0 - __half2float(h0));
    __half l1 = __float2half_rn(x1 - __half2float(h1));
    __half2 H(h0, h1), L(l0, l1);
    hi = *(uint32_t*)&H;
    lo = *(uint32_t*)&L;
}

// ---------------- reductions ----------------
__device__ __forceinline__ float breduce_sum(float v, float* sh, int nthr) {
#pragma unroll
    for (int o = 16; o > 0; o >>= 1) v += __shfl_xor_sync(0xffffffffu, v, o);
    int lane = threadIdx.x & 31, w = threadIdx.x >> 5;
    if (lane == 0) sh[w] = v;
    __syncthreads();
    float r = 0.f;
    if ((int)threadIdx.x < (nthr >> 5)) r = sh[threadIdx.x];
    if (threadIdx.x < 32) {
#pragma unroll
        for (int o = 16; o > 0; o >>= 1) r += __shfl_xor_sync(0xffffffffu, r, o);
        if (threadIdx.x == 0) sh[0] = r;
    }
    __syncthreads();
    r = sh[0];
    __syncthreads();
    return r;
}

// ---------------- automaton state scan ----------------
__global__ void state_scan_kernel(const int* __restrict__ ids, const int* __restrict__ mul) {
    __shared__ int smul[VOC*VOC];
    __shared__ int sids[BT];
    int tid = threadIdx.x;
    for (int i = tid; i < VOC*VOC; i += blockDim.x) smul[i] = mul[i];
    for (int i = tid; i < BT; i += blockDim.x) sids[i] = ids[i];
    __syncthreads();
    if (tid < BATCH) {
        int s = 0;
        const int* row = sids + tid * SEQ;
        int* pre = g_pre + tid * SEQ;
        for (int t = 0; t < SEQ; t++) {
            pre[t] = s;
            s = smul[row[t] * VOC + s];
        }
    }
}

__global__ void state_proj_kernel(const float* __restrict__ semb,
                                  const float* __restrict__ W,
                                  const float* __restrict__ b) {
    int idx = blockIdx.x * blockDim.x + threadIdx.x;
    if (idx >= VOC * EMB) return;
    int v = idx / EMB, e = idx % EMB;
    float acc = b[e];
#pragma unroll 8
    for (int d = 0; d < DST; d++) acc += semb[v * DST + d] * W[d * EMB + e];
    g_semb[idx] = acc;
}

__global__ void embed_kernel(const int* __restrict__ ids,
                             const float* __restrict__ tok_emb,
                             const float* __restrict__ wpe) {
    int idx = blockIdx.x * blockDim.x + threadIdx.x;
    if (idx >= BT * EMB) return;
    int bt = idx / EMB, e = idx % EMB;
    int t = bt % SEQ;
    g_h[idx] = tok_emb[ids[bt] * EMB + e] + g_semb[g_pre[bt] * EMB + e] + wpe[t * EMB + e];
}

// ---------------- weight convert: W[K][N] fp32 -> fp16 [N][K] --------------
// 32(n) x 64(k) tiles; 16B vectorized stores (8 halves per thread).
__global__ __launch_bounds__(256) void wconv_kernel(
    const float* __restrict__ W, __half* __restrict__ Hi, int K, int N)
{
    __shared__ float t[64][33];
    int l = blockIdx.z;
    const float* Wl = W + (size_t)l * K * N;
    __half* Hl = Hi + (size_t)l * K * N;
    int n0 = blockIdx.x * 32, k0 = blockIdx.y * 64;
    int tid = threadIdx.x;
    // load: 64 k-rows x 32 n-cols, coalesced in n
    int lk = tid >> 5, ln_ = tid & 31;
#pragma unroll
    for (int i = 0; i < 8; i++)
        t[lk + 8 * i][ln_] = Wl[(size_t)(k0 + lk + 8 * i) * N + n0 + ln_];
    __syncthreads();
    // store: thread (n, g) packs 8 consecutive k halves -> one 16B store
    int n = tid >> 3, g = tid & 7;
    __half hv[8];
#pragma unroll
    for (int j = 0; j < 8; j++)
        hv[j] = __float2half_rn(t[g * 8 + j][n]);
    *reinterpret_cast<uint4*>(Hl + (size_t)(n0 + n) * K + k0 + g * 8)
        = *reinterpret_cast<uint4*>(hv);
}

// ---------------- layernorm variants ----------------
__global__ __launch_bounds__(256) void ln_kernel(const float* __restrict__ x,
                                                 const float* __restrict__ g,
                                                 const float* __restrict__ b,
                                                 float* __restrict__ y) {
    __shared__ float sh[8];
    int row = blockIdx.x, tid = threadIdx.x;
    const float* xr = x + (size_t)row * EMB;
    float v0 = xr[tid], v1 = xr[tid + 256], v2 = xr[tid + 512];
    float mean = breduce_sum(v0 + v1 + v2, sh, 256) * (1.f / EMB);
    float d0 = v0 - mean, d1 = v1 - mean, d2 = v2 - mean;
    float var = breduce_sum(d0*d0 + d1*d1 + d2*d2, sh, 256) * (1.f / EMB);
    float rstd = rsqrtf(var + 1e-5f);
    float* yr = y + (size_t)row * EMB;
    yr[tid]       = d0 * rstd * g[tid]       + b[tid];
    yr[tid + 256] = d1 * rstd * g[tid + 256] + b[tid + 256];
    yr[tid + 512] = d2 * rstd * g[tid + 512] + b[tid + 512];
}

__global__ __launch_bounds__(256) void ln_f16_kernel(const float* __restrict__ x,
                                                     const float* __restrict__ g,
                                                     const float* __restrict__ b,
                                                     __half* __restrict__ yh,
                                                     __half* __restrict__ yl) {
    __shared__ float sh[8];
    int row = blockIdx.x, tid = threadIdx.x;
    const float* xr = x + (size_t)row * EMB;
    float v0 = xr[tid], v1 = xr[tid + 256], v2 = xr[tid + 512];
    float mean = breduce_sum(v0 + v1 + v2, sh, 256) * (1.f / EMB);
    float d0 = v0 - mean, d1 = v1 - mean, d2 = v2 - mean;
    float var = breduce_sum(d0*d0 + d1*d1 + d2*d2, sh, 256) * (1.f / EMB);
    float rstd = rsqrtf(var + 1e-5f);
    size_t base = (size_t)row * EMB;
#pragma unroll
    for (int q = 0; q < 3; q++) {
        int e = tid + q * 256;
        float d = (q == 0) ? d0 : (q == 1) ? d1 : d2;
        float v = d * rstd * g[e] + b[e];
        __half h = __float2half_rn(v);
        yh[base + e] = h;
        yl[base + e] = __float2half_rn(v - __half2float(h));
    }
}

// ================= mma.sync fp16 2-term GEMM (3-deep ring, R12 proven) =====
__device__ __forceinline__ float gelu_f(float x) {
    return 0.5f * x * (1.f + tanhf(0.7978845608028654f * (x + 0.044715f * x * x * x)));
}

#define ROWB 80
#define SM_AH 0
#define SM_AL 10240
#define SM_BH 20480
#define BUFSZ 25600
#define GEMM_SMEM (3*BUFSZ)   // 76800/CTA

template<int EPI>
__global__ __launch_bounds__(256, 2) void mma_gemm(
    const __half* __restrict__ Ah, const __half* __restrict__ Al,
    const __half* __restrict__ Bh,
    const float* __restrict__ bias,
    const float* __restrict__ Res,
    float* __restrict__ C,
    __half* __restrict__ Ch, __half* __restrict__ Cl,
    __half* __restrict__ Vh, __half* __restrict__ Vl,
    int K, int N)
{
    extern __shared__ __align__(16) char sm[];
    uint32_t sb = smem_u32(sm);
    int tid = threadIdx.x;
    int wid = tid >> 5, lane = tid & 31;
    int wm = wid & 3, wn = wid >> 2;
    int m0 = blockIdx.y * 128, n0 = blockIdx.x * 64;

    int p_row = tid >> 2;
    int p_seg = tid & 3;

    int a_row = lane & 15;
    int a_colb = ((lane >> 4) * 8) * 2;
    int b_row = (lane & 7) + ((lane >> 4) & 1) * 8;
    int b_colb = (((lane >> 3) & 1) * 8) * 2;

    float acc[2][4][4];
#pragma unroll
    for (int i = 0; i < 2; i++)
#pragma unroll
        for (int j = 0; j < 4; j++)
#pragma unroll
            for (int q = 0; q < 4; q++) acc[i][j][q] = 0.f;

    const int nch = K >> 5;

    auto issue = [&](int c, int bufsel) {
        int k0 = c << 5;
        uint32_t base = sb + bufsel * BUFSZ;
        uint32_t doff = (uint32_t)(p_row * ROWB + p_seg * 16);
#pragma unroll
        for (int i = 0; i < 2; i++) {
            int row = p_row + i * 64;
            size_t aoff = (size_t)(m0 + row) * K + k0 + p_seg * 8;
            cp16(base + SM_AH + doff + i * (64 * ROWB), Ah + aoff);
            cp16(base + SM_AL + doff + i * (64 * ROWB), Al + aoff);
        }
        size_t boff = (size_t)(n0 + p_row) * K + k0 + p_seg * 8;
        cp16(base + SM_BH + doff, Bh + boff);
    };

    issue(0, 0);
    CP_COMMIT();

    int curb = 0, nxtb = 1;
    for (int c = 0; c < nch; c++) {
        if (c + 1 < nch) {
            issue(c + 1, nxtb);
            CP_COMMIT();
            CP_WAIT(1);
        } else {
            CP_WAIT(0);
        }
        __syncthreads();

        uint32_t base = sb + curb * BUFSZ;
#pragma unroll
        for (int ks = 0; ks < 2; ks++) {
            uint32_t a_hi[2][4], a_lo[2][4];
#pragma unroll
            for (int mt = 0; mt < 2; mt++) {
                uint32_t off = (uint32_t)((wm * 32 + mt * 16 + a_row) * ROWB
                                          + ks * 32 + a_colb);
                ldsm_x4(a_hi[mt], base + SM_AH + off);
                ldsm_x4(a_lo[mt], base + SM_AL + off);
            }
            uint32_t b_hi[2][4];
#pragma unroll
            for (int p = 0; p < 2; p++) {
                uint32_t off = (uint32_t)((wn * 32 + p * 16 + b_row) * ROWB
                                          + ks * 32 + b_colb);
                ldsm_x4(b_hi[p], base + SM_BH + off);
            }
#pragma unroll
            for (int mt = 0; mt < 2; mt++)
#pragma unroll
                for (int p = 0; p < 2; p++) {
                    mma_f16(acc[mt][2*p],   a_hi[mt], &b_hi[p][0]);
                    mma_f16(acc[mt][2*p+1], a_hi[mt], &b_hi[p][2]);
                }
#pragma unroll
            for (int mt = 0; mt < 2; mt++)
#pragma unroll
                for (int p = 0; p < 2; p++) {
                    mma_f16(acc[mt][2*p],   a_lo[mt], &b_hi[p][0]);
                    mma_f16(acc[mt][2*p+1], a_lo[mt], &b_hi[p][2]);
                }
        }
        curb = nxtb;
        nxtb = (nxtb == 2) ? 0 : nxtb + 1;
    }

    int r0 = m0 + wm * 32 + (lane >> 2);
    int c0 = n0 + wn * 32 + (lane & 3) * 2;
#pragma unroll
    for (int mt = 0; mt < 2; mt++) {
#pragma unroll
        for (int nt = 0; nt < 4; nt++) {
            int r = r0 + mt * 16;
            int cc = c0 + nt * 8;
            float b0 = bias[cc], b1 = bias[cc + 1];
            float v0 = acc[mt][nt][0] + b0;
            float v1 = acc[mt][nt][1] + b1;
            float v2 = acc[mt][nt][2] + b0;
            float v3 = acc[mt][nt][3] + b1;
            if (EPI == 2) {
                v0 = gelu_f(v0); v1 = gelu_f(v1);
                v2 = gelu_f(v2); v3 = gelu_f(v3);
                uint32_t h01, l01, h23, l23;
                cvt_split2h(v0, v1, h01, l01);
                cvt_split2h(v2, v3, h23, l23);
                *(uint32_t*)(Ch + (size_t)r * N + cc) = h01;
                *(uint32_t*)(Cl + (size_t)r * N + cc) = l01;
                *(uint32_t*)(Ch + (size_t)(r + 8) * N + cc) = h23;
                *(uint32_t*)(Cl + (size_t)(r + 8) * N + cc) = l23;
            } else if (EPI == 3) {
                if (cc < 1536) {
                    int kk = (cc >= 768);
                    size_t idx = (size_t)kk * (BT * EMB)
                               + (size_t)r * EMB + (cc - kk * 768);
                    uint32_t h01, l01, h23, l23;
                    cvt_split2h(v0, v1, h01, l01);
                    cvt_split2h(v2, v3, h23, l23);
                    *(uint32_t*)(Ch + idx) = h01;
                    *(uint32_t*)(Cl + idx) = l01;
                    *(uint32_t*)(Ch + idx + (size_t)8 * EMB) = h23;
                    *(uint32_t*)(Cl + idx + (size_t)8 * EMB) = l23;
                } else {
                    int b = r >> 9, s = r & 511;
                    int hd = cc - 1536;
                    int hh_ = hd >> 6, d = hd & 63;
                    size_t idx = ((size_t)(b * NH + hh_) * 64 + d) * 512 + s;
                    __half a0 = __float2half_rn(v0);
                    Vh[idx] = a0;
                    Vl[idx] = __float2half_rn(v0 - __half2float(a0));
                    __half a1 = __float2half_rn(v1);
                    Vh[idx + 512] = a1;
                    Vl[idx + 512] = __float2half_rn(v1 - __half2float(a1));
                    __half a2 = __float2half_rn(v2);
                    Vh[idx + 8] = a2;
                    Vl[idx + 8] = __float2half_rn(v2 - __half2float(a2));
                    __half a3 = __float2half_rn(v3);
                    Vh[idx + 512 + 8] = a3;
                    Vl[idx + 512 + 8] = __float2half_rn(v3 - __half2float(a3));
                }
            } else {
                if (EPI == 1) {
                    const float* rp0 = Res + (size_t)r * N + cc;
                    const float* rp1 = Res + (size_t)(r + 8) * N + cc;
                    v0 += rp0[0]; v1 += rp0[1];
                    v2 += rp1[0]; v3 += rp1[1];
                }
                *reinterpret_cast<float2*>(C + (size_t)r * N + cc) = make_float2(v0, v1);
                *reinterpret_cast<float2*>(C + (size_t)(r + 8) * N + cc) = make_float2(v2, v3);
            }
        }
    }
}

// ================= tensor-core causal flash attention ======================
// fp16 hi/lo QKV from global; KV tiles double-buffered (R14).
#define FROWB 144
#define FT_QH 0
#define FT_QL (128*FROWB)            // 18432
#define FT_KV0 (2*128*FROWB)         // 36864
#define KV_KH 0
#define KV_KL (64*FROWB)             // 9216
#define KV_VH (2*64*FROWB)           // 18432
#define KV_VL (3*64*FROWB)           // 27648
#define KVBUF (4*64*FROWB)           // 36864
#define FT_SMEM (FT_KV0 + 2*KVBUF)   // 110592

__global__ __launch_bounds__(256, 2) void flash_tc_kernel() {
    extern __shared__ __align__(16) char fsm[];
    uint32_t sb = smem_u32(fsm);
    int bh = blockIdx.y;
    int b = bh / NH, h = bh % NH;
    int t0 = blockIdx.x * 128;
    int tid = threadIdx.x;
    int wid = tid >> 5, lane = tid & 31;

    const __half* Kh = g_qkh + (size_t)BT * EMB;
    const __half* Kl = g_qkl + (size_t)BT * EMB;

    int a_row = lane & 15;
    int a_colb = ((lane >> 4) * 8) * 2;
    int b_row = (lane & 7) + ((lane >> 4) & 1) * 8;
    int b_colb = (((lane >> 3) & 1) * 8) * 2;

    auto kv_issue = [&](int j, int buf) {
        int s = tid >> 2, seg = tid & 3;
        uint32_t base = sb + FT_KV0 + buf * KVBUF;
        size_t koff = (size_t)(b * SEQ + j * 64 + s) * EMB + h * DH + seg * 16;
        uint32_t kdh = base + KV_KH + s * FROWB + seg * 32;
        uint32_t kdl = base + KV_KL + s * FROWB + seg * 32;
        cp16(kdh,      Kh + koff);
        cp16(kdh + 16, Kh + koff + 8);
        cp16(kdl,      Kl + koff);
        cp16(kdl + 16, Kl + koff + 8);
        size_t voff = ((size_t)bh * 64 + s) * 512 + j * 64 + seg * 16;
        uint32_t vdh = base + KV_VH + s * FROWB + seg * 32;
        uint32_t vdl = base + KV_VL + s * FROWB + seg * 32;
        cp16(vdh,      g_vth + voff);
        cp16(vdh + 16, g_vth + voff + 8);
        cp16(vdl,      g_vtl + voff);
        cp16(vdl + 16, g_vtl + voff + 8);
    };

    {
        int row = tid >> 1, hf = tid & 1;
        size_t qoff = (size_t)(b * SEQ + t0 + row) * EMB + h * DH + hf * 32;
        uint32_t dh_ = sb + FT_QH + row * FROWB + hf * 64;
        uint32_t dl_ = sb + FT_QL + row * FROWB + hf * 64;
#pragma unroll
        for (int i = 0; i < 4; i++) {
            cp16(dh_ + 16 * i, g_qkh + qoff + 8 * i);
            cp16(dl_ + 16 * i, g_qkl + qoff + 8 * i);
        }
    }
    kv_issue(0, 0);
    CP_COMMIT();
    CP_WAIT(0);
    __syncthreads();

    float m0 = -1e30f, m1 = -1e30f, l0 = 0.f, l1 = 0.f;
    float O[8][4];
#pragma unroll
    for (int f = 0; f < 8; f++)
#pragma unroll
        for (int q = 0; q < 4; q++) O[f][q] = 0.f;

    int t_r0 = t0 + wid * 16 + (lane >> 2);
    int ntile = (t0 >> 6) + 2;

    for (int j = 0; j < ntile; j++) {
        int cur = j & 1;
        if (j + 1 < ntile) {
            kv_issue(j + 1, cur ^ 1);
            CP_COMMIT();
        }
        uint32_t kvb = sb + FT_KV0 + cur * KVBUF;

        float S[8][4];
#pragma unroll
        for (int f = 0; f < 8; f++)
#pragma unroll
            for (int q = 0; q < 4; q++) S[f][q] = 0.f;
#pragma unroll
        for (int ks = 0; ks < 4; ks++) {
            uint32_t aq_h[4], aq_l[4];
            uint32_t aoff = (uint32_t)((wid * 16 + a_row) * FROWB + ks * 32 + a_colb);
            ldsm_x4(aq_h, sb + FT_QH + aoff);
            ldsm_x4(aq_l, sb + FT_QL + aoff);
#pragma unroll
            for (int p = 0; p < 4; p++) {
                uint32_t bk_h[4], bk_l[4];
                uint32_t boff = (uint32_t)((p * 16 + b_row) * FROWB + ks * 32 + b_colb);
                ldsm_x4(bk_h, kvb + KV_KH + boff);
                ldsm_x4(bk_l, kvb + KV_KL + boff);
                mma_f16(S[2*p],   aq_h, &bk_h[0]);
                mma_f16(S[2*p+1], aq_h, &bk_h[2]);
                mma_f16(S[2*p],   aq_l, &bk_h[0]);
                mma_f16(S[2*p+1], aq_l, &bk_h[2]);
                mma_f16(S[2*p],   aq_h, &bk_l[0]);
                mma_f16(S[2*p+1], aq_h, &bk_l[2]);
            }
        }

#pragma unroll
        for (int f = 0; f < 8; f++) {
            int c = j * 64 + (f >> 1) * 16 + (f & 1) * 8 + (lane & 3) * 2;
#pragma unroll
            for (int q = 0; q < 4; q++) S[f][q] *= 0.125f;
            if (c     > t_r0) S[f][0] = -1e30f;
            if (c + 1 > t_r0) S[f][1] = -1e30f;
            if (c     > t_r0 + 8) S[f][2] = -1e30f;
            if (c + 1 > t_r0 + 8) S[f][3] = -1e30f;
        }

        float mx0 = -1e30f, mx1 = -1e30f;
#pragma unroll
        for (int f = 0; f < 8; f++) {
            mx0 = fmaxf(mx0, fmaxf(S[f][0], S[f][1]));
            mx1 = fmaxf(mx1, fmaxf(S[f][2], S[f][3]));
        }
        mx0 = fmaxf(mx0, __shfl_xor_sync(0xffffffffu, mx0, 1));
        mx0 = fmaxf(mx0, __shfl_xor_sync(0xffffffffu, mx0, 2));
        mx1 = fmaxf(mx1, __shfl_xor_sync(0xffffffffu, mx1, 1));
        mx1 = fmaxf(mx1, __shfl_xor_sync(0xffffffffu, mx1, 2));
        float mn0 = fmaxf(m0, mx0), mn1 = fmaxf(m1, mx1);
        float c0 = __expf(m0 - mn0), c1 = __expf(m1 - mn1);
        m0 = mn0; m1 = mn1;
        float rs0 = 0.f, rs1 = 0.f;
#pragma unroll
        for (int f = 0; f < 8; f++) {
            S[f][0] = __expf(S[f][0] - mn0);
            S[f][1] = __expf(S[f][1] - mn0);
            S[f][2] = __expf(S[f][2] - mn1);
            S[f][3] = __expf(S[f][3] - mn1);
            rs0 += S[f][0] + S[f][1];
            rs1 += S[f][2] + S[f][3];
        }
        rs0 += __shfl_xor_sync(0xffffffffu, rs0, 1);
        rs0 += __shfl_xor_sync(0xffffffffu, rs0, 2);
        rs1 += __shfl_xor_sync(0xffffffffu, rs1, 1);
        rs1 += __shfl_xor_sync(0xffffffffu, rs1, 2);
        l0 = l0 * c0 + rs0;
        l1 = l1 * c1 + rs1;
#pragma unroll
        for (int f = 0; f < 8; f++) {
            O[f][0] *= c0; O[f][1] *= c0;
            O[f][2] *= c1; O[f][3] *= c1;
        }

#pragma unroll
        for (int g = 0; g < 4; g++) {
            uint32_t pa[4];
            __half2 p0 = __floats2half2_rn(S[2*g][0],   S[2*g][1]);
            __half2 p1 = __floats2half2_rn(S[2*g][2],   S[2*g][3]);
            __half2 p2 = __floats2half2_rn(S[2*g+1][0], S[2*g+1][1]);
            __half2 p3 = __floats2half2_rn(S[2*g+1][2], S[2*g+1][3]);
            pa[0] = *(uint32_t*)&p0;
            pa[1] = *(uint32_t*)&p1;
            pa[2] = *(uint32_t*)&p2;
            pa[3] = *(uint32_t*)&p3;
#pragma unroll
            for (int p = 0; p < 4; p++) {
                uint32_t bv_h[4], bv_l[4];
                uint32_t boff = (uint32_t)((p * 16 + b_row) * FROWB + g * 32 + b_colb);
                ldsm_x4(bv_h, kvb + KV_VH + boff);
                ldsm_x4(bv_l, kvb + KV_VL + boff);
                mma_f16(O[2*p],   pa, &bv_h[0]);
                mma_f16(O[2*p+1], pa, &bv_h[2]);
                mma_f16(O[2*p],   pa, &bv_l[0]);
                mma_f16(O[2*p+1], pa, &bv_l[2]);
            }
        }

        if (j + 1 < ntile) {
            CP_WAIT(0);
        }
        __syncthreads();
    }

    float inv0 = 1.f / l0, inv1 = 1.f / l1;
#pragma unroll
    for (int f = 0; f < 8; f++) {
        int d = (f >> 1) * 16 + (f & 1) * 8 + (lane & 3) * 2;
        size_t base0 = (size_t)(b * SEQ + t_r0) * EMB + h * DH + d;
        size_t base1 = (size_t)(b * SEQ + t_r0 + 8) * EMB + h * DH + d;
        uint32_t hh, ll;
        cvt_split2h(O[f][0] * inv0, O[f][1] * inv0, hh, ll);
        *(uint32_t*)(g_atth + base0) = hh;
        *(uint32_t*)(g_attl + base0) = ll;
        cvt_split2h(O[f][2] * inv1, O[f][3] * inv1, hh, ll);
        *(uint32_t*)(g_atth + base1) = hh;
        *(uint32_t*)(g_attl + base1) = ll;
    }
}

// ---------------- head GEMM (N=60, FFMA) ----------------
__global__ __launch_bounds__(256) void head_gemm_kernel(
    const float* __restrict__ A,
    const float* __restrict__ Bm,
    const float* __restrict__ bias,
    float* __restrict__ C,
    int N, int K)
{
    __shared__ float As[16][68];
    __shared__ float Bs[16][64];
    int m0 = blockIdx.y * 64, n0 = blockIdx.x * 64;
    int tid = threadIdx.x;
    int tx = tid & 15, ty = tid >> 4;
    float acc[4][4] = {};
    for (int k0 = 0; k0 < K; k0 += 16) {
#pragma unroll
        for (int i = 0; i < 4; i++) {
            int lin = tid + i * 256;
            int r = lin >> 4, c = lin & 15;
            As[c][r] = A[(size_t)(m0 + r) * K + k0 + c];
        }
#pragma unroll
        for (int i = 0; i < 4; i++) {
            int lin = tid + i * 256;
            int r = lin >> 6, c = lin & 63;
            int n = n0 + c;
            Bs[r][c] = (n < N) ? Bm[(size_t)(k0 + r) * N + n] : 0.f;
        }
        __syncthreads();
#pragma unroll
        for (int kk = 0; kk < 16; kk++) {
            float4 a4 = *reinterpret_cast<const float4*>(&As[kk][ty * 4]);
            float4 b4 = *reinterpret_cast<const float4*>(&Bs[kk][tx * 4]);
            float a[4] = {a4.x, a4.y, a4.z, a4.w};
            float bv[4] = {b4.x, b4.y, b4.z, b4.w};
#pragma unroll
            for (int i = 0; i < 4; i++)
#pragma unroll
                for (int j = 0; j < 4; j++)
                    acc[i][j] = fmaf(a[i], bv[j], acc[i][j]);
        }
        __syncthreads();
    }
#pragma unroll
    for (int i = 0; i < 4; i++) {
        int m = m0 + ty * 4 + i;
#pragma unroll
        for (int j = 0; j < 4; j++) {
            int n = n0 + tx * 4 + j;
            if (n < N) C[(size_t)m * N + n] = acc[i][j] + bias[n];
        }
    }
}

// ---------------- host orchestration ----------------
extern "C" void kernel_launch(void* const* d_in, const int* in_sizes, int n_in,
                              void* d_out, int out_size) {
    const int*   ids          = (const int*)d_in[0];
    const int*   mul          = (const int*)d_in[1];
    const float* tok_emb      = (const float*)d_in[2];
    const float* state_emb    = (const float*)d_in[3];
    const float* state_proj_w = (const float*)d_in[4];
    const float* state_proj_b = (const float*)d_in[5];
    const float* wpe          = (const float*)d_in[6];
    const float* ln1_g        = (const float*)d_in[7];
    const float* ln1_b        = (const float*)d_in[8];
    const float* attn_w       = (const float*)d_in[9];
    const float* attn_b       = (const float*)d_in[10];
    const float* attn_proj_w  = (const float*)d_in[11];
    const float* attn_proj_b  = (const float*)d_in[12];
    const float* ln2_g        = (const float*)d_in[13];
    const float* ln2_b        = (const float*)d_in[14];
    const float* fc_w         = (const float*)d_in[15];
    const float* fc_b         = (const float*)d_in[16];
    const float* mlp_proj_w   = (const float*)d_in[17];
    const float* mlp_proj_b   = (const float*)d_in[18];
    const float* lnf_g        = (const float*)d_in[19];
    const float* lnf_b        = (const float*)d_in[20];
    const float* head_w       = (const float*)d_in[21];
    const float* head_b       = (const float*)d_in[22];
    float* out = (float*)d_out;

    float *h, *lnbuf;
    __half *wh, *lnh, *lnl, *atth, *attl, *midh, *midl, *qkh, *qkl, *vth, *vtl;
    cudaGetSymbolAddress((void**)&h,     g_h);
    cudaGetSymbolAddress((void**)&lnbuf, g_ln);
    cudaGetSymbolAddress((void**)&wh,    g_wh);
    cudaGetSymbolAddress((void**)&lnh,   g_lnh);
    cudaGetSymbolAddress((void**)&lnl,   g_lnl);
    cudaGetSymbolAddress((void**)&atth,  g_atth);
    cudaGetSymbolAddress((void**)&attl,  g_attl);
    cudaGetSymbolAddress((void**)&midh,  g_midh);
    cudaGetSymbolAddress((void**)&midl,  g_midl);
    cudaGetSymbolAddress((void**)&qkh,   g_qkh);
    cudaGetSymbolAddress((void**)&qkl,   g_qkl);
    cudaGetSymbolAddress((void**)&vth,   g_vth);
    cudaGetSymbolAddress((void**)&vtl,   g_vtl);

    cudaFuncSetAttribute(mma_gemm<1>, cudaFuncAttributeMaxDynamicSharedMemorySize, GEMM_SMEM);
    cudaFuncSetAttribute(mma_gemm<2>, cudaFuncAttributeMaxDynamicSharedMemorySize, GEMM_SMEM);
    cudaFuncSetAttribute(mma_gemm<3>, cudaFuncAttributeMaxDynamicSharedMemorySize, GEMM_SMEM);
    cudaFuncSetAttribute(flash_tc_kernel, cudaFuncAttributeMaxDynamicSharedMemorySize, FT_SMEM);

    wconv_kernel<<<dim3(QKVN/32, EMB/64, NLAYER), 256>>>(attn_w, wh + OFF_QKV, EMB, QKVN);
    wconv_kernel<<<dim3(EMB/32, EMB/64, NLAYER), 256>>>(attn_proj_w, wh + OFF_PROJ, EMB, EMB);
    wconv_kernel<<<dim3(FFN/32, EMB/64, NLAYER), 256>>>(fc_w, wh + OFF_FC, EMB, FFN);
    wconv_kernel<<<dim3(EMB/32, FFN/64, NLAYER), 256>>>(mlp_proj_w, wh + OFF_MLP, FFN, EMB);

    state_scan_kernel<<<1, 256>>>(ids, mul);
    state_proj_kernel<<<(VOC * EMB + 255) / 256, 256>>>(state_emb, state_proj_w, state_proj_b);
    embed_kernel<<<(BT * EMB + 255) / 256, 256>>>(ids, tok_emb, wpe);

    for (int l = 0; l < NLAYER; l++) {
        ln_f16_kernel<<<BT, 256>>>(h, ln1_g + l * EMB, ln1_b + l * EMB, lnh, lnl);
        mma_gemm<3><<<dim3(QKVN/64, BT/128), 256, GEMM_SMEM>>>(
            lnh, lnl, wh + OFF_QKV + (size_t)l * W_QKV,
            attn_b + l * QKVN, nullptr, nullptr, qkh, qkl, vth, vtl, EMB, QKVN);
        flash_tc_kernel<<<dim3(SEQ/128, BATCH * NH), 256, FT_SMEM>>>();
        mma_gemm<1><<<dim3(EMB/64, BT/128), 256, GEMM_SMEM>>>(
            atth, attl, wh + OFF_PROJ + (size_t)l * W_PROJ,
            attn_proj_b + l * EMB, h, h, nullptr, nullptr, nullptr, nullptr, EMB, EMB);
        ln_f16_kernel<<<BT, 256>>>(h, ln2_g + l * EMB, ln2_b + l * EMB, lnh, lnl);
        mma_gemm<2><<<dim3(FFN/64, BT/128), 256, GEMM_SMEM>>>(
            lnh, lnl, wh + OFF_FC + (size_t)l * W_FC,
            fc_b + l * FFN, nullptr, nullptr, midh, midl, nullptr, nullptr, EMB, FFN);
        mma_gemm<1><<<dim3(EMB/64, BT/128), 256, GEMM_SMEM>>>(
            midh, midl, wh + OFF_MLP + (size_t)l * W_MLP,
            mlp_proj_b + l * EMB, h, h, nullptr, nullptr, nullptr, nullptr, FFN, EMB);
    }

    ln_kernel<<<BT, 256>>>(h, lnf_g, lnf_b, lnbuf);
    head_gemm_kernel<<<dim3(1, BT / 64), 256>>>(lnbuf, head_w, head_b, out, VOC, EMB);
}

// round 16
// speedup vs baseline: 1.2179x; 1.0109x over previous
#include <cuda_runtime.h>
#include <cuda_fp16.h>
#include <math.h>
#include <stdint.h>

#define BATCH 8
#define SEQ 512
#define BT (BATCH*SEQ)        // 4096
#define EMB 768
#define NH 12
#define DH 64
#define VOC 60
#define DST 128
#define NLAYER 12
#define QKVN (3*EMB)          // 2304
#define FFN (4*EMB)           // 3072

#define W_QKV (QKVN*EMB)
#define W_PROJ (EMB*EMB)
#define W_FC (FFN*EMB)
#define W_MLP (EMB*FFN)
#define OFF_QKV 0
#define OFF_PROJ (12*W_QKV)
#define OFF_FC (OFF_PROJ + 12*W_PROJ)
#define OFF_MLP (OFF_FC + 12*W_FC)
#define W_TOTAL (OFF_MLP + 12*W_MLP)

// ---------------- scratch ----------------
__device__ float g_h[BT*EMB];
__device__ float g_ln[BT*EMB];
__device__ float g_semb[VOC*EMB];
__device__ int   g_pre[BT];

__device__ __half g_wh[W_TOTAL];                 // weights, single fp16, [N][K]
__device__ __half g_lnh[BT*EMB],  g_lnl[BT*EMB]; // activations, fp16 hi/lo
__device__ __half g_atth[BT*EMB], g_attl[BT*EMB];
__device__ __half g_midh[BT*FFN], g_midl[BT*FFN];
__device__ __half g_qkh[2*BT*EMB], g_qkl[2*BT*EMB];   // Q then K, row-major
__device__ __half g_vth[BATCH*NH*DH*SEQ], g_vtl[BATCH*NH*DH*SEQ]; // V^T [bh][d][s]

// ---------------- helpers ----------------
__device__ __forceinline__ uint32_t smem_u32(const void* p) {
    uint32_t a;
    asm("{ .reg .u64 t; cvta.to.shared.u64 t, %1; cvt.u32.u64 %0, t; }" : "=r"(a) : "l"(p));
    return a;
}

__device__ __forceinline__ void ldsm_x4(uint32_t* r, uint32_t addr) {
    asm volatile("ldmatrix.sync.aligned.m8n8.x4.shared.b16 {%0,%1,%2,%3}, [%4];"
        : "=r"(r[0]), "=r"(r[1]), "=r"(r[2]), "=r"(r[3]) : "r"(addr));
}

__device__ __forceinline__ void mma_f16(float* c, const uint32_t* a, const uint32_t* b) {
    asm volatile("mma.sync.aligned.m16n8k16.row.col.f32.f16.f16.f32 "
        "{%0,%1,%2,%3}, {%4,%5,%6,%7}, {%8,%9}, {%0,%1,%2,%3};"
        : "+f"(c[0]), "+f"(c[1]), "+f"(c[2]), "+f"(c[3])
        : "r"(a[0]), "r"(a[1]), "r"(a[2]), "r"(a[3]), "r"(b[0]), "r"(b[1]));
}

__device__ __forceinline__ void cp16(uint32_t dst, const void* src) {
    asm volatile("cp.async.cg.shared.global [%0], [%1], 16;" :: "r"(dst), "l"(src));
}
#define CP_COMMIT() asm volatile("cp.async.commit_group;" ::: "memory")
#define CP_WAIT(n)  asm volatile("cp.async.wait_group %0;" :: "n"(n) : "memory")

__device__ __forceinline__ void cvt_split2h(float x0, float x1, uint32_t& hi, uint32_t& lo) {
    __half h0 = __float2half_rn(x0);
    __half h1 = __float2half_rn(x1);
    __half l0 = __float2half_rn(x0 - __half2float(h0));
    __half l1 = __float2half_rn(x1 - __half2float(h1));
    __half2 H(h0, h1), L(l0, l1);
    hi = *(uint32_t*)&H;
    lo = *(uint32_t*)&L;
}

// ---------------- automaton state scan ----------------
__global__ void state_scan_kernel(const int* __restrict__ ids, const int* __restrict__ mul) {
    __shared__ int smul[VOC*VOC];
    __shared__ int sids[BT];
    int tid = threadIdx.x;
    for (int i = tid; i < VOC*VOC; i += blockDim.x) smul[i] = mul[i];
    for (int i = tid; i < BT; i += blockDim.x) sids[i] = ids[i];
    __syncthreads();
    if (tid < BATCH) {
        int s = 0;
        const int* row = sids + tid * SEQ;
        int* pre = g_pre + tid * SEQ;
        for (int t = 0; t < SEQ; t++) {
            pre[t] = s;
            s = smul[row[t] * VOC + s];
        }
    }
}

__global__ void state_proj_kernel(const float* __restrict__ semb,
                                  const float* __restrict__ W,
                                  const float* __restrict__ b) {
    int idx = blockIdx.x * blockDim.x + threadIdx.x;
    if (idx >= VOC * EMB) return;
    int v = idx / EMB, e = idx % EMB;
    float acc = b[e];
#pragma unroll 8
    for (int d = 0; d < DST; d++) acc += semb[v * DST + d] * W[d * EMB + e];
    g_semb[idx] = acc;
}

__global__ void embed_kernel(const int* __restrict__ ids,
                             const float* __restrict__ tok_emb,
                             const float* __restrict__ wpe) {
    int idx = blockIdx.x * blockDim.x + threadIdx.x;
    if (idx >= BT * EMB) return;
    int bt = idx / EMB, e = idx % EMB;
    int t = bt % SEQ;
    g_h[idx] = tok_emb[ids[bt] * EMB + e] + g_semb[g_pre[bt] * EMB + e] + wpe[t * EMB + e];
}

// ---------------- weight convert (R15 vectorized) ----------------
__global__ __launch_bounds__(256) void wconv_kernel(
    const float* __restrict__ W, __half* __restrict__ Hi, int K, int N)
{
    __shared__ float t[64][33];
    int l = blockIdx.z;
    const float* Wl = W + (size_t)l * K * N;
    __half* Hl = Hi + (size_t)l * K * N;
    int n0 = blockIdx.x * 32, k0 = blockIdx.y * 64;
    int tid = threadIdx.x;
    int lk = tid >> 5, ln_ = tid & 31;
#pragma unroll
    for (int i = 0; i < 8; i++)
        t[lk + 8 * i][ln_] = Wl[(size_t)(k0 + lk + 8 * i) * N + n0 + ln_];
    __syncthreads();
    int n = tid >> 3, g = tid & 7;
    __half hv[8];
#pragma unroll
    for (int j = 0; j < 8; j++)
        hv[j] = __float2half_rn(t[g * 8 + j][n]);
    *reinterpret_cast<uint4*>(Hl + (size_t)(n0 + n) * K + k0 + g * 8)
        = *reinterpret_cast<uint4*>(hv);
}

// ---------------- warp-per-row layernorm variants ----------------
// block = 8 warps = 8 rows; lane holds 24 elems (6 x float4); shuffle-only.
__global__ __launch_bounds__(256) void ln_kernel(const float* __restrict__ x,
                                                 const float* __restrict__ g,
                                                 const float* __restrict__ b,
                                                 float* __restrict__ y) {
    int row = blockIdx.x * 8 + (threadIdx.x >> 5);
    int lane = threadIdx.x & 31;
    const float* xr = x + (size_t)row * EMB;
    float4 v[6];
    float s = 0.f;
#pragma unroll
    for (int i = 0; i < 6; i++) {
        v[i] = *reinterpret_cast<const float4*>(xr + i * 128 + lane * 4);
        s += (v[i].x + v[i].y) + (v[i].z + v[i].w);
    }
#pragma unroll
    for (int o = 16; o > 0; o >>= 1) s += __shfl_xor_sync(0xffffffffu, s, o);
    float mean = s * (1.f / EMB);
    float q = 0.f;
#pragma unroll
    for (int i = 0; i < 6; i++) {
        v[i].x -= mean; v[i].y -= mean; v[i].z -= mean; v[i].w -= mean;
        q += (v[i].x * v[i].x + v[i].y * v[i].y)
           + (v[i].z * v[i].z + v[i].w * v[i].w);
    }
#pragma unroll
    for (int o = 16; o > 0; o >>= 1) q += __shfl_xor_sync(0xffffffffu, q, o);
    float rstd = rsqrtf(q * (1.f / EMB) + 1e-5f);
    float* yr = y + (size_t)row * EMB;
#pragma unroll
    for (int i = 0; i < 6; i++) {
        int e = i * 128 + lane * 4;
        float4 gg = *reinterpret_cast<const float4*>(g + e);
        float4 bb = *reinterpret_cast<const float4*>(b + e);
        float4 o;
        o.x = v[i].x * rstd * gg.x + bb.x;
        o.y = v[i].y * rstd * gg.y + bb.y;
        o.z = v[i].z * rstd * gg.z + bb.z;
        o.w = v[i].w * rstd * gg.w + bb.w;
        *reinterpret_cast<float4*>(yr + e) = o;
    }
}

__global__ __launch_bounds__(256) void ln_f16_kernel(const float* __restrict__ x,
                                                     const float* __restrict__ g,
                                                     const float* __restrict__ b,
                                                     __half* __restrict__ yh,
                                                     __half* __restrict__ yl) {
    int row = blockIdx.x * 8 + (threadIdx.x >> 5);
    int lane = threadIdx.x & 31;
    const float* xr = x + (size_t)row * EMB;
    float4 v[6];
    float s = 0.f;
#pragma unroll
    for (int i = 0; i < 6; i++) {
        v[i] = *reinterpret_cast<const float4*>(xr + i * 128 + lane * 4);
        s += (v[i].x + v[i].y) + (v[i].z + v[i].w);
    }
#pragma unroll
    for (int o = 16; o > 0; o >>= 1) s += __shfl_xor_sync(0xffffffffu, s, o);
    float mean = s * (1.f / EMB);
    float q = 0.f;
#pragma unroll
    for (int i = 0; i < 6; i++) {
        v[i].x -= mean; v[i].y -= mean; v[i].z -= mean; v[i].w -= mean;
        q += (v[i].x * v[i].x + v[i].y * v[i].y)
           + (v[i].z * v[i].z + v[i].w * v[i].w);
    }
#pragma unroll
    for (int o = 16; o > 0; o >>= 1) q += __shfl_xor_sync(0xffffffffu, q, o);
    float rstd = rsqrtf(q * (1.f / EMB) + 1e-5f);
    size_t base = (size_t)row * EMB;
#pragma unroll
    for (int i = 0; i < 6; i++) {
        int e = i * 128 + lane * 4;
        float4 gg = *reinterpret_cast<const float4*>(g + e);
        float4 bb = *reinterpret_cast<const float4*>(b + e);
        float o0 = v[i].x * rstd * gg.x + bb.x;
        float o1 = v[i].y * rstd * gg.y + bb.y;
        float o2 = v[i].z * rstd * gg.z + bb.z;
        float o3 = v[i].w * rstd * gg.w + bb.w;
        uint32_t h01, l01, h23, l23;
        cvt_split2h(o0, o1, h01, l01);
        cvt_split2h(o2, o3, h23, l23);
        uint2 hv = make_uint2(h01, h23);
        uint2 lv = make_uint2(l01, l23);
        *reinterpret_cast<uint2*>(yh + base + e) = hv;
        *reinterpret_cast<uint2*>(yl + base + e) = lv;
    }
}

// ================= mma.sync fp16 2-term GEMM (3-deep ring, R12 proven) =====
__device__ __forceinline__ float gelu_f(float x) {
    return 0.5f * x * (1.f + tanhf(0.7978845608028654f * (x + 0.044715f * x * x * x)));
}

#define ROWB 80
#define SM_AH 0
#define SM_AL 10240
#define SM_BH 20480
#define BUFSZ 25600
#define GEMM_SMEM (3*BUFSZ)   // 76800/CTA

template<int EPI>
__global__ __launch_bounds__(256, 2) void mma_gemm(
    const __half* __restrict__ Ah, const __half* __restrict__ Al,
    const __half* __restrict__ Bh,
    const float* __restrict__ bias,
    const float* __restrict__ Res,
    float* __restrict__ C,
    __half* __restrict__ Ch, __half* __restrict__ Cl,
    __half* __restrict__ Vh, __half* __restrict__ Vl,
    int K, int N)
{
    extern __shared__ __align__(16) char sm[];
    uint32_t sb = smem_u32(sm);
    int tid = threadIdx.x;
    int wid = tid >> 5, lane = tid & 31;
    int wm = wid & 3, wn = wid >> 2;
    int m0 = blockIdx.y * 128, n0 = blockIdx.x * 64;

    int p_row = tid >> 2;
    int p_seg = tid & 3;

    int a_row = lane & 15;
    int a_colb = ((lane >> 4) * 8) * 2;
    int b_row = (lane & 7) + ((lane >> 4) & 1) * 8;
    int b_colb = (((lane >> 3) & 1) * 8) * 2;

    float acc[2][4][4];
#pragma unroll
    for (int i = 0; i < 2; i++)
#pragma unroll
        for (int j = 0; j < 4; j++)
#pragma unroll
            for (int q = 0; q < 4; q++) acc[i][j][q] = 0.f;

    const int nch = K >> 5;

    auto issue = [&](int c, int bufsel) {
        int k0 = c << 5;
        uint32_t base = sb + bufsel * BUFSZ;
        uint32_t doff = (uint32_t)(p_row * ROWB + p_seg * 16);
#pragma unroll
        for (int i = 0; i < 2; i++) {
            int row = p_row + i * 64;
            size_t aoff = (size_t)(m0 + row) * K + k0 + p_seg * 8;
            cp16(base + SM_AH + doff + i * (64 * ROWB), Ah + aoff);
            cp16(base + SM_AL + doff + i * (64 * ROWB), Al + aoff);
        }
        size_t boff = (size_t)(n0 + p_row) * K + k0 + p_seg * 8;
        cp16(base + SM_BH + doff, Bh + boff);
    };

    issue(0, 0);
    CP_COMMIT();

    int curb = 0, nxtb = 1;
    for (int c = 0; c < nch; c++) {
        if (c + 1 < nch) {
            issue(c + 1, nxtb);
            CP_COMMIT();
            CP_WAIT(1);
        } else {
            CP_WAIT(0);
        }
        __syncthreads();

        uint32_t base = sb + curb * BUFSZ;
#pragma unroll
        for (int ks = 0; ks < 2; ks++) {
            uint32_t a_hi[2][4], a_lo[2][4];
#pragma unroll
            for (int mt = 0; mt < 2; mt++) {
                uint32_t off = (uint32_t)((wm * 32 + mt * 16 + a_row) * ROWB
                                          + ks * 32 + a_colb);
                ldsm_x4(a_hi[mt], base + SM_AH + off);
                ldsm_x4(a_lo[mt], base + SM_AL + off);
            }
            uint32_t b_hi[2][4];
#pragma unroll
            for (int p = 0; p < 2; p++) {
                uint32_t off = (uint32_t)((wn * 32 + p * 16 + b_row) * ROWB
                                          + ks * 32 + b_colb);
                ldsm_x4(b_hi[p], base + SM_BH + off);
            }
#pragma unroll
            for (int mt = 0; mt < 2; mt++)
#pragma unroll
                for (int p = 0; p < 2; p++) {
                    mma_f16(acc[mt][2*p],   a_hi[mt], &b_hi[p][0]);
                    mma_f16(acc[mt][2*p+1], a_hi[mt], &b_hi[p][2]);
                }
#pragma unroll
            for (int mt = 0; mt < 2; mt++)
#pragma unroll
                for (int p = 0; p < 2; p++) {
                    mma_f16(acc[mt][2*p],   a_lo[mt], &b_hi[p][0]);
                    mma_f16(acc[mt][2*p+1], a_lo[mt], &b_hi[p][2]);
                }
        }
        curb = nxtb;
        nxtb = (nxtb == 2) ? 0 : nxtb + 1;
    }

    int r0 = m0 + wm * 32 + (lane >> 2);
    int c0 = n0 + wn * 32 + (lane & 3) * 2;
#pragma unroll
    for (int mt = 0; mt < 2; mt++) {
#pragma unroll
        for (int nt = 0; nt < 4; nt++) {
            int r = r0 + mt * 16;
            int cc = c0 + nt * 8;
            float b0 = bias[cc], b1 = bias[cc + 1];
            float v0 = acc[mt][nt][0] + b0;
            float v1 = acc[mt][nt][1] + b1;
            float v2 = acc[mt][nt][2] + b0;
            float v3 = acc[mt][nt][3] + b1;
            if (EPI == 2) {
                v0 = gelu_f(v0); v1 = gelu_f(v1);
                v2 = gelu_f(v2); v3 = gelu_f(v3);
                uint32_t h01, l01, h23, l23;
                cvt_split2h(v0, v1, h01, l01);
                cvt_split2h(v2, v3, h23, l23);
                *(uint32_t*)(Ch + (size_t)r * N + cc) = h01;
                *(uint32_t*)(Cl + (size_t)r * N + cc) = l01;
                *(uint32_t*)(Ch + (size_t)(r + 8) * N + cc) = h23;
                *(uint32_t*)(Cl + (size_t)(r + 8) * N + cc) = l23;
            } else if (EPI == 3) {
                if (cc < 1536) {
                    int kk = (cc >= 768);
                    size_t idx = (size_t)kk * (BT * EMB)
                               + (size_t)r * EMB + (cc - kk * 768);
                    uint32_t h01, l01, h23, l23;
                    cvt_split2h(v0, v1, h01, l01);
                    cvt_split2h(v2, v3, h23, l23);
                    *(uint32_t*)(Ch + idx) = h01;
                    *(uint32_t*)(Cl + idx) = l01;
                    *(uint32_t*)(Ch + idx + (size_t)8 * EMB) = h23;
                    *(uint32_t*)(Cl + idx + (size_t)8 * EMB) = l23;
                } else {
                    int b = r >> 9, s = r & 511;
                    int hd = cc - 1536;
                    int hh_ = hd >> 6, d = hd & 63;
                    size_t idx = ((size_t)(b * NH + hh_) * 64 + d) * 512 + s;
                    __half a0 = __float2half_rn(v0);
                    Vh[idx] = a0;
                    Vl[idx] = __float2half_rn(v0 - __half2float(a0));
                    __half a1 = __float2half_rn(v1);
                    Vh[idx + 512] = a1;
                    Vl[idx + 512] = __float2half_rn(v1 - __half2float(a1));
                    __half a2 = __float2half_rn(v2);
                    Vh[idx + 8] = a2;
                    Vl[idx + 8] = __float2half_rn(v2 - __half2float(a2));
                    __half a3 = __float2half_rn(v3);
                    Vh[idx + 512 + 8] = a3;
                    Vl[idx + 512 + 8] = __float2half_rn(v3 - __half2float(a3));
                }
            } else {
                if (EPI == 1) {
                    const float* rp0 = Res + (size_t)r * N + cc;
                    const float* rp1 = Res + (size_t)(r + 8) * N + cc;
                    v0 += rp0[0]; v1 += rp0[1];
                    v2 += rp1[0]; v3 += rp1[1];
                }
                *reinterpret_cast<float2*>(C + (size_t)r * N + cc) = make_float2(v0, v1);
                *reinterpret_cast<float2*>(C + (size_t)(r + 8) * N + cc) = make_float2(v2, v3);
            }
        }
    }
}

// ================= tensor-core causal flash attention ======================
#define FROWB 144
#define FT_QH 0
#define FT_QL (128*FROWB)
#define FT_KV0 (2*128*FROWB)
#define KV_KH 0
#define KV_KL (64*FROWB)
#define KV_VH (2*64*FROWB)
#define KV_VL (3*64*FROWB)
#define KVBUF (4*64*FROWB)
#define FT_SMEM (FT_KV0 + 2*KVBUF)   // 110592

__global__ __launch_bounds__(256, 2) void flash_tc_kernel() {
    extern __shared__ __align__(16) char fsm[];
    uint32_t sb = smem_u32(fsm);
    int bh = blockIdx.y;
    int b = bh / NH, h = bh % NH;
    int t0 = blockIdx.x * 128;
    int tid = threadIdx.x;
    int wid = tid >> 5, lane = tid & 31;

    const __half* Kh = g_qkh + (size_t)BT * EMB;
    const __half* Kl = g_qkl + (size_t)BT * EMB;

    int a_row = lane & 15;
    int a_colb = ((lane >> 4) * 8) * 2;
    int b_row = (lane & 7) + ((lane >> 4) & 1) * 8;
    int b_colb = (((lane >> 3) & 1) * 8) * 2;

    auto kv_issue = [&](int j, int buf) {
        int s = tid >> 2, seg = tid & 3;
        uint32_t base = sb + FT_KV0 + buf * KVBUF;
        size_t koff = (size_t)(b * SEQ + j * 64 + s) * EMB + h * DH + seg * 16;
        uint32_t kdh = base + KV_KH + s * FROWB + seg * 32;
        uint32_t kdl = base + KV_KL + s * FROWB + seg * 32;
        cp16(kdh,      Kh + koff);
        cp16(kdh + 16, Kh + koff + 8);
        cp16(kdl,      Kl + koff);
        cp16(kdl + 16, Kl + koff + 8);
        size_t voff = ((size_t)bh * 64 + s) * 512 + j * 64 + seg * 16;
        uint32_t vdh = base + KV_VH + s * FROWB + seg * 32;
        uint32_t vdl = base + KV_VL + s * FROWB + seg * 32;
        cp16(vdh,      g_vth + voff);
        cp16(vdh + 16, g_vth + voff + 8);
        cp16(vdl,      g_vtl + voff);
        cp16(vdl + 16, g_vtl + voff + 8);
    };

    {
        int row = tid >> 1, hf = tid & 1;
        size_t qoff = (size_t)(b * SEQ + t0 + row) * EMB + h * DH + hf * 32;
        uint32_t dh_ = sb + FT_QH + row * FROWB + hf * 64;
        uint32_t dl_ = sb + FT_QL + row * FROWB + hf * 64;
#pragma unroll
        for (int i = 0; i < 4; i++) {
            cp16(dh_ + 16 * i, g_qkh + qoff + 8 * i);
            cp16(dl_ + 16 * i, g_qkl + qoff + 8 * i);
        }
    }
    kv_issue(0, 0);
    CP_COMMIT();
    CP_WAIT(0);
    __syncthreads();

    float m0 = -1e30f, m1 = -1e30f, l0 = 0.f, l1 = 0.f;
    float O[8][4];
#pragma unroll
    for (int f = 0; f < 8; f++)
#pragma unroll
        for (int q = 0; q < 4; q++) O[f][q] = 0.f;

    int t_r0 = t0 + wid * 16 + (lane >> 2);
    int ntile = (t0 >> 6) + 2;

    for (int j = 0; j < ntile; j++) {
        int cur = j & 1;
        if (j + 1 < ntile) {
            kv_issue(j + 1, cur ^ 1);
            CP_COMMIT();
        }
        uint32_t kvb = sb + FT_KV0 + cur * KVBUF;

        float S[8][4];
#pragma unroll
        for (int f = 0; f < 8; f++)
#pragma unroll
            for (int q = 0; q < 4; q++) S[f][q] = 0.f;
#pragma unroll
        for (int ks = 0; ks < 4; ks++) {
            uint32_t aq_h[4], aq_l[4];
            uint32_t aoff = (uint32_t)((wid * 16 + a_row) * FROWB + ks * 32 + a_colb);
            ldsm_x4(aq_h, sb + FT_QH + aoff);
            ldsm_x4(aq_l, sb + FT_QL + aoff);
#pragma unroll
            for (int p = 0; p < 4; p++) {
                uint32_t bk_h[4], bk_l[4];
                uint32_t boff = (uint32_t)((p * 16 + b_row) * FROWB + ks * 32 + b_colb);
                ldsm_x4(bk_h, kvb + KV_KH + boff);
                ldsm_x4(bk_l, kvb + KV_KL + boff);
                mma_f16(S[2*p],   aq_h, &bk_h[0]);
                mma_f16(S[2*p+1], aq_h, &bk_h[2]);
                mma_f16(S[2*p],   aq_l, &bk_h[0]);
                mma_f16(S[2*p+1], aq_l, &bk_h[2]);
                mma_f16(S[2*p],   aq_h, &bk_l[0]);
                mma_f16(S[2*p+1], aq_h, &bk_l[2]);
            }
        }

#pragma unroll
        for (int f = 0; f < 8; f++) {
            int c = j * 64 + (f >> 1) * 16 + (f & 1) * 8 + (lane & 3) * 2;
#pragma unroll
            for (int q = 0; q < 4; q++) S[f][q] *= 0.125f;
            if (c     > t_r0) S[f][0] = -1e30f;
            if (c + 1 > t_r0) S[f][1] = -1e30f;
            if (c     > t_r0 + 8) S[f][2] = -1e30f;
            if (c + 1 > t_r0 + 8) S[f][3] = -1e30f;
        }

        float mx0 = -1e30f, mx1 = -1e30f;
#pragma unroll
        for (int f = 0; f < 8; f++) {
            mx0 = fmaxf(mx0, fmaxf(S[f][0], S[f][1]));
            mx1 = fmaxf(mx1, fmaxf(S[f][2], S[f][3]));
        }
        mx0 = fmaxf(mx0, __shfl_xor_sync(0xffffffffu, mx0, 1));
        mx0 = fmaxf(mx0, __shfl_xor_sync(0xffffffffu, mx0, 2));
        mx1 = fmaxf(mx1, __shfl_xor_sync(0xffffffffu, mx1, 1));
        mx1 = fmaxf(mx1, __shfl_xor_sync(0xffffffffu, mx1, 2));
        float mn0 = fmaxf(m0, mx0), mn1 = fmaxf(m1, mx1);
        float c0 = __expf(m0 - mn0), c1 = __expf(m1 - mn1);
        m0 = mn0; m1 = mn1;
        float rs0 = 0.f, rs1 = 0.f;
#pragma unroll
        for (int f = 0; f < 8; f++) {
            S[f][0] = __expf(S[f][0] - mn0);
            S[f][1] = __expf(S[f][1] - mn0);
            S[f][2] = __expf(S[f][2] - mn1);
            S[f][3] = __expf(S[f][3] - mn1);
            rs0 += S[f][0] + S[f][1];
            rs1 += S[f][2] + S[f][3];
        }
        rs0 += __shfl_xor_sync(0xffffffffu, rs0, 1);
        rs0 += __shfl_xor_sync(0xffffffffu, rs0, 2);
        rs1 += __shfl_xor_sync(0xffffffffu, rs1, 1);
        rs1 += __shfl_xor_sync(0xffffffffu, rs1, 2);
        l0 = l0 * c0 + rs0;
        l1 = l1 * c1 + rs1;
#pragma unroll
        for (int f = 0; f < 8; f++) {
            O[f][0] *= c0; O[f][1] *= c0;
            O[f][2] *= c1; O[f][3] *= c1;
        }

#pragma unroll
        for (int g = 0; g < 4; g++) {
            uint32_t pa[4];
            __half2 p0 = __floats2half2_rn(S[2*g][0],   S[2*g][1]);
            __half2 p1 = __floats2half2_rn(S[2*g][2],   S[2*g][3]);
            __half2 p2 = __floats2half2_rn(S[2*g+1][0], S[2*g+1][1]);
            __half2 p3 = __floats2half2_rn(S[2*g+1][2], S[2*g+1][3]);
            pa[0] = *(uint32_t*)&p0;
            pa[1] = *(uint32_t*)&p1;
            pa[2] = *(uint32_t*)&p2;
            pa[3] = *(uint32_t*)&p3;
#pragma unroll
            for (int p = 0; p < 4; p++) {
                uint32_t bv_h[4], bv_l[4];
                uint32_t boff = (uint32_t)((p * 16 + b_row) * FROWB + g * 32 + b_colb);
                ldsm_x4(bv_h, kvb + KV_VH + boff);
                ldsm_x4(bv_l, kvb + KV_VL + boff);
                mma_f16(O[2*p],   pa, &bv_h[0]);
                mma_f16(O[2*p+1], pa, &bv_h[2]);
                mma_f16(O[2*p],   pa, &bv_l[0]);
                mma_f16(O[2*p+1], pa, &bv_l[2]);
            }
        }

        if (j + 1 < ntile) {
            CP_WAIT(0);
        }
        __syncthreads();
    }

    float inv0 = 1.f / l0, inv1 = 1.f / l1;
#pragma unroll
    for (int f = 0; f < 8; f++) {
        int d = (f >> 1) * 16 + (f & 1) * 8 + (lane & 3) * 2;
        size_t base0 = (size_t)(b * SEQ + t_r0) * EMB + h * DH + d;
        size_t base1 = (size_t)(b * SEQ + t_r0 + 8) * EMB + h * DH + d;
        uint32_t hh, ll;
        cvt_split2h(O[f][0] * inv0, O[f][1] * inv0, hh, ll);
        *(uint32_t*)(g_atth + base0) = hh;
        *(uint32_t*)(g_attl + base0) = ll;
        cvt_split2h(O[f][2] * inv1, O[f][3] * inv1, hh, ll);
        *(uint32_t*)(g_atth + base1) = hh;
        *(uint32_t*)(g_attl + base1) = ll;
    }
}

// ---------------- head GEMM (N=60, FFMA) ----------------
__global__ __launch_bounds__(256) void head_gemm_kernel(
    const float* __restrict__ A,
    const float* __restrict__ Bm,
    const float* __restrict__ bias,
    float* __restrict__ C,
    int N, int K)
{
    __shared__ float As[16][68];
    __shared__ float Bs[16][64];
    int m0 = blockIdx.y * 64, n0 = blockIdx.x * 64;
    int tid = threadIdx.x;
    int tx = tid & 15, ty = tid >> 4;
    float acc[4][4] = {};
    for (int k0 = 0; k0 < K; k0 += 16) {
#pragma unroll
        for (int i = 0; i < 4; i++) {
            int lin = tid + i * 256;
            int r = lin >> 4, c = lin & 15;
            As[c][r] = A[(size_t)(m0 + r) * K + k0 + c];
        }
#pragma unroll
        for (int i = 0; i < 4; i++) {
            int lin = tid + i * 256;
            int r = lin >> 6, c = lin & 63;
            int n = n0 + c;
            Bs[r][c] = (n < N) ? Bm[(size_t)(k0 + r) * N + n] : 0.f;
        }
        __syncthreads();
#pragma unroll
        for (int kk = 0; kk < 16; kk++) {
            float4 a4 = *reinterpret_cast<const float4*>(&As[kk][ty * 4]);
            float4 b4 = *reinterpret_cast<const float4*>(&Bs[kk][tx * 4]);
            float a[4] = {a4.x, a4.y, a4.z, a4.w};
            float bv[4] = {b4.x, b4.y, b4.z, b4.w};
#pragma unroll
            for (int i = 0; i < 4; i++)
#pragma unroll
                for (int j = 0; j < 4; j++)
                    acc[i][j] = fmaf(a[i], bv[j], acc[i][j]);
        }
        __syncthreads();
    }
#pragma unroll
    for (int i = 0; i < 4; i++) {
        int m = m0 + ty * 4 + i;
#pragma unroll
        for (int j = 0; j < 4; j++) {
            int n = n0 + tx * 4 + j;
            if (n < N) C[(size_t)m * N + n] = acc[i][j] + bias[n];
        }
    }
}

// ---------------- host orchestration ----------------
extern "C" void kernel_launch(void* const* d_in, const int* in_sizes, int n_in,
                              void* d_out, int out_size) {
    const int*   ids          = (const int*)d_in[0];
    const int*   mul          = (const int*)d_in[1];
    const float* tok_emb      = (const float*)d_in[2];
    const float* state_emb    = (const float*)d_in[3];
    const float* state_proj_w = (const float*)d_in[4];
    const float* state_proj_b = (const float*)d_in[5];
    const float* wpe          = (const float*)d_in[6];
    const float* ln1_g        = (const float*)d_in[7];
    const float* ln1_b        = (const float*)d_in[8];
    const float* attn_w       = (const float*)d_in[9];
    const float* attn_b       = (const float*)d_in[10];
    const float* attn_proj_w  = (const float*)d_in[11];
    const float* attn_proj_b  = (const float*)d_in[12];
    const float* ln2_g        = (const float*)d_in[13];
    const float* ln2_b        = (const float*)d_in[14];
    const float* fc_w         = (const float*)d_in[15];
    const float* fc_b         = (const float*)d_in[16];
    const float* mlp_proj_w   = (const float*)d_in[17];
    const float* mlp_proj_b   = (const float*)d_in[18];
    const float* lnf_g        = (const float*)d_in[19];
    const float* lnf_b        = (const float*)d_in[20];
    const float* head_w       = (const float*)d_in[21];
    const float* head_b       = (const float*)d_in[22];
    float* out = (float*)d_out;

    float *h, *lnbuf;
    __half *wh, *lnh, *lnl, *atth, *attl, *midh, *midl, *qkh, *qkl, *vth, *vtl;
    cudaGetSymbolAddress((void**)&h,     g_h);
    cudaGetSymbolAddress((void**)&lnbuf, g_ln);
    cudaGetSymbolAddress((void**)&wh,    g_wh);
    cudaGetSymbolAddress((void**)&lnh,   g_lnh);
    cudaGetSymbolAddress((void**)&lnl,   g_lnl);
    cudaGetSymbolAddress((void**)&atth,  g_atth);
    cudaGetSymbolAddress((void**)&attl,  g_attl);
    cudaGetSymbolAddress((void**)&midh,  g_midh);
    cudaGetSymbolAddress((void**)&midl,  g_midl);
    cudaGetSymbolAddress((void**)&qkh,   g_qkh);
    cudaGetSymbolAddress((void**)&qkl,   g_qkl);
    cudaGetSymbolAddress((void**)&vth,   g_vth);
    cudaGetSymbolAddress((void**)&vtl,   g_vtl);

    cudaFuncSetAttribute(mma_gemm<1>, cudaFuncAttributeMaxDynamicSharedMemorySize, GEMM_SMEM);
    cudaFuncSetAttribute(mma_gemm<2>, cudaFuncAttributeMaxDynamicSharedMemorySize, GEMM_SMEM);
    cudaFuncSetAttribute(mma_gemm<3>, cudaFuncAttributeMaxDynamicSharedMemorySize, GEMM_SMEM);
    cudaFuncSetAttribute(flash_tc_kernel, cudaFuncAttributeMaxDynamicSharedMemorySize, FT_SMEM);

    wconv_kernel<<<dim3(QKVN/32, EMB/64, NLAYER), 256>>>(attn_w, wh + OFF_QKV, EMB, QKVN);
    wconv_kernel<<<dim3(EMB/32, EMB/64, NLAYER), 256>>>(attn_proj_w, wh + OFF_PROJ, EMB, EMB);
    wconv_kernel<<<dim3(FFN/32, EMB/64, NLAYER), 256>>>(fc_w, wh + OFF_FC, EMB, FFN);
    wconv_kernel<<<dim3(EMB/32, FFN/64, NLAYER), 256>>>(mlp_proj_w, wh + OFF_MLP, FFN, EMB);

    state_scan_kernel<<<1, 256>>>(ids, mul);
    state_proj_kernel<<<(VOC * EMB + 255) / 256, 256>>>(state_emb, state_proj_w, state_proj_b);
    embed_kernel<<<(BT * EMB + 255) / 256, 256>>>(ids, tok_emb, wpe);

    for (int l = 0; l < NLAYER; l++) {
        ln_f16_kernel<<<BT/8, 256>>>(h, ln1_g + l * EMB, ln1_b + l * EMB, lnh, lnl);
        mma_gemm<3><<<dim3(QKVN/64, BT/128), 256, GEMM_SMEM>>>(
            lnh, lnl, wh + OFF_QKV + (size_t)l * W_QKV,
            attn_b + l * QKVN, nullptr, nullptr, qkh, qkl, vth, vtl, EMB, QKVN);
        flash_tc_kernel<<<dim3(SEQ/128, BATCH * NH), 256, FT_SMEM>>>();
        mma_gemm<1><<<dim3(EMB/64, BT/128), 256, GEMM_SMEM>>>(
            atth, attl, wh + OFF_PROJ + (size_t)l * W_PROJ,
            attn_proj_b + l * EMB, h, h, nullptr, nullptr, nullptr, nullptr, EMB, EMB);
        ln_f16_kernel<<<BT/8, 256>>>(h, ln2_g + l * EMB, ln2_b + l * EMB, lnh, lnl);
        mma_gemm<2><<<dim3(FFN/64, BT/128), 256, GEMM_SMEM>>>(
            lnh, lnl, wh + OFF_FC + (size_t)l * W_FC,
            fc_b + l * FFN, nullptr, nullptr, midh, midl, nullptr, nullptr, EMB, FFN);
        mma_gemm<1><<<dim3(EMB/64, BT/128), 256, GEMM_SMEM>>>(
            midh, midl, wh + OFF_MLP + (size_t)l * W_MLP,
            mlp_proj_b + l * EMB, h, h, nullptr, nullptr, nullptr, nullptr, FFN, EMB);
    }

    ln_kernel<<<BT/8, 256>>>(h, lnf_g, lnf_b, lnbuf);
    head_gemm_kernel<<<dim3(1, BT / 64), 256>>>(lnbuf, head_w, head_b, out, VOC, EMB);
}

// round 17
// speedup vs baseline: 1.2707x; 1.0433x over previous
#include <cuda_runtime.h>
#include <cuda_fp16.h>
#include <math.h>
#include <stdint.h>

#define BATCH 8
#define SEQ 512
#define BT (BATCH*SEQ)        // 4096
#define EMB 768
#define NH 12
#define DH 64
#define VOC 60
#define DST 128
#define NLAYER 12
#define QKVN (3*EMB)          // 2304
#define FFN (4*EMB)           // 3072

#define W_QKV (QKVN*EMB)
#define W_PROJ (EMB*EMB)
#define W_FC (FFN*EMB)
#define W_MLP (EMB*FFN)
#define OFF_QKV 0
#define OFF_PROJ (12*W_QKV)
#define OFF_FC (OFF_PROJ + 12*W_PROJ)
#define OFF_MLP (OFF_FC + 12*W_FC)
#define W_TOTAL (OFF_MLP + 12*W_MLP)

// ---------------- scratch ----------------
__device__ float g_h[BT*EMB];
__device__ float g_ln[BT*EMB];
__device__ float g_semb[VOC*EMB];
__device__ int   g_pre[BT];

__device__ __half g_wh[W_TOTAL];                 // weights, single fp16, [N][K]
__device__ __half g_lnh[BT*EMB],  g_lnl[BT*EMB]; // activations, fp16 hi/lo
__device__ __half g_atth[BT*EMB], g_attl[BT*EMB];
__device__ __half g_midh[BT*FFN], g_midl[BT*FFN];
__device__ __half g_qkh[2*BT*EMB], g_qkl[2*BT*EMB];   // Q then K, row-major
__device__ __half g_vth[BATCH*NH*DH*SEQ], g_vtl[BATCH*NH*DH*SEQ]; // V^T [bh][d][s]

// ---------------- helpers ----------------
__device__ __forceinline__ uint32_t smem_u32(const void* p) {
    uint32_t a;
    asm("{ .reg .u64 t; cvta.to.shared.u64 t, %1; cvt.u32.u64 %0, t; }" : "=r"(a) : "l"(p));
    return a;
}

__device__ __forceinline__ void ldsm_x4(uint32_t* r, uint32_t addr) {
    asm volatile("ldmatrix.sync.aligned.m8n8.x4.shared.b16 {%0,%1,%2,%3}, [%4];"
        : "=r"(r[0]), "=r"(r[1]), "=r"(r[2]), "=r"(r[3]) : "r"(addr));
}

__device__ __forceinline__ void mma_f16(float* c, const uint32_t* a, const uint32_t* b) {
    asm volatile("mma.sync.aligned.m16n8k16.row.col.f32.f16.f16.f32 "
        "{%0,%1,%2,%3}, {%4,%5,%6,%7}, {%8,%9}, {%0,%1,%2,%3};"
        : "+f"(c[0]), "+f"(c[1]), "+f"(c[2]), "+f"(c[3])
        : "r"(a[0]), "r"(a[1]), "r"(a[2]), "r"(a[3]), "r"(b[0]), "r"(b[1]));
}

__device__ __forceinline__ void cp16(uint32_t dst, const void* src) {
    asm volatile("cp.async.cg.shared.global [%0], [%1], 16;" :: "r"(dst), "l"(src));
}
#define CP_COMMIT() asm volatile("cp.async.commit_group;" ::: "memory")
#define CP_WAIT(n)  asm volatile("cp.async.wait_group %0;" :: "n"(n) : "memory")

__device__ __forceinline__ void cvt_split2h(float x0, float x1, uint32_t& hi, uint32_t& lo) {
    __half h0 = __float2half_rn(x0);
    __half h1 = __float2half_rn(x1);
    __half l0 = __float2half_rn(x0 - __half2float(h0));
    __half l1 = __float2half_rn(x1 - __half2float(h1));
    __half2 H(h0, h1), L(l0, l1);
    hi = *(uint32_t*)&H;
    lo = *(uint32_t*)&L;
}

// ---------------- automaton state scan ----------------
__global__ void state_scan_kernel(const int* __restrict__ ids, const int* __restrict__ mul) {
    __shared__ int smul[VOC*VOC];
    __shared__ int sids[BT];
    int tid = threadIdx.x;
    for (int i = tid; i < VOC*VOC; i += blockDim.x) smul[i] = mul[i];
    for (int i = tid; i < BT; i += blockDim.x) sids[i] = ids[i];
    __syncthreads();
    if (tid < BATCH) {
        int s = 0;
        const int* row = sids + tid * SEQ;
        int* pre = g_pre + tid * SEQ;
        for (int t = 0; t < SEQ; t++) {
            pre[t] = s;
            s = smul[row[t] * VOC + s];
        }
    }
}

__global__ void state_proj_kernel(const float* __restrict__ semb,
                                  const float* __restrict__ W,
                                  const float* __restrict__ b) {
    int idx = blockIdx.x * blockDim.x + threadIdx.x;
    if (idx >= VOC * EMB) return;
    int v = idx / EMB, e = idx % EMB;
    float acc = b[e];
#pragma unroll 8
    for (int d = 0; d < DST; d++) acc += semb[v * DST + d] * W[d * EMB + e];
    g_semb[idx] = acc;
}

__global__ void embed_kernel(const int* __restrict__ ids,
                             const float* __restrict__ tok_emb,
                             const float* __restrict__ wpe) {
    int idx = blockIdx.x * blockDim.x + threadIdx.x;
    if (idx >= BT * EMB) return;
    int bt = idx / EMB, e = idx % EMB;
    int t = bt % SEQ;
    g_h[idx] = tok_emb[ids[bt] * EMB + e] + g_semb[g_pre[bt] * EMB + e] + wpe[t * EMB + e];
}

// ---------------- weight convert (R15 vectorized) ----------------
__global__ __launch_bounds__(256) void wconv_kernel(
    const float* __restrict__ W, __half* __restrict__ Hi, int K, int N)
{
    __shared__ float t[64][33];
    int l = blockIdx.z;
    const float* Wl = W + (size_t)l * K * N;
    __half* Hl = Hi + (size_t)l * K * N;
    int n0 = blockIdx.x * 32, k0 = blockIdx.y * 64;
    int tid = threadIdx.x;
    int lk = tid >> 5, ln_ = tid & 31;
#pragma unroll
    for (int i = 0; i < 8; i++)
        t[lk + 8 * i][ln_] = Wl[(size_t)(k0 + lk + 8 * i) * N + n0 + ln_];
    __syncthreads();
    int n = tid >> 3, g = tid & 7;
    __half hv[8];
#pragma unroll
    for (int j = 0; j < 8; j++)
        hv[j] = __float2half_rn(t[g * 8 + j][n]);
    *reinterpret_cast<uint4*>(Hl + (size_t)(n0 + n) * K + k0 + g * 8)
        = *reinterpret_cast<uint4*>(hv);
}

// ---------------- warp-per-row layernorm variants (R16) ----------------
__global__ __launch_bounds__(256) void ln_kernel(const float* __restrict__ x,
                                                 const float* __restrict__ g,
                                                 const float* __restrict__ b,
                                                 float* __restrict__ y) {
    int row = blockIdx.x * 8 + (threadIdx.x >> 5);
    int lane = threadIdx.x & 31;
    const float* xr = x + (size_t)row * EMB;
    float4 v[6];
    float s = 0.f;
#pragma unroll
    for (int i = 0; i < 6; i++) {
        v[i] = *reinterpret_cast<const float4*>(xr + i * 128 + lane * 4);
        s += (v[i].x + v[i].y) + (v[i].z + v[i].w);
    }
#pragma unroll
    for (int o = 16; o > 0; o >>= 1) s += __shfl_xor_sync(0xffffffffu, s, o);
    float mean = s * (1.f / EMB);
    float q = 0.f;
#pragma unroll
    for (int i = 0; i < 6; i++) {
        v[i].x -= mean; v[i].y -= mean; v[i].z -= mean; v[i].w -= mean;
        q += (v[i].x * v[i].x + v[i].y * v[i].y)
           + (v[i].z * v[i].z + v[i].w * v[i].w);
    }
#pragma unroll
    for (int o = 16; o > 0; o >>= 1) q += __shfl_xor_sync(0xffffffffu, q, o);
    float rstd = rsqrtf(q * (1.f / EMB) + 1e-5f);
    float* yr = y + (size_t)row * EMB;
#pragma unroll
    for (int i = 0; i < 6; i++) {
        int e = i * 128 + lane * 4;
        float4 gg = *reinterpret_cast<const float4*>(g + e);
        float4 bb = *reinterpret_cast<const float4*>(b + e);
        float4 o;
        o.x = v[i].x * rstd * gg.x + bb.x;
        o.y = v[i].y * rstd * gg.y + bb.y;
        o.z = v[i].z * rstd * gg.z + bb.z;
        o.w = v[i].w * rstd * gg.w + bb.w;
        *reinterpret_cast<float4*>(yr + e) = o;
    }
}

__global__ __launch_bounds__(256) void ln_f16_kernel(const float* __restrict__ x,
                                                     const float* __restrict__ g,
                                                     const float* __restrict__ b,
                                                     __half* __restrict__ yh,
                                                     __half* __restrict__ yl) {
    int row = blockIdx.x * 8 + (threadIdx.x >> 5);
    int lane = threadIdx.x & 31;
    const float* xr = x + (size_t)row * EMB;
    float4 v[6];
    float s = 0.f;
#pragma unroll
    for (int i = 0; i < 6; i++) {
        v[i] = *reinterpret_cast<const float4*>(xr + i * 128 + lane * 4);
        s += (v[i].x + v[i].y) + (v[i].z + v[i].w);
    }
#pragma unroll
    for (int o = 16; o > 0; o >>= 1) s += __shfl_xor_sync(0xffffffffu, s, o);
    float mean = s * (1.f / EMB);
    float q = 0.f;
#pragma unroll
    for (int i = 0; i < 6; i++) {
        v[i].x -= mean; v[i].y -= mean; v[i].z -= mean; v[i].w -= mean;
        q += (v[i].x * v[i].x + v[i].y * v[i].y)
           + (v[i].z * v[i].z + v[i].w * v[i].w);
    }
#pragma unroll
    for (int o = 16; o > 0; o >>= 1) q += __shfl_xor_sync(0xffffffffu, q, o);
    float rstd = rsqrtf(q * (1.f / EMB) + 1e-5f);
    size_t base = (size_t)row * EMB;
#pragma unroll
    for (int i = 0; i < 6; i++) {
        int e = i * 128 + lane * 4;
        float4 gg = *reinterpret_cast<const float4*>(g + e);
        float4 bb = *reinterpret_cast<const float4*>(b + e);
        float o0 = v[i].x * rstd * gg.x + bb.x;
        float o1 = v[i].y * rstd * gg.y + bb.y;
        float o2 = v[i].z * rstd * gg.z + bb.z;
        float o3 = v[i].w * rstd * gg.w + bb.w;
        uint32_t h01, l01, h23, l23;
        cvt_split2h(o0, o1, h01, l01);
        cvt_split2h(o2, o3, h23, l23);
        uint2 hv = make_uint2(h01, h23);
        uint2 lv = make_uint2(l01, l23);
        *reinterpret_cast<uint2*>(yh + base + e) = hv;
        *reinterpret_cast<uint2*>(yl + base + e) = lv;
    }
}

// ================= mma.sync fp16 2-term GEMM (3-deep ring, 3 CTAs/SM) ======
__device__ __forceinline__ float gelu_f(float x) {
    return 0.5f * x * (1.f + tanhf(0.7978845608028654f * (x + 0.044715f * x * x * x)));
}

#define ROWB 80
#define SM_AH 0
#define SM_AL 10240
#define SM_BH 20480
#define BUFSZ 25600
#define GEMM_SMEM (3*BUFSZ)   // 76800/CTA; x3 CTAs = 230400/SM

template<int EPI>
__global__ __launch_bounds__(256, 3) void mma_gemm(
    const __half* __restrict__ Ah, const __half* __restrict__ Al,
    const __half* __restrict__ Bh,
    const float* __restrict__ bias,
    const float* __restrict__ Res,
    float* __restrict__ C,
    __half* __restrict__ Ch, __half* __restrict__ Cl,
    __half* __restrict__ Vh, __half* __restrict__ Vl,
    int K, int N)
{
    extern __shared__ __align__(16) char sm[];
    uint32_t sb = smem_u32(sm);
    int tid = threadIdx.x;
    int wid = tid >> 5, lane = tid & 31;
    int wm = wid & 3, wn = wid >> 2;
    int m0 = blockIdx.y * 128, n0 = blockIdx.x * 64;

    int p_row = tid >> 2;
    int p_seg = tid & 3;

    int a_row = lane & 15;
    int a_colb = ((lane >> 4) * 8) * 2;
    int b_row = (lane & 7) + ((lane >> 4) & 1) * 8;
    int b_colb = (((lane >> 3) & 1) * 8) * 2;

    float acc[2][4][4];
#pragma unroll
    for (int i = 0; i < 2; i++)
#pragma unroll
        for (int j = 0; j < 4; j++)
#pragma unroll
            for (int q = 0; q < 4; q++) acc[i][j][q] = 0.f;

    const int nch = K >> 5;

    auto issue = [&](int c, int bufsel) {
        int k0 = c << 5;
        uint32_t base = sb + bufsel * BUFSZ;
        uint32_t doff = (uint32_t)(p_row * ROWB + p_seg * 16);
#pragma unroll
        for (int i = 0; i < 2; i++) {
            int row = p_row + i * 64;
            size_t aoff = (size_t)(m0 + row) * K + k0 + p_seg * 8;
            cp16(base + SM_AH + doff + i * (64 * ROWB), Ah + aoff);
            cp16(base + SM_AL + doff + i * (64 * ROWB), Al + aoff);
        }
        size_t boff = (size_t)(n0 + p_row) * K + k0 + p_seg * 8;
        cp16(base + SM_BH + doff, Bh + boff);
    };

    issue(0, 0);
    CP_COMMIT();

    int curb = 0, nxtb = 1;
    for (int c = 0; c < nch; c++) {
        if (c + 1 < nch) {
            issue(c + 1, nxtb);
            CP_COMMIT();
            CP_WAIT(1);
        } else {
            CP_WAIT(0);
        }
        __syncthreads();

        uint32_t base = sb + curb * BUFSZ;
#pragma unroll
        for (int ks = 0; ks < 2; ks++) {
            uint32_t a_hi[2][4], a_lo[2][4];
#pragma unroll
            for (int mt = 0; mt < 2; mt++) {
                uint32_t off = (uint32_t)((wm * 32 + mt * 16 + a_row) * ROWB
                                          + ks * 32 + a_colb);
                ldsm_x4(a_hi[mt], base + SM_AH + off);
                ldsm_x4(a_lo[mt], base + SM_AL + off);
            }
            uint32_t b_hi[2][4];
#pragma unroll
            for (int p = 0; p < 2; p++) {
                uint32_t off = (uint32_t)((wn * 32 + p * 16 + b_row) * ROWB
                                          + ks * 32 + b_colb);
                ldsm_x4(b_hi[p], base + SM_BH + off);
            }
#pragma unroll
            for (int mt = 0; mt < 2; mt++)
#pragma unroll
                for (int p = 0; p < 2; p++) {
                    mma_f16(acc[mt][2*p],   a_hi[mt], &b_hi[p][0]);
                    mma_f16(acc[mt][2*p+1], a_hi[mt], &b_hi[p][2]);
                }
#pragma unroll
            for (int mt = 0; mt < 2; mt++)
#pragma unroll
                for (int p = 0; p < 2; p++) {
                    mma_f16(acc[mt][2*p],   a_lo[mt], &b_hi[p][0]);
                    mma_f16(acc[mt][2*p+1], a_lo[mt], &b_hi[p][2]);
                }
        }
        curb = nxtb;
        nxtb = (nxtb == 2) ? 0 : nxtb + 1;
    }

    int r0 = m0 + wm * 32 + (lane >> 2);
    int c0 = n0 + wn * 32 + (lane & 3) * 2;
#pragma unroll
    for (int mt = 0; mt < 2; mt++) {
#pragma unroll
        for (int nt = 0; nt < 4; nt++) {
            int r = r0 + mt * 16;
            int cc = c0 + nt * 8;
            float b0 = bias[cc], b1 = bias[cc + 1];
            float v0 = acc[mt][nt][0] + b0;
            float v1 = acc[mt][nt][1] + b1;
            float v2 = acc[mt][nt][2] + b0;
            float v3 = acc[mt][nt][3] + b1;
            if (EPI == 2) {
                v0 = gelu_f(v0); v1 = gelu_f(v1);
                v2 = gelu_f(v2); v3 = gelu_f(v3);
                uint32_t h01, l01, h23, l23;
                cvt_split2h(v0, v1, h01, l01);
                cvt_split2h(v2, v3, h23, l23);
                *(uint32_t*)(Ch + (size_t)r * N + cc) = h01;
                *(uint32_t*)(Cl + (size_t)r * N + cc) = l01;
                *(uint32_t*)(Ch + (size_t)(r + 8) * N + cc) = h23;
                *(uint32_t*)(Cl + (size_t)(r + 8) * N + cc) = l23;
            } else if (EPI == 3) {
                if (cc < 1536) {
                    int kk = (cc >= 768);
                    size_t idx = (size_t)kk * (BT * EMB)
                               + (size_t)r * EMB + (cc - kk * 768);
                    uint32_t h01, l01, h23, l23;
                    cvt_split2h(v0, v1, h01, l01);
                    cvt_split2h(v2, v3, h23, l23);
                    *(uint32_t*)(Ch + idx) = h01;
                    *(uint32_t*)(Cl + idx) = l01;
                    *(uint32_t*)(Ch + idx + (size_t)8 * EMB) = h23;
                    *(uint32_t*)(Cl + idx + (size_t)8 * EMB) = l23;
                } else {
                    int b = r >> 9, s = r & 511;
                    int hd = cc - 1536;
                    int hh_ = hd >> 6, d = hd & 63;
                    size_t idx = ((size_t)(b * NH + hh_) * 64 + d) * 512 + s;
                    __half a0 = __float2half_rn(v0);
                    Vh[idx] = a0;
                    Vl[idx] = __float2half_rn(v0 - __half2float(a0));
                    __half a1 = __float2half_rn(v1);
                    Vh[idx + 512] = a1;
                    Vl[idx + 512] = __float2half_rn(v1 - __half2float(a1));
                    __half a2 = __float2half_rn(v2);
                    Vh[idx + 8] = a2;
                    Vl[idx + 8] = __float2half_rn(v2 - __half2float(a2));
                    __half a3 = __float2half_rn(v3);
                    Vh[idx + 512 + 8] = a3;
                    Vl[idx + 512 + 8] = __float2half_rn(v3 - __half2float(a3));
                }
            } else {
                if (EPI == 1) {
                    const float* rp0 = Res + (size_t)r * N + cc;
                    const float* rp1 = Res + (size_t)(r + 8) * N + cc;
                    v0 += rp0[0]; v1 += rp0[1];
                    v2 += rp1[0]; v3 += rp1[1];
                }
                *reinterpret_cast<float2*>(C + (size_t)r * N + cc) = make_float2(v0, v1);
                *reinterpret_cast<float2*>(C + (size_t)(r + 8) * N + cc) = make_float2(v2, v3);
            }
        }
    }
}

// ================= tensor-core causal flash attention (R14/R15) ============
#define FROWB 144
#define FT_QH 0
#define FT_QL (128*FROWB)
#define FT_KV0 (2*128*FROWB)
#define KV_KH 0
#define KV_KL (64*FROWB)
#define KV_VH (2*64*FROWB)
#define KV_VL (3*64*FROWB)
#define KVBUF (4*64*FROWB)
#define FT_SMEM (FT_KV0 + 2*KVBUF)   // 110592

__global__ __launch_bounds__(256, 2) void flash_tc_kernel() {
    extern __shared__ __align__(16) char fsm[];
    uint32_t sb = smem_u32(fsm);
    int bh = blockIdx.y;
    int b = bh / NH, h = bh % NH;
    int t0 = blockIdx.x * 128;
    int tid = threadIdx.x;
    int wid = tid >> 5, lane = tid & 31;

    const __half* Kh = g_qkh + (size_t)BT * EMB;
    const __half* Kl = g_qkl + (size_t)BT * EMB;

    int a_row = lane & 15;
    int a_colb = ((lane >> 4) * 8) * 2;
    int b_row = (lane & 7) + ((lane >> 4) & 1) * 8;
    int b_colb = (((lane >> 3) & 1) * 8) * 2;

    auto kv_issue = [&](int j, int buf) {
        int s = tid >> 2, seg = tid & 3;
        uint32_t base = sb + FT_KV0 + buf * KVBUF;
        size_t koff = (size_t)(b * SEQ + j * 64 + s) * EMB + h * DH + seg * 16;
        uint32_t kdh = base + KV_KH + s * FROWB + seg * 32;
        uint32_t kdl = base + KV_KL + s * FROWB + seg * 32;
        cp16(kdh,      Kh + koff);
        cp16(kdh + 16, Kh + koff + 8);
        cp16(kdl,      Kl + koff);
        cp16(kdl + 16, Kl + koff + 8);
        size_t voff = ((size_t)bh * 64 + s) * 512 + j * 64 + seg * 16;
        uint32_t vdh = base + KV_VH + s * FROWB + seg * 32;
        uint32_t vdl = base + KV_VL + s * FROWB + seg * 32;
        cp16(vdh,      g_vth + voff);
        cp16(vdh + 16, g_vth + voff + 8);
        cp16(vdl,      g_vtl + voff);
        cp16(vdl + 16, g_vtl + voff + 8);
    };

    {
        int row = tid >> 1, hf = tid & 1;
        size_t qoff = (size_t)(b * SEQ + t0 + row) * EMB + h * DH + hf * 32;
        uint32_t dh_ = sb + FT_QH + row * FROWB + hf * 64;
        uint32_t dl_ = sb + FT_QL + row * FROWB + hf * 64;
#pragma unroll
        for (int i = 0; i < 4; i++) {
            cp16(dh_ + 16 * i, g_qkh + qoff + 8 * i);
            cp16(dl_ + 16 * i, g_qkl + qoff + 8 * i);
        }
    }
    kv_issue(0, 0);
    CP_COMMIT();
    CP_WAIT(0);
    __syncthreads();

    float m0 = -1e30f, m1 = -1e30f, l0 = 0.f, l1 = 0.f;
    float O[8][4];
#pragma unroll
    for (int f = 0; f < 8; f++)
#pragma unroll
        for (int q = 0; q < 4; q++) O[f][q] = 0.f;

    int t_r0 = t0 + wid * 16 + (lane >> 2);
    int ntile = (t0 >> 6) + 2;

    for (int j = 0; j < ntile; j++) {
        int cur = j & 1;
        if (j + 1 < ntile) {
            kv_issue(j + 1, cur ^ 1);
            CP_COMMIT();
        }
        uint32_t kvb = sb + FT_KV0 + cur * KVBUF;

        float S[8][4];
#pragma unroll
        for (int f = 0; f < 8; f++)
#pragma unroll
            for (int q = 0; q < 4; q++) S[f][q] = 0.f;
#pragma unroll
        for (int ks = 0; ks < 4; ks++) {
            uint32_t aq_h[4], aq_l[4];
            uint32_t aoff = (uint32_t)((wid * 16 + a_row) * FROWB + ks * 32 + a_colb);
            ldsm_x4(aq_h, sb + FT_QH + aoff);
            ldsm_x4(aq_l, sb + FT_QL + aoff);
#pragma unroll
            for (int p = 0; p < 4; p++) {
                uint32_t bk_h[4], bk_l[4];
                uint32_t boff = (uint32_t)((p * 16 + b_row) * FROWB + ks * 32 + b_colb);
                ldsm_x4(bk_h, kvb + KV_KH + boff);
                ldsm_x4(bk_l, kvb + KV_KL + boff);
                mma_f16(S[2*p],   aq_h, &bk_h[0]);
                mma_f16(S[2*p+1], aq_h, &bk_h[2]);
                mma_f16(S[2*p],   aq_l, &bk_h[0]);
                mma_f16(S[2*p+1], aq_l, &bk_h[2]);
                mma_f16(S[2*p],   aq_h, &bk_l[0]);
                mma_f16(S[2*p+1], aq_h, &bk_l[2]);
            }
        }

#pragma unroll
        for (int f = 0; f < 8; f++) {
            int c = j * 64 + (f >> 1) * 16 + (f & 1) * 8 + (lane & 3) * 2;
#pragma unroll
            for (int q = 0; q < 4; q++) S[f][q] *= 0.125f;
            if (c     > t_r0) S[f][0] = -1e30f;
            if (c + 1 > t_r0) S[f][1] = -1e30f;
            if (c     > t_r0 + 8) S[f][2] = -1e30f;
            if (c + 1 > t_r0 + 8) S[f][3] = -1e30f;
        }

        float mx0 = -1e30f, mx1 = -1e30f;
#pragma unroll
        for (int f = 0; f < 8; f++) {
            mx0 = fmaxf(mx0, fmaxf(S[f][0], S[f][1]));
            mx1 = fmaxf(mx1, fmaxf(S[f][2], S[f][3]));
        }
        mx0 = fmaxf(mx0, __shfl_xor_sync(0xffffffffu, mx0, 1));
        mx0 = fmaxf(mx0, __shfl_xor_sync(0xffffffffu, mx0, 2));
        mx1 = fmaxf(mx1, __shfl_xor_sync(0xffffffffu, mx1, 1));
        mx1 = fmaxf(mx1, __shfl_xor_sync(0xffffffffu, mx1, 2));
        float mn0 = fmaxf(m0, mx0), mn1 = fmaxf(m1, mx1);
        float c0 = __expf(m0 - mn0), c1 = __expf(m1 - mn1);
        m0 = mn0; m1 = mn1;
        float rs0 = 0.f, rs1 = 0.f;
#pragma unroll
        for (int f = 0; f < 8; f++) {
            S[f][0] = __expf(S[f][0] - mn0);
            S[f][1] = __expf(S[f][1] - mn0);
            S[f][2] = __expf(S[f][2] - mn1);
            S[f][3] = __expf(S[f][3] - mn1);
            rs0 += S[f][0] + S[f][1];
            rs1 += S[f][2] + S[f][3];
        }
        rs0 += __shfl_xor_sync(0xffffffffu, rs0, 1);
        rs0 += __shfl_xor_sync(0xffffffffu, rs0, 2);
        rs1 += __shfl_xor_sync(0xffffffffu, rs1, 1);
        rs1 += __shfl_xor_sync(0xffffffffu, rs1, 2);
        l0 = l0 * c0 + rs0;
        l1 = l1 * c1 + rs1;
#pragma unroll
        for (int f = 0; f < 8; f++) {
            O[f][0] *= c0; O[f][1] *= c0;
            O[f][2] *= c1; O[f][3] *= c1;
        }

#pragma unroll
        for (int g = 0; g < 4; g++) {
            uint32_t pa[4];
            __half2 p0 = __floats2half2_rn(S[2*g][0],   S[2*g][1]);
            __half2 p1 = __floats2half2_rn(S[2*g][2],   S[2*g][3]);
            __half2 p2 = __floats2half2_rn(S[2*g+1][0], S[2*g+1][1]);
            __half2 p3 = __floats2half2_rn(S[2*g+1][2], S[2*g+1][3]);
            pa[0] = *(uint32_t*)&p0;
            pa[1] = *(uint32_t*)&p1;
            pa[2] = *(uint32_t*)&p2;
            pa[3] = *(uint32_t*)&p3;
#pragma unroll
            for (int p = 0; p < 4; p++) {
                uint32_t bv_h[4], bv_l[4];
                uint32_t boff = (uint32_t)((p * 16 + b_row) * FROWB + g * 32 + b_colb);
                ldsm_x4(bv_h, kvb + KV_VH + boff);
                ldsm_x4(bv_l, kvb + KV_VL + boff);
                mma_f16(O[2*p],   pa, &bv_h[0]);
                mma_f16(O[2*p+1], pa, &bv_h[2]);
                mma_f16(O[2*p],   pa, &bv_l[0]);
                mma_f16(O[2*p+1], pa, &bv_l[2]);
            }
        }

        if (j + 1 < ntile) {
            CP_WAIT(0);
        }
        __syncthreads();
    }

    float inv0 = 1.f / l0, inv1 = 1.f / l1;
#pragma unroll
    for (int f = 0; f < 8; f++) {
        int d = (f >> 1) * 16 + (f & 1) * 8 + (lane & 3) * 2;
        size_t base0 = (size_t)(b * SEQ + t_r0) * EMB + h * DH + d;
        size_t base1 = (size_t)(b * SEQ + t_r0 + 8) * EMB + h * DH + d;
        uint32_t hh, ll;
        cvt_split2h(O[f][0] * inv0, O[f][1] * inv0, hh, ll);
        *(uint32_t*)(g_atth + base0) = hh;
        *(uint32_t*)(g_attl + base0) = ll;
        cvt_split2h(O[f][2] * inv1, O[f][3] * inv1, hh, ll);
        *(uint32_t*)(g_atth + base1) = hh;
        *(uint32_t*)(g_attl + base1) = ll;
    }
}

// ---------------- head GEMM (N=60, FFMA) ----------------
__global__ __launch_bounds__(256) void head_gemm_kernel(
    const float* __restrict__ A,
    const float* __restrict__ Bm,
    const float* __restrict__ bias,
    float* __restrict__ C,
    int N, int K)
{
    __shared__ float As[16][68];
    __shared__ float Bs[16][64];
    int m0 = blockIdx.y * 64, n0 = blockIdx.x * 64;
    int tid = threadIdx.x;
    int tx = tid & 15, ty = tid >> 4;
    float acc[4][4] = {};
    for (int k0 = 0; k0 < K; k0 += 16) {
#pragma unroll
        for (int i = 0; i < 4; i++) {
            int lin = tid + i * 256;
            int r = lin >> 4, c = lin & 15;
            As[c][r] = A[(size_t)(m0 + r) * K + k0 + c];
        }
#pragma unroll
        for (int i = 0; i < 4; i++) {
            int lin = tid + i * 256;
            int r = lin >> 6, c = lin & 63;
            int n = n0 + c;
            Bs[r][c] = (n < N) ? Bm[(size_t)(k0 + r) * N + n] : 0.f;
        }
        __syncthreads();
#pragma unroll
        for (int kk = 0; kk < 16; kk++) {
            float4 a4 = *reinterpret_cast<const float4*>(&As[kk][ty * 4]);
            float4 b4 = *reinterpret_cast<const float4*>(&Bs[kk][tx * 4]);
            float a[4] = {a4.x, a4.y, a4.z, a4.w};
            float bv[4] = {b4.x, b4.y, b4.z, b4.w};
#pragma unroll
            for (int i = 0; i < 4; i++)
#pragma unroll
                for (int j = 0; j < 4; j++)
                    acc[i][j] = fmaf(a[i], bv[j], acc[i][j]);
        }
        __syncthreads();
    }
#pragma unroll
    for (int i = 0; i < 4; i++) {
        int m = m0 + ty * 4 + i;
#pragma unroll
        for (int j = 0; j < 4; j++) {
            int n = n0 + tx * 4 + j;
            if (n < N) C[(size_t)m * N + n] = acc[i][j] + bias[n];
        }
    }
}

// ---------------- host orchestration ----------------
extern "C" void kernel_launch(void* const* d_in, const int* in_sizes, int n_in,
                              void* d_out, int out_size) {
    const int*   ids          = (const int*)d_in[0];
    const int*   mul          = (const int*)d_in[1];
    const float* tok_emb      = (const float*)d_in[2];
    const float* state_emb    = (const float*)d_in[3];
    const float* state_proj_w = (const float*)d_in[4];
    const float* state_proj_b = (const float*)d_in[5];
    const float* wpe          = (const float*)d_in[6];
    const float* ln1_g        = (const float*)d_in[7];
    const float* ln1_b        = (const float*)d_in[8];
    const float* attn_w       = (const float*)d_in[9];
    const float* attn_b       = (const float*)d_in[10];
    const float* attn_proj_w  = (const float*)d_in[11];
    const float* attn_proj_b  = (const float*)d_in[12];
    const float* ln2_g        = (const float*)d_in[13];
    const float* ln2_b        = (const float*)d_in[14];
    const float* fc_w         = (const float*)d_in[15];
    const float* fc_b         = (const float*)d_in[16];
    const float* mlp_proj_w   = (const float*)d_in[17];
    const float* mlp_proj_b   = (const float*)d_in[18];
    const float* lnf_g        = (const float*)d_in[19];
    const float* lnf_b        = (const float*)d_in[20];
    const float* head_w       = (const float*)d_in[21];
    const float* head_b       = (const float*)d_in[22];
    float* out = (float*)d_out;

    float *h, *lnbuf;
    __half *wh, *lnh, *lnl, *atth, *attl, *midh, *midl, *qkh, *qkl, *vth, *vtl;
    cudaGetSymbolAddress((void**)&h,     g_h);
    cudaGetSymbolAddress((void**)&lnbuf, g_ln);
    cudaGetSymbolAddress((void**)&wh,    g_wh);
    cudaGetSymbolAddress((void**)&lnh,   g_lnh);
    cudaGetSymbolAddress((void**)&lnl,   g_lnl);
    cudaGetSymbolAddress((void**)&atth,  g_atth);
    cudaGetSymbolAddress((void**)&attl,  g_attl);
    cudaGetSymbolAddress((void**)&midh,  g_midh);
    cudaGetSymbolAddress((void**)&midl,  g_midl);
    cudaGetSymbolAddress((void**)&qkh,   g_qkh);
    cudaGetSymbolAddress((void**)&qkl,   g_qkl);
    cudaGetSymbolAddress((void**)&vth,   g_vth);
    cudaGetSymbolAddress((void**)&vtl,   g_vtl);

    cudaFuncSetAttribute(mma_gemm<1>, cudaFuncAttributeMaxDynamicSharedMemorySize, GEMM_SMEM);
    cudaFuncSetAttribute(mma_gemm<2>, cudaFuncAttributeMaxDynamicSharedMemorySize, GEMM_SMEM);
    cudaFuncSetAttribute(mma_gemm<3>, cudaFuncAttributeMaxDynamicSharedMemorySize, GEMM_SMEM);
    cudaFuncSetAttribute(flash_tc_kernel, cudaFuncAttributeMaxDynamicSharedMemorySize, FT_SMEM);

    wconv_kernel<<<dim3(QKVN/32, EMB/64, NLAYER), 256>>>(attn_w, wh + OFF_QKV, EMB, QKVN);
    wconv_kernel<<<dim3(EMB/32, EMB/64, NLAYER), 256>>>(attn_proj_w, wh + OFF_PROJ, EMB, EMB);
    wconv_kernel<<<dim3(FFN/32, EMB/64, NLAYER), 256>>>(fc_w, wh + OFF_FC, EMB, FFN);
    wconv_kernel<<<dim3(EMB/32, FFN/64, NLAYER), 256>>>(mlp_proj_w, wh + OFF_MLP, FFN, EMB);

    state_scan_kernel<<<1, 256>>>(ids, mul);
    state_proj_kernel<<<(VOC * EMB + 255) / 256, 256>>>(state_emb, state_proj_w, state_proj_b);
    embed_kernel<<<(BT * EMB + 255) / 256, 256>>>(ids, tok_emb, wpe);

    for (int l = 0; l < NLAYER; l++) {
        ln_f16_kernel<<<BT/8, 256>>>(h, ln1_g + l * EMB, ln1_b + l * EMB, lnh, lnl);
        mma_gemm<3><<<dim3(QKVN/64, BT/128), 256, GEMM_SMEM>>>(
            lnh, lnl, wh + OFF_QKV + (size_t)l * W_QKV,
            attn_b + l * QKVN, nullptr, nullptr, qkh, qkl, vth, vtl, EMB, QKVN);
        flash_tc_kernel<<<dim3(SEQ/128, BATCH * NH), 256, FT_SMEM>>>();
        mma_gemm<1><<<dim3(EMB/64, BT/128), 256, GEMM_SMEM>>>(
            atth, attl, wh + OFF_PROJ + (size_t)l * W_PROJ,
            attn_proj_b + l * EMB, h, h, nullptr, nullptr, nullptr, nullptr, EMB, EMB);
        ln_f16_kernel<<<BT/8, 256>>>(h, ln2_g + l * EMB, ln2_b + l * EMB, lnh, lnl);
        mma_gemm<2><<<dim3(FFN/64, BT/128), 256, GEMM_SMEM>>>(
            lnh, lnl, wh + OFF_FC + (size_t)l * W_FC,
            fc_b + l * FFN, nullptr, nullptr, midh, midl, nullptr, nullptr, EMB, FFN);
        mma_gemm<1><<<dim3(EMB/64, BT/128), 256, GEMM_SMEM>>>(
            midh, midl, wh + OFF_MLP + (size_t)l * W_MLP,
            mlp_proj_b + l * EMB, h, h, nullptr, nullptr, nullptr, nullptr, FFN, EMB);
    }

    ln_kernel<<<BT/8, 256>>>(h, lnf_g, lnf_b, lnbuf);
    head_gemm_kernel<<<dim3(1, BT / 64), 256>>>(lnbuf, head_w, head_b, out, VOC, EMB);
}